// round 7
// baseline (speedup 1.0000x reference)
#include <cuda_runtime.h>
#include <cuda_bf16.h>
#include <cstdint>

// ---------------------------------------------------------------------------
// GATGraphSimilarity: Siamese 2-layer GAT (heads=4 then 1) + mean pool.
// Round 7: aggregate-first conv1 (gather x, 512B/edge; alphas via P = fold(W,a)),
// dual-graph fusion (both graphs in every launch), setup consolidation.
// GEMMs via mma.sync m16n8k16 split-bf16 (fp32 accum).
// ---------------------------------------------------------------------------

#define NMAX 50000
#define EMAX 800000
#define GNUM 64
#define NEG_SLOPE 0.2f
#define SCAN_CHUNK 4096
#define SCAN_NB ((NMAX + SCAN_CHUNK - 1) / SCAN_CHUNK)

__device__ float g_AGG [2][(size_t)NMAX * 512];   // conv1 aggregated x: [n][4][128]
__device__ float g_OUT [2][(size_t)NMAX * 256];   // conv1 output (elu'd)
__device__ float g_H2  [2][(size_t)NMAX * 64];    // conv2 pre-agg features
__device__ float g_AS  [2][NMAX * 4];
__device__ float g_AD  [2][NMAX * 4];
__device__ int   g_DEG [2][NMAX];
__device__ int   g_ROWPTR[2][NMAX + 1];
__device__ int   g_CUR [2][NMAX];
__device__ int   g_ECOL[2][EMAX];
__device__ int   g_PART[2][SCAN_NB + 1];
__device__ float g_POOL[2 * GNUM * 64];
__device__ float g_CNT [2 * GNUM];
__device__ float g_P1S [128 * 4];                  // P[k][h] = fold(W1, a_src1)
__device__ float g_P1D [128 * 4];
__device__ __nv_bfloat16 g_W1T_HI[256 * 128];      // [N,K] K-contiguous
__device__ __nv_bfloat16 g_W1T_LO[256 * 128];
__device__ __nv_bfloat16 g_W2T_HI[64 * 256];
__device__ __nv_bfloat16 g_W2T_LO[64 * 256];

static inline int cdiv(int a, int b) { return (a + b - 1) / b; }

__device__ __forceinline__ float leaky(float v) {
    return v > 0.0f ? v : NEG_SLOPE * v;
}

__device__ __forceinline__ uint32_t bf2u(__nv_bfloat162 v) {
    return *reinterpret_cast<uint32_t*>(&v);
}

__device__ __forceinline__ void mma16816(float* d, const uint32_t* a, const uint32_t* b) {
    asm volatile(
        "mma.sync.aligned.m16n8k16.row.col.f32.bf16.bf16.f32 "
        "{%0,%1,%2,%3}, {%4,%5,%6,%7}, {%8,%9}, {%0,%1,%2,%3};"
        : "+f"(d[0]), "+f"(d[1]), "+f"(d[2]), "+f"(d[3])
        : "r"(a[0]), "r"(a[1]), "r"(a[2]), "r"(a[3]), "r"(b[0]), "r"(b[1]));
}

// ---------------------------------------------------------------------------
// Setup: zero pool, prep split-bf16 transposed weights, fold P1 = W1 . a
// ---------------------------------------------------------------------------
#define SEG1 (256 * 128)            // W1T
#define SEG2 (64 * 256)             // W2T
#define SEG3 1024                   // P fold (512 src + 512 dst)
#define SEG4 (2 * GNUM * 64 + 2 * GNUM)
#define SETUP_TOTAL (SEG1 + SEG2 + SEG3 + SEG4)

__global__ void setup_kernel(const float* __restrict__ W1,
                             const float* __restrict__ W2,
                             const float* __restrict__ as1,
                             const float* __restrict__ ad1,
                             __nv_bfloat16* __restrict__ W1TH,
                             __nv_bfloat16* __restrict__ W1TL,
                             __nv_bfloat16* __restrict__ W2TH,
                             __nv_bfloat16* __restrict__ W2TL,
                             float* __restrict__ P1S,
                             float* __restrict__ P1D,
                             float* __restrict__ POOL,
                             float* __restrict__ CNT) {
    int i = blockIdx.x * blockDim.x + threadIdx.x;
    if (i < SEG1) {                                 // W1: [128,256] -> [256,128]
        int n = i / 128, k = i % 128;
        float v = W1[(size_t)k * 256 + n];
        __nv_bfloat16 h = __float2bfloat16(v);
        W1TH[i] = h;
        W1TL[i] = __float2bfloat16(v - __bfloat162float(h));
        return;
    }
    i -= SEG1;
    if (i < SEG2) {                                 // W2: [256,64] -> [64,256]
        int n = i / 256, k = i % 256;
        float v = W2[(size_t)k * 64 + n];
        __nv_bfloat16 h = __float2bfloat16(v);
        W2TH[i] = h;
        W2TL[i] = __float2bfloat16(v - __bfloat162float(h));
        return;
    }
    i -= SEG2;
    if (i < SEG3) {                                 // P[k][h] = sum_d W1[k, h*64+d]*a[h*64+d]
        int is_dst = i >> 9;
        int o = i & 511;
        int k = o >> 2, h = o & 3;
        const float* a = is_dst ? ad1 : as1;
        float s = 0.0f;
        #pragma unroll 8
        for (int d = 0; d < 64; d++)
            s += W1[(size_t)k * 256 + h * 64 + d] * a[h * 64 + d];
        (is_dst ? P1D : P1S)[k * 4 + h] = s;
        return;
    }
    i -= SEG3;
    if (i < 2 * GNUM * 64) { POOL[i] = 0.0f; return; }
    i -= 2 * GNUM * 64;
    if (i < 2 * GNUM) CNT[i] = 0.0f;
}

// ---------------------------------------------------------------------------
// CSR build (dual-graph via blockIdx.y)
// ---------------------------------------------------------------------------
__global__ void deg_zero_kernel(int* __restrict__ deg, int n) {
    int g = blockIdx.y;
    int i = blockIdx.x * blockDim.x + threadIdx.x;
    if (i < n) deg[g * NMAX + i] = 0;
}

__global__ void hist_kernel(const int* __restrict__ ei0, const int* __restrict__ ei1,
                            int* __restrict__ deg, int E) {
    int g = blockIdx.y;
    const int* ei = g ? ei1 : ei0;
    int i = blockIdx.x * blockDim.x + threadIdx.x;
    if (i < E) atomicAdd(&deg[g * NMAX + ei[E + i]], 1);
}

__global__ void scan_partial_kernel(const int* __restrict__ deg,
                                    int* __restrict__ part, int n) {
    __shared__ int red[256];
    const int g = blockIdx.y;
    const int t = threadIdx.x;
    const int base = blockIdx.x * SCAN_CHUNK + t * 16;
    int s = 0;
    #pragma unroll
    for (int q = 0; q < 16; q++) {
        int i = base + q;
        if (i < n) s += deg[g * NMAX + i];
    }
    red[t] = s;
    __syncthreads();
    #pragma unroll
    for (int off = 128; off >= 1; off >>= 1) {
        if (t < off) red[t] += red[t + off];
        __syncthreads();
    }
    if (t == 0) part[g * (SCAN_NB + 1) + blockIdx.x] = red[0];
}

__global__ void scan_root_kernel(int* __restrict__ part, int nb) {
    int g = blockIdx.x;
    if (threadIdx.x == 0) {
        int* p = part + g * (SCAN_NB + 1);
        int run = 0;
        for (int i = 0; i < nb; i++) {
            int v = p[i];
            p[i] = run;
            run += v;
        }
        p[nb] = run;
    }
}

__global__ void scan_final_kernel(const int* __restrict__ deg,
                                  const int* __restrict__ part,
                                  int* __restrict__ rowptr,
                                  int* __restrict__ cur,
                                  int n, int nb) {
    __shared__ int thr[256];
    const int g = blockIdx.y;
    const int t = threadIdx.x;
    const int base = blockIdx.x * SCAN_CHUNK + t * 16;
    const int* dg = deg + g * NMAX;
    int* rp = rowptr + g * (NMAX + 1);
    int* cu = cur + g * NMAX;
    int s = 0;
    int dloc[16];
    #pragma unroll
    for (int q = 0; q < 16; q++) {
        int i = base + q;
        dloc[q] = (i < n) ? dg[i] : 0;
        s += dloc[q];
    }
    thr[t] = s;
    __syncthreads();
    #pragma unroll
    for (int off = 1; off < 256; off <<= 1) {
        int v = (t >= off) ? thr[t - off] : 0;
        __syncthreads();
        thr[t] += v;
        __syncthreads();
    }
    int offset = part[g * (SCAN_NB + 1) + blockIdx.x] + ((t == 0) ? 0 : thr[t - 1]);
    #pragma unroll
    for (int q = 0; q < 16; q++) {
        int i = base + q;
        if (i < n) {
            rp[i] = offset;
            cu[i] = offset;
            offset += dloc[q];
        }
    }
    if (blockIdx.x == 0 && t == 0) rp[n] = part[g * (SCAN_NB + 1) + nb];
}

__global__ void fill_kernel(const int* __restrict__ ei0, const int* __restrict__ ei1,
                            int* __restrict__ cur, int* __restrict__ ecol, int E) {
    int g = blockIdx.y;
    const int* ei = g ? ei1 : ei0;
    int i = blockIdx.x * blockDim.x + threadIdx.x;
    if (i >= E) return;
    int s = ei[i];
    int d = ei[E + i];
    int slot = atomicAdd(&cur[g * NMAX + d], 1);
    ecol[(size_t)g * EMAX + slot] = s;
}

// ---------------------------------------------------------------------------
// conv1 alphas from raw x: AS[n,h] = x[n] . P1S[:,h], AD likewise.
// Warp per node; lane owns 4 k-dims.
// ---------------------------------------------------------------------------
__global__ void alphas_x_kernel(const float* __restrict__ x0,
                                const float* __restrict__ x1,
                                const float* __restrict__ P1S,
                                const float* __restrict__ P1D,
                                float* __restrict__ AS,
                                float* __restrict__ AD,
                                int n) {
    const int g = blockIdx.y;
    const float* x = g ? x1 : x0;
    const int warp = (blockIdx.x * blockDim.x + threadIdx.x) >> 5;
    const int lane = threadIdx.x & 31;
    if (warp >= n) return;
    float4 xv = *(const float4*)&x[(size_t)warp * 128 + lane * 4];
    float s[4] = {0.f, 0.f, 0.f, 0.f};
    float d[4] = {0.f, 0.f, 0.f, 0.f};
    const float* xp = (const float*)&xv;
    #pragma unroll
    for (int j = 0; j < 4; j++) {
        float xk = xp[j];
        float4 ps = *(const float4*)&P1S[(lane * 4 + j) * 4];
        float4 pd = *(const float4*)&P1D[(lane * 4 + j) * 4];
        s[0] += xk * ps.x; s[1] += xk * ps.y; s[2] += xk * ps.z; s[3] += xk * ps.w;
        d[0] += xk * pd.x; d[1] += xk * pd.y; d[2] += xk * pd.z; d[3] += xk * pd.w;
    }
    #pragma unroll
    for (int off = 16; off >= 1; off >>= 1) {
        #pragma unroll
        for (int h = 0; h < 4; h++) {
            s[h] += __shfl_xor_sync(0xffffffffu, s[h], off);
            d[h] += __shfl_xor_sync(0xffffffffu, d[h], off);
        }
    }
    if (lane == 0) {
        *(float4*)&AS[(size_t)g * NMAX * 4 + warp * 4] = make_float4(s[0], s[1], s[2], s[3]);
        *(float4*)&AD[(size_t)g * NMAX * 4 + warp * 4] = make_float4(d[0], d[1], d[2], d[3]);
    }
}

// ---------------------------------------------------------------------------
// conv1 aggregate-first: warp per dst node, gather x rows (512B/edge),
// 4-head softmax weights, write normalized AGG [n][4][128].
// ---------------------------------------------------------------------------
__global__ void agg_x_kernel(const int* __restrict__ rowptr,
                             const int* __restrict__ ecol,
                             const float* __restrict__ AS,
                             const float* __restrict__ AD,
                             const float* __restrict__ x0,
                             const float* __restrict__ x1,
                             float* __restrict__ AGG,
                             int n) {
    const int g = blockIdx.y;
    const float* x = g ? x1 : x0;
    const int* rp = rowptr + g * (NMAX + 1);
    const int* ec = ecol + (size_t)g * EMAX;
    const float* as = AS + (size_t)g * NMAX * 4;
    const float* ad = AD + (size_t)g * NMAX * 4;
    float* agg = AGG + (size_t)g * NMAX * 512;

    const int warp = (blockIdx.x * blockDim.x + threadIdx.x) >> 5;
    const int lane = threadIdx.x & 31;
    if (warp >= n) return;
    const int d = warp;
    const int beg = rp[d];
    const int end = rp[d + 1];

    float4 adv = *(const float4*)&ad[d * 4];
    float4 asv = *(const float4*)&as[d * 4];
    float self_e[4] = {leaky(asv.x + adv.x), leaky(asv.y + adv.y),
                       leaky(asv.z + adv.z), leaky(asv.w + adv.w)};
    float mx[4] = {self_e[0], self_e[1], self_e[2], self_e[3]};

    // pass 1: max (lane-strided)
    for (int j = beg + lane; j < end; j += 32) {
        int s = ec[j];
        float4 a4 = *(const float4*)&as[s * 4];
        mx[0] = fmaxf(mx[0], leaky(a4.x + adv.x));
        mx[1] = fmaxf(mx[1], leaky(a4.y + adv.y));
        mx[2] = fmaxf(mx[2], leaky(a4.z + adv.z));
        mx[3] = fmaxf(mx[3], leaky(a4.w + adv.w));
    }
    #pragma unroll
    for (int h = 0; h < 4; h++) {
        #pragma unroll
        for (int off = 16; off >= 1; off >>= 1)
            mx[h] = fmaxf(mx[h], __shfl_xor_sync(0xffffffffu, mx[h], off));
    }

    // pass 2: denom + weighted x accumulate (lane owns dims lane*4..+3)
    float4 xd = *(const float4*)&x[(size_t)d * 128 + lane * 4];
    float den[4], acc[4][4];
    #pragma unroll
    for (int h = 0; h < 4; h++) {
        float ex = __expf(self_e[h] - mx[h]);
        den[h] = ex;
        acc[h][0] = ex * xd.x; acc[h][1] = ex * xd.y;
        acc[h][2] = ex * xd.z; acc[h][3] = ex * xd.w;
    }
    for (int j = beg; j < end; j++) {
        int s = ec[j];
        float4 a4 = *(const float4*)&as[s * 4];
        float e0 = __expf(leaky(a4.x + adv.x) - mx[0]);
        float e1 = __expf(leaky(a4.y + adv.y) - mx[1]);
        float e2 = __expf(leaky(a4.z + adv.z) - mx[2]);
        float e3 = __expf(leaky(a4.w + adv.w) - mx[3]);
        den[0] += e0; den[1] += e1; den[2] += e2; den[3] += e3;
        float4 xs = *(const float4*)&x[(size_t)s * 128 + lane * 4];
        acc[0][0] += e0 * xs.x; acc[0][1] += e0 * xs.y; acc[0][2] += e0 * xs.z; acc[0][3] += e0 * xs.w;
        acc[1][0] += e1 * xs.x; acc[1][1] += e1 * xs.y; acc[1][2] += e1 * xs.z; acc[1][3] += e1 * xs.w;
        acc[2][0] += e2 * xs.x; acc[2][1] += e2 * xs.y; acc[2][2] += e2 * xs.z; acc[2][3] += e2 * xs.w;
        acc[3][0] += e3 * xs.x; acc[3][1] += e3 * xs.y; acc[3][2] += e3 * xs.z; acc[3][3] += e3 * xs.w;
    }
    #pragma unroll
    for (int h = 0; h < 4; h++) {
        float inv = 1.0f / (den[h] + 1e-16f);
        float4 v = make_float4(acc[h][0] * inv, acc[h][1] * inv,
                               acc[h][2] * inv, acc[h][3] * inv);
        *(float4*)&agg[(size_t)d * 512 + h * 128 + lane * 4] = v;
    }
}

// ---------------------------------------------------------------------------
// mma.sync GEMM core constants (128x64 tile, 8 warps, warp tile 32x32)
// ---------------------------------------------------------------------------
#define SM_AH 0
#define SM_AL 34816
#define SM_BH 69632
#define SM_BL 87040
#define SM_ALPHA 104448
#define SM_TOTAL 105472

// conv1 GEMM: OUT[:, h*64:+64] = elu(AGG[:,h,:] @ W1T[h]^T + b1[h block])
__global__ __launch_bounds__(256, 1)
void gemm1_kernel(const float* __restrict__ AGG,
                  const __nv_bfloat16* __restrict__ Bhi,
                  const __nv_bfloat16* __restrict__ Blo,
                  const float* __restrict__ bias,
                  float* __restrict__ OUT,
                  int M) {
    extern __shared__ char smem[];
    uint32_t* Ah = (uint32_t*)(smem + SM_AH);
    uint32_t* Al = (uint32_t*)(smem + SM_AL);
    uint32_t* Bh = (uint32_t*)(smem + SM_BH);
    uint32_t* Bl = (uint32_t*)(smem + SM_BL);

    const int g = blockIdx.z;
    const float* A = AGG + (size_t)g * NMAX * 512;
    float* C = OUT + (size_t)g * NMAX * 256;
    const int tid = threadIdx.x;
    const int lane = tid & 31;
    const int wid = tid >> 5;
    const int warp_m = wid & 3;
    const int warp_n = wid >> 2;
    const int h = blockIdx.x;
    const int m0 = blockIdx.y * 128;

    float acc[2][4][4] = {};

    // A: 128 rows x 128 k from AGG (row stride 512, head offset h*128)
    #pragma unroll
    for (int q = 0; q < 16; q++) {
        int idx = q * 256 + tid;
        int r = idx >> 5;
        int c4 = idx & 31;
        int gr = m0 + r;
        float4 v = make_float4(0.f, 0.f, 0.f, 0.f);
        if (gr < M) v = *(const float4*)&A[(size_t)gr * 512 + h * 128 + c4 * 4];
        __nv_bfloat162 hxy = __floats2bfloat162_rn(v.x, v.y);
        __nv_bfloat162 hzw = __floats2bfloat162_rn(v.z, v.w);
        float2 fxy = __bfloat1622float2(hxy);
        float2 fzw = __bfloat1622float2(hzw);
        __nv_bfloat162 lxy = __floats2bfloat162_rn(v.x - fxy.x, v.y - fxy.y);
        __nv_bfloat162 lzw = __floats2bfloat162_rn(v.z - fzw.x, v.w - fzw.y);
        int w = r * 68 + c4 * 2;
        Ah[w] = bf2u(hxy); Ah[w + 1] = bf2u(hzw);
        Al[w] = bf2u(lxy); Al[w + 1] = bf2u(lzw);
    }
    // B: rows h*64..+63 of W1T, 128 bf16 each
    #pragma unroll
    for (int q = 0; q < 4; q++) {
        int idx = q * 256 + tid;
        int r = idx >> 4;
        int c8 = idx & 15;
        uint4 vh = *(const uint4*)&Bhi[(size_t)(h * 64 + r) * 128 + c8 * 8];
        uint4 vl = *(const uint4*)&Blo[(size_t)(h * 64 + r) * 128 + c8 * 8];
        *(uint4*)&Bh[r * 68 + c8 * 4] = vh;
        *(uint4*)&Bl[r * 68 + c8 * 4] = vl;
    }
    __syncthreads();

    #pragma unroll
    for (int ks = 0; ks < 8; ks++) {
        const int kw = ks * 8 + (lane & 3);
        uint32_t ah[2][4], al[2][4], bh[4][2], bl[4][2];
        #pragma unroll
        for (int mt = 0; mt < 2; mt++) {
            int r0 = warp_m * 32 + mt * 16 + (lane >> 2);
            ah[mt][0] = Ah[r0 * 68 + kw];
            ah[mt][1] = Ah[(r0 + 8) * 68 + kw];
            ah[mt][2] = Ah[r0 * 68 + kw + 4];
            ah[mt][3] = Ah[(r0 + 8) * 68 + kw + 4];
            al[mt][0] = Al[r0 * 68 + kw];
            al[mt][1] = Al[(r0 + 8) * 68 + kw];
            al[mt][2] = Al[r0 * 68 + kw + 4];
            al[mt][3] = Al[(r0 + 8) * 68 + kw + 4];
        }
        #pragma unroll
        for (int nt = 0; nt < 4; nt++) {
            int n0 = warp_n * 32 + nt * 8 + (lane >> 2);
            bh[nt][0] = Bh[n0 * 68 + kw];
            bh[nt][1] = Bh[n0 * 68 + kw + 4];
            bl[nt][0] = Bl[n0 * 68 + kw];
            bl[nt][1] = Bl[n0 * 68 + kw + 4];
        }
        #pragma unroll
        for (int mt = 0; mt < 2; mt++)
            #pragma unroll
            for (int nt = 0; nt < 4; nt++) {
                mma16816(acc[mt][nt], ah[mt], bh[nt]);
                mma16816(acc[mt][nt], ah[mt], bl[nt]);
                mma16816(acc[mt][nt], al[mt], bh[nt]);
            }
    }

    // epilogue: +bias, ELU, write OUT
    #pragma unroll
    for (int mt = 0; mt < 2; mt++) {
        int r0 = warp_m * 32 + mt * 16 + (lane >> 2);
        #pragma unroll
        for (int nt = 0; nt < 4; nt++) {
            int c0 = warp_n * 32 + nt * 8 + (lane & 3) * 2;
            float b0 = __ldg(&bias[h * 64 + c0]);
            float b1v = __ldg(&bias[h * 64 + c0 + 1]);
            float* a4 = acc[mt][nt];
            float v00 = a4[0] + b0, v01 = a4[1] + b1v;
            float v10 = a4[2] + b0, v11 = a4[3] + b1v;
            v00 = v00 > 0.f ? v00 : (__expf(v00) - 1.f);
            v01 = v01 > 0.f ? v01 : (__expf(v01) - 1.f);
            v10 = v10 > 0.f ? v10 : (__expf(v10) - 1.f);
            v11 = v11 > 0.f ? v11 : (__expf(v11) - 1.f);
            int gr0 = m0 + r0, gr1 = gr0 + 8;
            if (gr0 < M) *(float2*)&C[(size_t)gr0 * 256 + h * 64 + c0] = make_float2(v00, v01);
            if (gr1 < M) *(float2*)&C[(size_t)gr1 * 256 + h * 64 + c0] = make_float2(v10, v11);
        }
    }
}

// conv2 GEMM: H2 = OUT @ W2 (K=256, N=64) + alpha epilogue (heads=1)
__global__ __launch_bounds__(256, 1)
void gemm2_kernel(const float* __restrict__ OUT,
                  const __nv_bfloat16* __restrict__ Bhi,
                  const __nv_bfloat16* __restrict__ Blo,
                  float* __restrict__ H2,
                  const float* __restrict__ a_src,
                  const float* __restrict__ a_dst,
                  float* __restrict__ AS,
                  float* __restrict__ AD,
                  int M) {
    extern __shared__ char smem[];
    uint32_t* Ah = (uint32_t*)(smem + SM_AH);
    uint32_t* Al = (uint32_t*)(smem + SM_AL);
    uint32_t* Bh = (uint32_t*)(smem + SM_BH);
    uint32_t* Bl = (uint32_t*)(smem + SM_BL);
    float* alpha_s = (float*)(smem + SM_ALPHA);
    float* alpha_d = alpha_s + 128;

    const int g = blockIdx.z;
    const float* A = OUT + (size_t)g * NMAX * 256;
    float* C = H2 + (size_t)g * NMAX * 64;
    float* ASg = AS + (size_t)g * NMAX * 4;
    float* ADg = AD + (size_t)g * NMAX * 4;
    const int tid = threadIdx.x;
    const int lane = tid & 31;
    const int wid = tid >> 5;
    const int warp_m = wid & 3;
    const int warp_n = wid >> 2;
    const int m0 = blockIdx.y * 128;

    float acc[2][4][4] = {};

    for (int kc = 0; kc < 256; kc += 128) {
        #pragma unroll
        for (int q = 0; q < 16; q++) {
            int idx = q * 256 + tid;
            int r = idx >> 5;
            int c4 = idx & 31;
            int gr = m0 + r;
            float4 v = make_float4(0.f, 0.f, 0.f, 0.f);
            if (gr < M) v = *(const float4*)&A[(size_t)gr * 256 + kc + c4 * 4];
            __nv_bfloat162 hxy = __floats2bfloat162_rn(v.x, v.y);
            __nv_bfloat162 hzw = __floats2bfloat162_rn(v.z, v.w);
            float2 fxy = __bfloat1622float2(hxy);
            float2 fzw = __bfloat1622float2(hzw);
            __nv_bfloat162 lxy = __floats2bfloat162_rn(v.x - fxy.x, v.y - fxy.y);
            __nv_bfloat162 lzw = __floats2bfloat162_rn(v.z - fzw.x, v.w - fzw.y);
            int w = r * 68 + c4 * 2;
            Ah[w] = bf2u(hxy); Ah[w + 1] = bf2u(hzw);
            Al[w] = bf2u(lxy); Al[w + 1] = bf2u(lzw);
        }
        #pragma unroll
        for (int q = 0; q < 4; q++) {
            int idx = q * 256 + tid;
            int r = idx >> 4;
            int c8 = idx & 15;
            uint4 vh = *(const uint4*)&Bhi[(size_t)r * 256 + kc + c8 * 8];
            uint4 vl = *(const uint4*)&Blo[(size_t)r * 256 + kc + c8 * 8];
            *(uint4*)&Bh[r * 68 + c8 * 4] = vh;
            *(uint4*)&Bl[r * 68 + c8 * 4] = vl;
        }
        __syncthreads();

        #pragma unroll
        for (int ks = 0; ks < 8; ks++) {
            const int kw = ks * 8 + (lane & 3);
            uint32_t ah[2][4], al[2][4], bh[4][2], bl[4][2];
            #pragma unroll
            for (int mt = 0; mt < 2; mt++) {
                int r0 = warp_m * 32 + mt * 16 + (lane >> 2);
                ah[mt][0] = Ah[r0 * 68 + kw];
                ah[mt][1] = Ah[(r0 + 8) * 68 + kw];
                ah[mt][2] = Ah[r0 * 68 + kw + 4];
                ah[mt][3] = Ah[(r0 + 8) * 68 + kw + 4];
                al[mt][0] = Al[r0 * 68 + kw];
                al[mt][1] = Al[(r0 + 8) * 68 + kw];
                al[mt][2] = Al[r0 * 68 + kw + 4];
                al[mt][3] = Al[(r0 + 8) * 68 + kw + 4];
            }
            #pragma unroll
            for (int nt = 0; nt < 4; nt++) {
                int n0 = warp_n * 32 + nt * 8 + (lane >> 2);
                bh[nt][0] = Bh[n0 * 68 + kw];
                bh[nt][1] = Bh[n0 * 68 + kw + 4];
                bl[nt][0] = Bl[n0 * 68 + kw];
                bl[nt][1] = Bl[n0 * 68 + kw + 4];
            }
            #pragma unroll
            for (int mt = 0; mt < 2; mt++)
                #pragma unroll
                for (int nt = 0; nt < 4; nt++) {
                    mma16816(acc[mt][nt], ah[mt], bh[nt]);
                    mma16816(acc[mt][nt], ah[mt], bl[nt]);
                    mma16816(acc[mt][nt], al[mt], bh[nt]);
                }
        }
        __syncthreads();
    }

    if (tid < 128) { alpha_s[tid] = 0.0f; alpha_d[tid] = 0.0f; }
    __syncthreads();

    float sp[4] = {0.f, 0.f, 0.f, 0.f};
    float dp[4] = {0.f, 0.f, 0.f, 0.f};
    #pragma unroll
    for (int mt = 0; mt < 2; mt++) {
        int r0 = warp_m * 32 + mt * 16 + (lane >> 2);
        #pragma unroll
        for (int nt = 0; nt < 4; nt++) {
            int c0 = warp_n * 32 + nt * 8 + (lane & 3) * 2;
            float* a4 = acc[mt][nt];
            int gr0 = m0 + r0, gr1 = gr0 + 8;
            if (gr0 < M) *(float2*)&C[(size_t)gr0 * 64 + c0] = make_float2(a4[0], a4[1]);
            if (gr1 < M) *(float2*)&C[(size_t)gr1 * 64 + c0] = make_float2(a4[2], a4[3]);
            float s0 = __ldg(&a_src[c0]);
            float s1 = __ldg(&a_src[c0 + 1]);
            float d0 = __ldg(&a_dst[c0]);
            float d1 = __ldg(&a_dst[c0 + 1]);
            sp[mt * 2]     += a4[0] * s0 + a4[1] * s1;
            sp[mt * 2 + 1] += a4[2] * s0 + a4[3] * s1;
            dp[mt * 2]     += a4[0] * d0 + a4[1] * d1;
            dp[mt * 2 + 1] += a4[2] * d0 + a4[3] * d1;
        }
    }
    #pragma unroll
    for (int i = 0; i < 4; i++) {
        sp[i] += __shfl_xor_sync(0xffffffffu, sp[i], 1);
        sp[i] += __shfl_xor_sync(0xffffffffu, sp[i], 2);
        dp[i] += __shfl_xor_sync(0xffffffffu, dp[i], 1);
        dp[i] += __shfl_xor_sync(0xffffffffu, dp[i], 2);
    }
    if ((lane & 3) == 0) {
        int r0 = warp_m * 32 + (lane >> 2);
        atomicAdd(&alpha_s[r0],      sp[0]);
        atomicAdd(&alpha_s[r0 + 8],  sp[1]);
        atomicAdd(&alpha_s[r0 + 16], sp[2]);
        atomicAdd(&alpha_s[r0 + 24], sp[3]);
        atomicAdd(&alpha_d[r0],      dp[0]);
        atomicAdd(&alpha_d[r0 + 8],  dp[1]);
        atomicAdd(&alpha_d[r0 + 16], dp[2]);
        atomicAdd(&alpha_d[r0 + 24], dp[3]);
    }
    __syncthreads();
    if (tid < 128) {
        int gr = m0 + tid;
        if (gr < M) {
            ASg[gr * 4] = alpha_s[tid];   // heads=1: slot 0 of the 4-wide array
            ADg[gr * 4] = alpha_d[tid];
        }
    }
}

// ---------------------------------------------------------------------------
// conv2 aggregation (heads=1, D=64) fused with mean-pool accumulation.
// ---------------------------------------------------------------------------
__global__ void agg2_pool_kernel(const int* __restrict__ rowptr,
                                 const int* __restrict__ ecol,
                                 const float* __restrict__ AS,
                                 const float* __restrict__ AD,
                                 const float* __restrict__ H2,
                                 const float* __restrict__ bias,
                                 const int* __restrict__ bt0,
                                 const int* __restrict__ bt1,
                                 float* __restrict__ POOL,
                                 float* __restrict__ CNT,
                                 int n) {
    const int g = blockIdx.y;
    const int* rp = rowptr + g * (NMAX + 1);
    const int* ec = ecol + (size_t)g * EMAX;
    const float* as = AS + (size_t)g * NMAX * 4;
    const float* ad = AD + (size_t)g * NMAX * 4;
    const float* H = H2 + (size_t)g * NMAX * 64;
    const int* batch = g ? bt1 : bt0;
    float* pool = POOL + g * GNUM * 64;
    float* cnt = CNT + g * GNUM;

    const int warp = (blockIdx.x * blockDim.x + threadIdx.x) >> 5;
    const int lane = threadIdx.x & 31;
    if (warp >= n) return;
    const int d = warp;
    const int beg = rp[d];
    const int end = rp[d + 1];

    float ad_d = ad[d * 4];
    float self_e = leaky(as[d * 4] + ad_d);
    float mx = self_e;
    for (int j = beg + lane; j < end; j += 32)
        mx = fmaxf(mx, leaky(as[ec[j] * 4] + ad_d));
    #pragma unroll
    for (int off = 16; off >= 1; off >>= 1)
        mx = fmaxf(mx, __shfl_xor_sync(0xffffffffu, mx, off));

    float ex = __expf(self_e - mx);
    float den = ex;
    float2 hv = *(const float2*)&H[(size_t)d * 64 + lane * 2];
    float a0 = ex * hv.x, a1 = ex * hv.y;
    for (int j = beg; j < end; j++) {
        int s = ec[j];
        float e = __expf(leaky(as[s * 4] + ad_d) - mx);
        den += e;
        float2 hs = *(const float2*)&H[(size_t)s * 64 + lane * 2];
        a0 += e * hs.x;
        a1 += e * hs.y;
    }
    float inv = 1.0f / (den + 1e-16f);
    float v0 = a0 * inv + bias[lane * 2];
    float v1 = a1 * inv + bias[lane * 2 + 1];
    v0 = v0 > 0.0f ? v0 : (__expf(v0) - 1.0f);
    v1 = v1 > 0.0f ? v1 : (__expf(v1) - 1.0f);
    int grp = batch[d];
    atomicAdd(&pool[grp * 64 + lane * 2], v0);
    atomicAdd(&pool[grp * 64 + lane * 2 + 1], v1);
    if (lane == 0) atomicAdd(&cnt[grp], 1.0f);
}

__global__ void final_write_kernel(const float* __restrict__ POOL,
                                   const float* __restrict__ CNT,
                                   float* __restrict__ out) {
    int i = blockIdx.x * blockDim.x + threadIdx.x;
    if (i >= 2 * GNUM * 64) return;
    float c = CNT[i >> 6];
    out[i] = POOL[i] / fmaxf(c, 1.0f);
}

// ---------------------------------------------------------------------------
// Launch
// ---------------------------------------------------------------------------
extern "C" void kernel_launch(void* const* d_in, const int* in_sizes, int n_in,
                              void* d_out, int out_size) {
    const float* x1  = (const float*)d_in[0];
    const int*   ei1 = (const int*)d_in[1];
    const int*   bt1 = (const int*)d_in[2];
    const float* x2  = (const float*)d_in[3];
    const int*   ei2 = (const int*)d_in[4];
    const int*   bt2 = (const int*)d_in[5];
    const float* W1  = (const float*)d_in[6];
    const float* as1 = (const float*)d_in[7];
    const float* ad1 = (const float*)d_in[8];
    const float* b1  = (const float*)d_in[9];
    const float* W2  = (const float*)d_in[10];
    const float* as2 = (const float*)d_in[11];
    const float* ad2 = (const float*)d_in[12];
    const float* b2  = (const float*)d_in[13];

    const int n = in_sizes[0] / 128;
    const int e = in_sizes[1] / 2;
    const int nb = cdiv(n, SCAN_CHUNK);

    float *AGG, *OUT, *H2, *AS, *AD, *POOL, *CNT, *P1S, *P1D;
    int *DEG, *ROWPTR, *CUR, *ECOL, *PART;
    __nv_bfloat16 *W1TH, *W1TL, *W2TH, *W2TL;
    cudaGetSymbolAddress((void**)&AGG,    g_AGG);
    cudaGetSymbolAddress((void**)&OUT,    g_OUT);
    cudaGetSymbolAddress((void**)&H2,     g_H2);
    cudaGetSymbolAddress((void**)&AS,     g_AS);
    cudaGetSymbolAddress((void**)&AD,     g_AD);
    cudaGetSymbolAddress((void**)&DEG,    g_DEG);
    cudaGetSymbolAddress((void**)&ROWPTR, g_ROWPTR);
    cudaGetSymbolAddress((void**)&CUR,    g_CUR);
    cudaGetSymbolAddress((void**)&ECOL,   g_ECOL);
    cudaGetSymbolAddress((void**)&PART,   g_PART);
    cudaGetSymbolAddress((void**)&POOL,   g_POOL);
    cudaGetSymbolAddress((void**)&CNT,    g_CNT);
    cudaGetSymbolAddress((void**)&P1S,    g_P1S);
    cudaGetSymbolAddress((void**)&P1D,    g_P1D);
    cudaGetSymbolAddress((void**)&W1TH,   g_W1T_HI);
    cudaGetSymbolAddress((void**)&W1TL,   g_W1T_LO);
    cudaGetSymbolAddress((void**)&W2TH,   g_W2T_HI);
    cudaGetSymbolAddress((void**)&W2TL,   g_W2T_LO);

    cudaFuncSetAttribute(gemm1_kernel, cudaFuncAttributeMaxDynamicSharedMemorySize, SM_TOTAL);
    cudaFuncSetAttribute(gemm2_kernel, cudaFuncAttributeMaxDynamicSharedMemorySize, SM_TOTAL);

    // 1. setup (pool zero + weight prep + P fold)
    setup_kernel<<<cdiv(SETUP_TOTAL, 256), 256>>>(W1, W2, as1, ad1,
                                                  W1TH, W1TL, W2TH, W2TL,
                                                  P1S, P1D, POOL, CNT);
    // 2-7. CSR build for both graphs
    {
        dim3 gy2(cdiv(n, 256), 2);
        deg_zero_kernel<<<gy2, 256>>>(DEG, n);
    }
    {
        dim3 ge2(cdiv(e, 256), 2);
        hist_kernel<<<ge2, 256>>>(ei1, ei2, DEG, e);
    }
    {
        dim3 gs2(nb, 2);
        scan_partial_kernel<<<gs2, 256>>>(DEG, PART, n);
        scan_root_kernel<<<2, 32>>>(PART, nb);
        scan_final_kernel<<<gs2, 256>>>(DEG, PART, ROWPTR, CUR, n, nb);
    }
    {
        dim3 ge2(cdiv(e, 256), 2);
        fill_kernel<<<ge2, 256>>>(ei1, ei2, CUR, ECOL, e);
    }
    // 8. conv1 alphas from x
    {
        dim3 ga(cdiv(n, 8), 2);
        alphas_x_kernel<<<ga, 256>>>(x1, x2, P1S, P1D, AS, AD, n);
    }
    // 9. conv1 aggregate-first
    {
        dim3 ga(cdiv(n, 8), 2);
        agg_x_kernel<<<ga, 256>>>(ROWPTR, ECOL, AS, AD, x1, x2, AGG, n);
    }
    // 10. conv1 GEMM + bias + ELU
    {
        dim3 gg(4, cdiv(n, 128), 2);
        gemm1_kernel<<<gg, 256, SM_TOTAL>>>(AGG, W1TH, W1TL, b1, OUT, n);
    }
    // 11. conv2 GEMM + alpha epilogue
    {
        dim3 gg(1, cdiv(n, 128), 2);
        gemm2_kernel<<<gg, 256, SM_TOTAL>>>(OUT, W2TH, W2TL, H2, as2, ad2, AS, AD, n);
    }
    // 12. conv2 aggregation + pooling
    {
        dim3 ga(cdiv(n, 8), 2);
        agg2_pool_kernel<<<ga, 256>>>(ROWPTR, ECOL, AS, AD, H2, b2,
                                      bt1, bt2, POOL, CNT, n);
    }
    // 13. final mean
    final_write_kernel<<<cdiv(2 * GNUM * 64, 256), 256>>>(POOL, CNT, (float*)d_out);
}

// round 8
// speedup vs baseline: 1.0453x; 1.0453x over previous
#include <cuda_runtime.h>
#include <cuda_bf16.h>
#include <cstdint>

// ---------------------------------------------------------------------------
// GATGraphSimilarity: Siamese 2-layer GAT (heads=4 then 1) + mean pool.
// Round 8: bf16 message compression end-to-end on the edge-gather paths:
//   x -> X16 (bf16, written inside alphas kernel), conv1 gathers 256B/edge;
//   AGG stored bf16 (direct MMA A operand, 2-term GEMM1);
//   H2 stored bf16 (conv2 gather 128B/edge).
// Alphas/softmax/accumulators all stay fp32. Dual-graph fused launches.
// ---------------------------------------------------------------------------

#define NMAX 50000
#define EMAX 800000
#define GNUM 64
#define NEG_SLOPE 0.2f
#define SCAN_CHUNK 4096
#define SCAN_NB ((NMAX + SCAN_CHUNK - 1) / SCAN_CHUNK)

__device__ __nv_bfloat16 g_X16[2][(size_t)NMAX * 128];   // bf16 copy of x
__device__ __nv_bfloat16 g_AGG[2][(size_t)NMAX * 512];   // aggregated x [n][4][128] bf16
__device__ float g_OUT [2][(size_t)NMAX * 256];          // conv1 output (elu'd) fp32
__device__ __nv_bfloat16 g_H2 [2][(size_t)NMAX * 64];    // conv2 pre-agg features bf16
__device__ float g_AS  [2][NMAX * 4];
__device__ float g_AD  [2][NMAX * 4];
__device__ int   g_DEG [2][NMAX];
__device__ int   g_ROWPTR[2][NMAX + 1];
__device__ int   g_CUR [2][NMAX];
__device__ int   g_ECOL[2][EMAX];
__device__ int   g_PART[2][SCAN_NB + 1];
__device__ float g_POOL[2 * GNUM * 64];
__device__ float g_CNT [2 * GNUM];
__device__ float g_P1S [128 * 4];
__device__ float g_P1D [128 * 4];
__device__ __nv_bfloat16 g_W1T_HI[256 * 128];            // [N,K] K-contiguous
__device__ __nv_bfloat16 g_W1T_LO[256 * 128];
__device__ __nv_bfloat16 g_W2T_HI[64 * 256];
__device__ __nv_bfloat16 g_W2T_LO[64 * 256];

static inline int cdiv(int a, int b) { return (a + b - 1) / b; }

__device__ __forceinline__ float leaky(float v) {
    return v > 0.0f ? v : NEG_SLOPE * v;
}

__device__ __forceinline__ uint32_t bf2u(__nv_bfloat162 v) {
    return *reinterpret_cast<uint32_t*>(&v);
}

__device__ __forceinline__ void mma16816(float* d, const uint32_t* a, const uint32_t* b) {
    asm volatile(
        "mma.sync.aligned.m16n8k16.row.col.f32.bf16.bf16.f32 "
        "{%0,%1,%2,%3}, {%4,%5,%6,%7}, {%8,%9}, {%0,%1,%2,%3};"
        : "+f"(d[0]), "+f"(d[1]), "+f"(d[2]), "+f"(d[3])
        : "r"(a[0]), "r"(a[1]), "r"(a[2]), "r"(a[3]), "r"(b[0]), "r"(b[1]));
}

// ---------------------------------------------------------------------------
// Setup: weight prep, P1 fold, pool zero, DEG zero
// ---------------------------------------------------------------------------
#define SEG1 (256 * 128)
#define SEG2 (64 * 256)
#define SEG3 1024
#define SEG4 (2 * GNUM * 64 + 2 * GNUM)
#define SEG5 (2 * NMAX)
#define SETUP_TOTAL (SEG1 + SEG2 + SEG3 + SEG4 + SEG5)

__global__ void setup_kernel(const float* __restrict__ W1,
                             const float* __restrict__ W2,
                             const float* __restrict__ as1,
                             const float* __restrict__ ad1,
                             __nv_bfloat16* __restrict__ W1TH,
                             __nv_bfloat16* __restrict__ W1TL,
                             __nv_bfloat16* __restrict__ W2TH,
                             __nv_bfloat16* __restrict__ W2TL,
                             float* __restrict__ P1S,
                             float* __restrict__ P1D,
                             float* __restrict__ POOL,
                             float* __restrict__ CNT,
                             int* __restrict__ DEG) {
    int i = blockIdx.x * blockDim.x + threadIdx.x;
    if (i < SEG1) {
        int n = i / 128, k = i % 128;
        float v = W1[(size_t)k * 256 + n];
        __nv_bfloat16 h = __float2bfloat16(v);
        W1TH[i] = h;
        W1TL[i] = __float2bfloat16(v - __bfloat162float(h));
        return;
    }
    i -= SEG1;
    if (i < SEG2) {
        int n = i / 256, k = i % 256;
        float v = W2[(size_t)k * 64 + n];
        __nv_bfloat16 h = __float2bfloat16(v);
        W2TH[i] = h;
        W2TL[i] = __float2bfloat16(v - __bfloat162float(h));
        return;
    }
    i -= SEG2;
    if (i < SEG3) {
        int is_dst = i >> 9;
        int o = i & 511;
        int k = o >> 2, h = o & 3;
        const float* a = is_dst ? ad1 : as1;
        float s = 0.0f;
        #pragma unroll 8
        for (int d = 0; d < 64; d++)
            s += W1[(size_t)k * 256 + h * 64 + d] * a[h * 64 + d];
        (is_dst ? P1D : P1S)[k * 4 + h] = s;
        return;
    }
    i -= SEG3;
    if (i < 2 * GNUM * 64) { POOL[i] = 0.0f; return; }
    i -= 2 * GNUM * 64;
    if (i < 2 * GNUM) { CNT[i] = 0.0f; return; }
    i -= 2 * GNUM;
    if (i < SEG5) DEG[i] = 0;
}

// ---------------------------------------------------------------------------
// CSR build (dual-graph)
// ---------------------------------------------------------------------------
__global__ void hist_kernel(const int* __restrict__ ei0, const int* __restrict__ ei1,
                            int* __restrict__ deg, int E) {
    int g = blockIdx.y;
    const int* ei = g ? ei1 : ei0;
    int i = blockIdx.x * blockDim.x + threadIdx.x;
    if (i < E) atomicAdd(&deg[g * NMAX + ei[E + i]], 1);
}

__global__ void scan_partial_kernel(const int* __restrict__ deg,
                                    int* __restrict__ part, int n) {
    __shared__ int red[256];
    const int g = blockIdx.y;
    const int t = threadIdx.x;
    const int base = blockIdx.x * SCAN_CHUNK + t * 16;
    int s = 0;
    #pragma unroll
    for (int q = 0; q < 16; q++) {
        int i = base + q;
        if (i < n) s += deg[g * NMAX + i];
    }
    red[t] = s;
    __syncthreads();
    #pragma unroll
    for (int off = 128; off >= 1; off >>= 1) {
        if (t < off) red[t] += red[t + off];
        __syncthreads();
    }
    if (t == 0) part[g * (SCAN_NB + 1) + blockIdx.x] = red[0];
}

__global__ void scan_root_kernel(int* __restrict__ part, int nb) {
    int g = blockIdx.x;
    if (threadIdx.x == 0) {
        int* p = part + g * (SCAN_NB + 1);
        int run = 0;
        for (int i = 0; i < nb; i++) {
            int v = p[i];
            p[i] = run;
            run += v;
        }
        p[nb] = run;
    }
}

__global__ void scan_final_kernel(const int* __restrict__ deg,
                                  const int* __restrict__ part,
                                  int* __restrict__ rowptr,
                                  int* __restrict__ cur,
                                  int n, int nb) {
    __shared__ int thr[256];
    const int g = blockIdx.y;
    const int t = threadIdx.x;
    const int base = blockIdx.x * SCAN_CHUNK + t * 16;
    const int* dg = deg + g * NMAX;
    int* rp = rowptr + g * (NMAX + 1);
    int* cu = cur + g * NMAX;
    int s = 0;
    int dloc[16];
    #pragma unroll
    for (int q = 0; q < 16; q++) {
        int i = base + q;
        dloc[q] = (i < n) ? dg[i] : 0;
        s += dloc[q];
    }
    thr[t] = s;
    __syncthreads();
    #pragma unroll
    for (int off = 1; off < 256; off <<= 1) {
        int v = (t >= off) ? thr[t - off] : 0;
        __syncthreads();
        thr[t] += v;
        __syncthreads();
    }
    int offset = part[g * (SCAN_NB + 1) + blockIdx.x] + ((t == 0) ? 0 : thr[t - 1]);
    #pragma unroll
    for (int q = 0; q < 16; q++) {
        int i = base + q;
        if (i < n) {
            rp[i] = offset;
            cu[i] = offset;
            offset += dloc[q];
        }
    }
    if (blockIdx.x == 0 && t == 0) rp[n] = part[g * (SCAN_NB + 1) + nb];
}

__global__ void fill_kernel(const int* __restrict__ ei0, const int* __restrict__ ei1,
                            int* __restrict__ cur, int* __restrict__ ecol, int E) {
    int g = blockIdx.y;
    const int* ei = g ? ei1 : ei0;
    int i = blockIdx.x * blockDim.x + threadIdx.x;
    if (i >= E) return;
    int s = ei[i];
    int d = ei[E + i];
    int slot = atomicAdd(&cur[g * NMAX + d], 1);
    ecol[(size_t)g * EMAX + slot] = s;
}

// ---------------------------------------------------------------------------
// conv1 alphas from raw x (fp32, exact) + X16 bf16 conversion (fused).
// ---------------------------------------------------------------------------
__global__ void alphas_x_kernel(const float* __restrict__ x0,
                                const float* __restrict__ x1,
                                const float* __restrict__ P1S,
                                const float* __restrict__ P1D,
                                float* __restrict__ AS,
                                float* __restrict__ AD,
                                __nv_bfloat16* __restrict__ X16,
                                int n) {
    const int g = blockIdx.y;
    const float* x = g ? x1 : x0;
    const int warp = (blockIdx.x * blockDim.x + threadIdx.x) >> 5;
    const int lane = threadIdx.x & 31;
    if (warp >= n) return;
    float4 xv = *(const float4*)&x[(size_t)warp * 128 + lane * 4];

    // X16 write
    {
        __nv_bfloat162 p0 = __floats2bfloat162_rn(xv.x, xv.y);
        __nv_bfloat162 p1 = __floats2bfloat162_rn(xv.z, xv.w);
        uint2 u = make_uint2(bf2u(p0), bf2u(p1));
        *(uint2*)&X16[(size_t)g * NMAX * 128 + (size_t)warp * 128 + lane * 4] = u;
    }

    float s[4] = {0.f, 0.f, 0.f, 0.f};
    float d[4] = {0.f, 0.f, 0.f, 0.f};
    const float* xp = (const float*)&xv;
    #pragma unroll
    for (int j = 0; j < 4; j++) {
        float xk = xp[j];
        float4 ps = *(const float4*)&P1S[(lane * 4 + j) * 4];
        float4 pd = *(const float4*)&P1D[(lane * 4 + j) * 4];
        s[0] += xk * ps.x; s[1] += xk * ps.y; s[2] += xk * ps.z; s[3] += xk * ps.w;
        d[0] += xk * pd.x; d[1] += xk * pd.y; d[2] += xk * pd.z; d[3] += xk * pd.w;
    }
    #pragma unroll
    for (int off = 16; off >= 1; off >>= 1) {
        #pragma unroll
        for (int h = 0; h < 4; h++) {
            s[h] += __shfl_xor_sync(0xffffffffu, s[h], off);
            d[h] += __shfl_xor_sync(0xffffffffu, d[h], off);
        }
    }
    if (lane == 0) {
        *(float4*)&AS[(size_t)g * NMAX * 4 + warp * 4] = make_float4(s[0], s[1], s[2], s[3]);
        *(float4*)&AD[(size_t)g * NMAX * 4 + warp * 4] = make_float4(d[0], d[1], d[2], d[3]);
    }
}

// ---------------------------------------------------------------------------
// conv1 aggregate-first: warp per dst node, gather bf16 x rows (256B/edge),
// fp32 accumulate, write normalized AGG bf16 [n][4][128].
// ---------------------------------------------------------------------------
__global__ void agg_x_kernel(const int* __restrict__ rowptr,
                             const int* __restrict__ ecol,
                             const float* __restrict__ AS,
                             const float* __restrict__ AD,
                             const __nv_bfloat16* __restrict__ X16,
                             __nv_bfloat16* __restrict__ AGG,
                             int n) {
    const int g = blockIdx.y;
    const int* rp = rowptr + g * (NMAX + 1);
    const int* ec = ecol + (size_t)g * EMAX;
    const float* as = AS + (size_t)g * NMAX * 4;
    const float* ad = AD + (size_t)g * NMAX * 4;
    const __nv_bfloat16* X = X16 + (size_t)g * NMAX * 128;
    __nv_bfloat16* agg = AGG + (size_t)g * NMAX * 512;

    const int warp = (blockIdx.x * blockDim.x + threadIdx.x) >> 5;
    const int lane = threadIdx.x & 31;
    if (warp >= n) return;
    const int d = warp;
    const int beg = rp[d];
    const int end = rp[d + 1];

    float4 adv = *(const float4*)&ad[d * 4];
    float4 asv = *(const float4*)&as[d * 4];
    float self_e[4] = {leaky(asv.x + adv.x), leaky(asv.y + adv.y),
                       leaky(asv.z + adv.z), leaky(asv.w + adv.w)};
    float mx[4] = {self_e[0], self_e[1], self_e[2], self_e[3]};

    for (int j = beg + lane; j < end; j += 32) {
        int s = ec[j];
        float4 a4 = *(const float4*)&as[s * 4];
        mx[0] = fmaxf(mx[0], leaky(a4.x + adv.x));
        mx[1] = fmaxf(mx[1], leaky(a4.y + adv.y));
        mx[2] = fmaxf(mx[2], leaky(a4.z + adv.z));
        mx[3] = fmaxf(mx[3], leaky(a4.w + adv.w));
    }
    #pragma unroll
    for (int h = 0; h < 4; h++) {
        #pragma unroll
        for (int off = 16; off >= 1; off >>= 1)
            mx[h] = fmaxf(mx[h], __shfl_xor_sync(0xffffffffu, mx[h], off));
    }

    // self feature (bf16, consistent with gathered messages)
    uint2 ux = *(const uint2*)&X[(size_t)d * 128 + lane * 4];
    float2 xd01 = __bfloat1622float2(*(__nv_bfloat162*)&ux.x);
    float2 xd23 = __bfloat1622float2(*(__nv_bfloat162*)&ux.y);

    float den[4], acc[4][4];
    #pragma unroll
    for (int h = 0; h < 4; h++) {
        float ex = __expf(self_e[h] - mx[h]);
        den[h] = ex;
        acc[h][0] = ex * xd01.x; acc[h][1] = ex * xd01.y;
        acc[h][2] = ex * xd23.x; acc[h][3] = ex * xd23.y;
    }
    for (int j = beg; j < end; j++) {
        int s = ec[j];
        float4 a4 = *(const float4*)&as[s * 4];
        float e0 = __expf(leaky(a4.x + adv.x) - mx[0]);
        float e1 = __expf(leaky(a4.y + adv.y) - mx[1]);
        float e2 = __expf(leaky(a4.z + adv.z) - mx[2]);
        float e3 = __expf(leaky(a4.w + adv.w) - mx[3]);
        den[0] += e0; den[1] += e1; den[2] += e2; den[3] += e3;
        uint2 us = *(const uint2*)&X[(size_t)s * 128 + lane * 4];
        float2 f01 = __bfloat1622float2(*(__nv_bfloat162*)&us.x);
        float2 f23 = __bfloat1622float2(*(__nv_bfloat162*)&us.y);
        acc[0][0] += e0 * f01.x; acc[0][1] += e0 * f01.y; acc[0][2] += e0 * f23.x; acc[0][3] += e0 * f23.y;
        acc[1][0] += e1 * f01.x; acc[1][1] += e1 * f01.y; acc[1][2] += e1 * f23.x; acc[1][3] += e1 * f23.y;
        acc[2][0] += e2 * f01.x; acc[2][1] += e2 * f01.y; acc[2][2] += e2 * f23.x; acc[2][3] += e2 * f23.y;
        acc[3][0] += e3 * f01.x; acc[3][1] += e3 * f01.y; acc[3][2] += e3 * f23.x; acc[3][3] += e3 * f23.y;
    }
    #pragma unroll
    for (int h = 0; h < 4; h++) {
        float inv = 1.0f / (den[h] + 1e-16f);
        __nv_bfloat162 q0 = __floats2bfloat162_rn(acc[h][0] * inv, acc[h][1] * inv);
        __nv_bfloat162 q1 = __floats2bfloat162_rn(acc[h][2] * inv, acc[h][3] * inv);
        uint2 u = make_uint2(bf2u(q0), bf2u(q1));
        *(uint2*)&agg[(size_t)d * 512 + h * 128 + lane * 4] = u;
    }
}

// ---------------------------------------------------------------------------
// GEMM1: OUT[:, h*64:+64] = elu(AGG[:,h,:] @ W1T[h]^T + b1).  A is bf16 (AGG),
// 2-term MMA (A.Bh + A.Bl). Smem ~70KB -> up to 3 blocks/SM.
// ---------------------------------------------------------------------------
#define SM1_AH 0
#define SM1_BH 34816
#define SM1_BL 52224
#define SM1_TOTAL 69632

__global__ __launch_bounds__(256)
void gemm1_kernel(const __nv_bfloat16* __restrict__ AGG,
                  const __nv_bfloat16* __restrict__ Bhi,
                  const __nv_bfloat16* __restrict__ Blo,
                  const float* __restrict__ bias,
                  float* __restrict__ OUT,
                  int M) {
    extern __shared__ char smem[];
    uint32_t* Ah = (uint32_t*)(smem + SM1_AH);
    uint32_t* Bh = (uint32_t*)(smem + SM1_BH);
    uint32_t* Bl = (uint32_t*)(smem + SM1_BL);

    const int g = blockIdx.z;
    const __nv_bfloat16* A = AGG + (size_t)g * NMAX * 512;
    float* C = OUT + (size_t)g * NMAX * 256;
    const int tid = threadIdx.x;
    const int lane = tid & 31;
    const int wid = tid >> 5;
    const int warp_m = wid & 3;
    const int warp_n = wid >> 2;
    const int h = blockIdx.x;
    const int m0 = blockIdx.y * 128;

    float acc[2][4][4] = {};

    // A: 128 rows x 128 k bf16 (2048 uint4 slots, 8 per thread)
    #pragma unroll
    for (int q = 0; q < 8; q++) {
        int idx = q * 256 + tid;
        int r = idx >> 4;
        int c8 = idx & 15;
        int gr = m0 + r;
        uint4 v = make_uint4(0u, 0u, 0u, 0u);
        if (gr < M) v = *(const uint4*)&A[(size_t)gr * 512 + h * 128 + c8 * 8];
        *(uint4*)&Ah[r * 68 + c8 * 4] = v;
    }
    // B: rows h*64..+63 of W1T
    #pragma unroll
    for (int q = 0; q < 4; q++) {
        int idx = q * 256 + tid;
        int r = idx >> 4;
        int c8 = idx & 15;
        uint4 vh = *(const uint4*)&Bhi[(size_t)(h * 64 + r) * 128 + c8 * 8];
        uint4 vl = *(const uint4*)&Blo[(size_t)(h * 64 + r) * 128 + c8 * 8];
        *(uint4*)&Bh[r * 68 + c8 * 4] = vh;
        *(uint4*)&Bl[r * 68 + c8 * 4] = vl;
    }
    __syncthreads();

    #pragma unroll
    for (int ks = 0; ks < 8; ks++) {
        const int kw = ks * 8 + (lane & 3);
        uint32_t ah[2][4], bh[4][2], bl[4][2];
        #pragma unroll
        for (int mt = 0; mt < 2; mt++) {
            int r0 = warp_m * 32 + mt * 16 + (lane >> 2);
            ah[mt][0] = Ah[r0 * 68 + kw];
            ah[mt][1] = Ah[(r0 + 8) * 68 + kw];
            ah[mt][2] = Ah[r0 * 68 + kw + 4];
            ah[mt][3] = Ah[(r0 + 8) * 68 + kw + 4];
        }
        #pragma unroll
        for (int nt = 0; nt < 4; nt++) {
            int n0 = warp_n * 32 + nt * 8 + (lane >> 2);
            bh[nt][0] = Bh[n0 * 68 + kw];
            bh[nt][1] = Bh[n0 * 68 + kw + 4];
            bl[nt][0] = Bl[n0 * 68 + kw];
            bl[nt][1] = Bl[n0 * 68 + kw + 4];
        }
        #pragma unroll
        for (int mt = 0; mt < 2; mt++)
            #pragma unroll
            for (int nt = 0; nt < 4; nt++) {
                mma16816(acc[mt][nt], ah[mt], bh[nt]);
                mma16816(acc[mt][nt], ah[mt], bl[nt]);
            }
    }

    #pragma unroll
    for (int mt = 0; mt < 2; mt++) {
        int r0 = warp_m * 32 + mt * 16 + (lane >> 2);
        #pragma unroll
        for (int nt = 0; nt < 4; nt++) {
            int c0 = warp_n * 32 + nt * 8 + (lane & 3) * 2;
            float b0 = __ldg(&bias[h * 64 + c0]);
            float b1v = __ldg(&bias[h * 64 + c0 + 1]);
            float* a4 = acc[mt][nt];
            float v00 = a4[0] + b0, v01 = a4[1] + b1v;
            float v10 = a4[2] + b0, v11 = a4[3] + b1v;
            v00 = v00 > 0.f ? v00 : (__expf(v00) - 1.f);
            v01 = v01 > 0.f ? v01 : (__expf(v01) - 1.f);
            v10 = v10 > 0.f ? v10 : (__expf(v10) - 1.f);
            v11 = v11 > 0.f ? v11 : (__expf(v11) - 1.f);
            int gr0 = m0 + r0, gr1 = gr0 + 8;
            if (gr0 < M) *(float2*)&C[(size_t)gr0 * 256 + h * 64 + c0] = make_float2(v00, v01);
            if (gr1 < M) *(float2*)&C[(size_t)gr1 * 256 + h * 64 + c0] = make_float2(v10, v11);
        }
    }
}

// ---------------------------------------------------------------------------
// GEMM2: H2(bf16) = OUT @ W2 (K=256, N=64), split-bf16 A, alpha epilogue fp32.
// ---------------------------------------------------------------------------
#define SM_AH 0
#define SM_AL 34816
#define SM_BH 69632
#define SM_BL 87040
#define SM_ALPHA 104448
#define SM_TOTAL 105472

__global__ __launch_bounds__(256, 1)
void gemm2_kernel(const float* __restrict__ OUT,
                  const __nv_bfloat16* __restrict__ Bhi,
                  const __nv_bfloat16* __restrict__ Blo,
                  __nv_bfloat16* __restrict__ H2,
                  const float* __restrict__ a_src,
                  const float* __restrict__ a_dst,
                  float* __restrict__ AS,
                  float* __restrict__ AD,
                  int M) {
    extern __shared__ char smem[];
    uint32_t* Ah = (uint32_t*)(smem + SM_AH);
    uint32_t* Al = (uint32_t*)(smem + SM_AL);
    uint32_t* Bh = (uint32_t*)(smem + SM_BH);
    uint32_t* Bl = (uint32_t*)(smem + SM_BL);
    float* alpha_s = (float*)(smem + SM_ALPHA);
    float* alpha_d = alpha_s + 128;

    const int g = blockIdx.z;
    const float* A = OUT + (size_t)g * NMAX * 256;
    __nv_bfloat16* C = H2 + (size_t)g * NMAX * 64;
    float* ASg = AS + (size_t)g * NMAX * 4;
    float* ADg = AD + (size_t)g * NMAX * 4;
    const int tid = threadIdx.x;
    const int lane = tid & 31;
    const int wid = tid >> 5;
    const int warp_m = wid & 3;
    const int warp_n = wid >> 2;
    const int m0 = blockIdx.y * 128;

    float acc[2][4][4] = {};

    for (int kc = 0; kc < 256; kc += 128) {
        #pragma unroll
        for (int q = 0; q < 16; q++) {
            int idx = q * 256 + tid;
            int r = idx >> 5;
            int c4 = idx & 31;
            int gr = m0 + r;
            float4 v = make_float4(0.f, 0.f, 0.f, 0.f);
            if (gr < M) v = *(const float4*)&A[(size_t)gr * 256 + kc + c4 * 4];
            __nv_bfloat162 hxy = __floats2bfloat162_rn(v.x, v.y);
            __nv_bfloat162 hzw = __floats2bfloat162_rn(v.z, v.w);
            float2 fxy = __bfloat1622float2(hxy);
            float2 fzw = __bfloat1622float2(hzw);
            __nv_bfloat162 lxy = __floats2bfloat162_rn(v.x - fxy.x, v.y - fxy.y);
            __nv_bfloat162 lzw = __floats2bfloat162_rn(v.z - fzw.x, v.w - fzw.y);
            int w = r * 68 + c4 * 2;
            Ah[w] = bf2u(hxy); Ah[w + 1] = bf2u(hzw);
            Al[w] = bf2u(lxy); Al[w + 1] = bf2u(lzw);
        }
        #pragma unroll
        for (int q = 0; q < 4; q++) {
            int idx = q * 256 + tid;
            int r = idx >> 4;
            int c8 = idx & 15;
            uint4 vh = *(const uint4*)&Bhi[(size_t)r * 256 + kc + c8 * 8];
            uint4 vl = *(const uint4*)&Blo[(size_t)r * 256 + kc + c8 * 8];
            *(uint4*)&Bh[r * 68 + c8 * 4] = vh;
            *(uint4*)&Bl[r * 68 + c8 * 4] = vl;
        }
        __syncthreads();

        #pragma unroll
        for (int ks = 0; ks < 8; ks++) {
            const int kw = ks * 8 + (lane & 3);
            uint32_t ah[2][4], al[2][4], bh[4][2], bl[4][2];
            #pragma unroll
            for (int mt = 0; mt < 2; mt++) {
                int r0 = warp_m * 32 + mt * 16 + (lane >> 2);
                ah[mt][0] = Ah[r0 * 68 + kw];
                ah[mt][1] = Ah[(r0 + 8) * 68 + kw];
                ah[mt][2] = Ah[r0 * 68 + kw + 4];
                ah[mt][3] = Ah[(r0 + 8) * 68 + kw + 4];
                al[mt][0] = Al[r0 * 68 + kw];
                al[mt][1] = Al[(r0 + 8) * 68 + kw];
                al[mt][2] = Al[r0 * 68 + kw + 4];
                al[mt][3] = Al[(r0 + 8) * 68 + kw + 4];
            }
            #pragma unroll
            for (int nt = 0; nt < 4; nt++) {
                int n0 = warp_n * 32 + nt * 8 + (lane >> 2);
                bh[nt][0] = Bh[n0 * 68 + kw];
                bh[nt][1] = Bh[n0 * 68 + kw + 4];
                bl[nt][0] = Bl[n0 * 68 + kw];
                bl[nt][1] = Bl[n0 * 68 + kw + 4];
            }
            #pragma unroll
            for (int mt = 0; mt < 2; mt++)
                #pragma unroll
                for (int nt = 0; nt < 4; nt++) {
                    mma16816(acc[mt][nt], ah[mt], bh[nt]);
                    mma16816(acc[mt][nt], ah[mt], bl[nt]);
                    mma16816(acc[mt][nt], al[mt], bh[nt]);
                }
        }
        __syncthreads();
    }

    if (tid < 128) { alpha_s[tid] = 0.0f; alpha_d[tid] = 0.0f; }
    __syncthreads();

    float sp[4] = {0.f, 0.f, 0.f, 0.f};
    float dp[4] = {0.f, 0.f, 0.f, 0.f};
    #pragma unroll
    for (int mt = 0; mt < 2; mt++) {
        int r0 = warp_m * 32 + mt * 16 + (lane >> 2);
        #pragma unroll
        for (int nt = 0; nt < 4; nt++) {
            int c0 = warp_n * 32 + nt * 8 + (lane & 3) * 2;
            float* a4 = acc[mt][nt];
            int gr0 = m0 + r0, gr1 = gr0 + 8;
            if (gr0 < M)
                *(__nv_bfloat162*)&C[(size_t)gr0 * 64 + c0] = __floats2bfloat162_rn(a4[0], a4[1]);
            if (gr1 < M)
                *(__nv_bfloat162*)&C[(size_t)gr1 * 64 + c0] = __floats2bfloat162_rn(a4[2], a4[3]);
            float s0 = __ldg(&a_src[c0]);
            float s1 = __ldg(&a_src[c0 + 1]);
            float d0 = __ldg(&a_dst[c0]);
            float d1 = __ldg(&a_dst[c0 + 1]);
            sp[mt * 2]     += a4[0] * s0 + a4[1] * s1;
            sp[mt * 2 + 1] += a4[2] * s0 + a4[3] * s1;
            dp[mt * 2]     += a4[0] * d0 + a4[1] * d1;
            dp[mt * 2 + 1] += a4[2] * d0 + a4[3] * d1;
        }
    }
    #pragma unroll
    for (int i = 0; i < 4; i++) {
        sp[i] += __shfl_xor_sync(0xffffffffu, sp[i], 1);
        sp[i] += __shfl_xor_sync(0xffffffffu, sp[i], 2);
        dp[i] += __shfl_xor_sync(0xffffffffu, dp[i], 1);
        dp[i] += __shfl_xor_sync(0xffffffffu, dp[i], 2);
    }
    if ((lane & 3) == 0) {
        int r0 = warp_m * 32 + (lane >> 2);
        atomicAdd(&alpha_s[r0],      sp[0]);
        atomicAdd(&alpha_s[r0 + 8],  sp[1]);
        atomicAdd(&alpha_s[r0 + 16], sp[2]);
        atomicAdd(&alpha_s[r0 + 24], sp[3]);
        atomicAdd(&alpha_d[r0],      dp[0]);
        atomicAdd(&alpha_d[r0 + 8],  dp[1]);
        atomicAdd(&alpha_d[r0 + 16], dp[2]);
        atomicAdd(&alpha_d[r0 + 24], dp[3]);
    }
    __syncthreads();
    if (tid < 128) {
        int gr = m0 + tid;
        if (gr < M) {
            ASg[gr * 4] = alpha_s[tid];
            ADg[gr * 4] = alpha_d[tid];
        }
    }
}

// ---------------------------------------------------------------------------
// conv2 aggregation (heads=1, D=64, bf16 messages) fused with mean pool.
// ---------------------------------------------------------------------------
__global__ void agg2_pool_kernel(const int* __restrict__ rowptr,
                                 const int* __restrict__ ecol,
                                 const float* __restrict__ AS,
                                 const float* __restrict__ AD,
                                 const __nv_bfloat16* __restrict__ H2,
                                 const float* __restrict__ bias,
                                 const int* __restrict__ bt0,
                                 const int* __restrict__ bt1,
                                 float* __restrict__ POOL,
                                 float* __restrict__ CNT,
                                 int n) {
    const int g = blockIdx.y;
    const int* rp = rowptr + g * (NMAX + 1);
    const int* ec = ecol + (size_t)g * EMAX;
    const float* as = AS + (size_t)g * NMAX * 4;
    const float* ad = AD + (size_t)g * NMAX * 4;
    const __nv_bfloat16* H = H2 + (size_t)g * NMAX * 64;
    const int* batch = g ? bt1 : bt0;
    float* pool = POOL + g * GNUM * 64;
    float* cnt = CNT + g * GNUM;

    const int warp = (blockIdx.x * blockDim.x + threadIdx.x) >> 5;
    const int lane = threadIdx.x & 31;
    if (warp >= n) return;
    const int d = warp;
    const int beg = rp[d];
    const int end = rp[d + 1];

    float ad_d = ad[d * 4];
    float self_e = leaky(as[d * 4] + ad_d);
    float mx = self_e;
    for (int j = beg + lane; j < end; j += 32)
        mx = fmaxf(mx, leaky(as[ec[j] * 4] + ad_d));
    #pragma unroll
    for (int off = 16; off >= 1; off >>= 1)
        mx = fmaxf(mx, __shfl_xor_sync(0xffffffffu, mx, off));

    float ex = __expf(self_e - mx);
    float den = ex;
    float2 hv = __bfloat1622float2(*(const __nv_bfloat162*)&H[(size_t)d * 64 + lane * 2]);
    float a0 = ex * hv.x, a1 = ex * hv.y;
    for (int j = beg; j < end; j++) {
        int s = ec[j];
        float e = __expf(leaky(as[s * 4] + ad_d) - mx);
        den += e;
        float2 hs = __bfloat1622float2(*(const __nv_bfloat162*)&H[(size_t)s * 64 + lane * 2]);
        a0 += e * hs.x;
        a1 += e * hs.y;
    }
    float inv = 1.0f / (den + 1e-16f);
    float v0 = a0 * inv + bias[lane * 2];
    float v1 = a1 * inv + bias[lane * 2 + 1];
    v0 = v0 > 0.0f ? v0 : (__expf(v0) - 1.0f);
    v1 = v1 > 0.0f ? v1 : (__expf(v1) - 1.0f);
    int grp = batch[d];
    atomicAdd(&pool[grp * 64 + lane * 2], v0);
    atomicAdd(&pool[grp * 64 + lane * 2 + 1], v1);
    if (lane == 0) atomicAdd(&cnt[grp], 1.0f);
}

__global__ void final_write_kernel(const float* __restrict__ POOL,
                                   const float* __restrict__ CNT,
                                   float* __restrict__ out) {
    int i = blockIdx.x * blockDim.x + threadIdx.x;
    if (i >= 2 * GNUM * 64) return;
    float c = CNT[i >> 6];
    out[i] = POOL[i] / fmaxf(c, 1.0f);
}

// ---------------------------------------------------------------------------
// Launch
// ---------------------------------------------------------------------------
extern "C" void kernel_launch(void* const* d_in, const int* in_sizes, int n_in,
                              void* d_out, int out_size) {
    const float* x1  = (const float*)d_in[0];
    const int*   ei1 = (const int*)d_in[1];
    const int*   bt1 = (const int*)d_in[2];
    const float* x2  = (const float*)d_in[3];
    const int*   ei2 = (const int*)d_in[4];
    const int*   bt2 = (const int*)d_in[5];
    const float* W1  = (const float*)d_in[6];
    const float* as1 = (const float*)d_in[7];
    const float* ad1 = (const float*)d_in[8];
    const float* b1  = (const float*)d_in[9];
    const float* W2  = (const float*)d_in[10];
    const float* as2 = (const float*)d_in[11];
    const float* ad2 = (const float*)d_in[12];
    const float* b2  = (const float*)d_in[13];

    const int n = in_sizes[0] / 128;
    const int e = in_sizes[1] / 2;
    const int nb = cdiv(n, SCAN_CHUNK);

    float *OUT, *AS, *AD, *POOL, *CNT, *P1S, *P1D;
    int *DEG, *ROWPTR, *CUR, *ECOL, *PART;
    __nv_bfloat16 *X16, *AGG, *H2, *W1TH, *W1TL, *W2TH, *W2TL;
    cudaGetSymbolAddress((void**)&X16,    g_X16);
    cudaGetSymbolAddress((void**)&AGG,    g_AGG);
    cudaGetSymbolAddress((void**)&OUT,    g_OUT);
    cudaGetSymbolAddress((void**)&H2,     g_H2);
    cudaGetSymbolAddress((void**)&AS,     g_AS);
    cudaGetSymbolAddress((void**)&AD,     g_AD);
    cudaGetSymbolAddress((void**)&DEG,    g_DEG);
    cudaGetSymbolAddress((void**)&ROWPTR, g_ROWPTR);
    cudaGetSymbolAddress((void**)&CUR,    g_CUR);
    cudaGetSymbolAddress((void**)&ECOL,   g_ECOL);
    cudaGetSymbolAddress((void**)&PART,   g_PART);
    cudaGetSymbolAddress((void**)&POOL,   g_POOL);
    cudaGetSymbolAddress((void**)&CNT,    g_CNT);
    cudaGetSymbolAddress((void**)&P1S,    g_P1S);
    cudaGetSymbolAddress((void**)&P1D,    g_P1D);
    cudaGetSymbolAddress((void**)&W1TH,   g_W1T_HI);
    cudaGetSymbolAddress((void**)&W1TL,   g_W1T_LO);
    cudaGetSymbolAddress((void**)&W2TH,   g_W2T_HI);
    cudaGetSymbolAddress((void**)&W2TL,   g_W2T_LO);

    cudaFuncSetAttribute(gemm1_kernel, cudaFuncAttributeMaxDynamicSharedMemorySize, SM1_TOTAL);
    cudaFuncSetAttribute(gemm2_kernel, cudaFuncAttributeMaxDynamicSharedMemorySize, SM_TOTAL);

    setup_kernel<<<cdiv(SETUP_TOTAL, 256), 256>>>(W1, W2, as1, ad1,
                                                  W1TH, W1TL, W2TH, W2TL,
                                                  P1S, P1D, POOL, CNT, DEG);
    {
        dim3 ge2(cdiv(e, 256), 2);
        hist_kernel<<<ge2, 256>>>(ei1, ei2, DEG, e);
    }
    {
        dim3 gs2(nb, 2);
        scan_partial_kernel<<<gs2, 256>>>(DEG, PART, n);
        scan_root_kernel<<<2, 32>>>(PART, nb);
        scan_final_kernel<<<gs2, 256>>>(DEG, PART, ROWPTR, CUR, n, nb);
    }
    {
        dim3 ge2(cdiv(e, 256), 2);
        fill_kernel<<<ge2, 256>>>(ei1, ei2, CUR, ECOL, e);
    }
    {
        dim3 ga(cdiv(n, 8), 2);
        alphas_x_kernel<<<ga, 256>>>(x1, x2, P1S, P1D, AS, AD, X16, n);
        agg_x_kernel<<<ga, 256>>>(ROWPTR, ECOL, AS, AD, X16, AGG, n);
    }
    {
        dim3 gg(4, cdiv(n, 128), 2);
        gemm1_kernel<<<gg, 256, SM1_TOTAL>>>(AGG, W1TH, W1TL, b1, OUT, n);
    }
    {
        dim3 gg(1, cdiv(n, 128), 2);
        gemm2_kernel<<<gg, 256, SM_TOTAL>>>(OUT, W2TH, W2TL, H2, as2, ad2, AS, AD, n);
    }
    {
        dim3 ga(cdiv(n, 8), 2);
        agg2_pool_kernel<<<ga, 256>>>(ROWPTR, ECOL, AS, AD, H2, b2,
                                      bt1, bt2, POOL, CNT, n);
    }
    final_write_kernel<<<cdiv(2 * GNUM * 64, 256), 256>>>(POOL, CNT, (float*)d_out);
}

// round 9
// speedup vs baseline: 1.0788x; 1.0320x over previous
#include <cuda_runtime.h>
#include <cuda_bf16.h>
#include <cstdint>

// ---------------------------------------------------------------------------
// GATGraphSimilarity: Siamese 2-layer GAT (heads=4 then 1) + mean pool.
// Round 9: max-free softmax (mathematically identical, args are O(5)),
// edge weights precomputed LANE-PARALLEL (conv1 fused into fill_kernel,
// conv2 via edge-parallel w2_kernel) -> agg loops are pure gather+FMA.
// bf16 messages (X16/AGG/H2), fp32 weights/alphas/accumulators.
// ---------------------------------------------------------------------------

#define NMAX 50000
#define EMAX 800000
#define GNUM 64
#define NEG_SLOPE 0.2f
#define SCAN_CHUNK 4096
#define SCAN_NB ((NMAX + SCAN_CHUNK - 1) / SCAN_CHUNK)

__device__ __nv_bfloat16 g_X16[2][(size_t)NMAX * 128];
__device__ __nv_bfloat16 g_AGG[2][(size_t)NMAX * 512];
__device__ float g_OUT [2][(size_t)NMAX * 256];
__device__ __nv_bfloat16 g_H2 [2][(size_t)NMAX * 64];
__device__ float g_AS  [2][NMAX * 4];
__device__ float g_AD  [2][NMAX * 4];
__device__ int   g_DEG [2][NMAX];
__device__ int   g_ROWPTR[2][NMAX + 1];
__device__ int   g_CUR [2][NMAX];
__device__ int   g_ECOL[2][EMAX];
__device__ int   g_EDST[2][EMAX];
__device__ float g_U1  [2][(size_t)EMAX * 4];   // conv1 edge weights (unnormalized)
__device__ float g_U2  [2][EMAX];               // conv2 edge weights
__device__ int   g_PART[2][SCAN_NB + 1];
__device__ float g_POOL[2 * GNUM * 64];
__device__ float g_CNT [2 * GNUM];
__device__ float g_P1S [128 * 4];
__device__ float g_P1D [128 * 4];
__device__ __nv_bfloat16 g_W1T_HI[256 * 128];
__device__ __nv_bfloat16 g_W1T_LO[256 * 128];
__device__ __nv_bfloat16 g_W2T_HI[64 * 256];
__device__ __nv_bfloat16 g_W2T_LO[64 * 256];

static inline int cdiv(int a, int b) { return (a + b - 1) / b; }

__device__ __forceinline__ float leaky(float v) {
    return v > 0.0f ? v : NEG_SLOPE * v;
}

__device__ __forceinline__ uint32_t bf2u(__nv_bfloat162 v) {
    return *reinterpret_cast<uint32_t*>(&v);
}

__device__ __forceinline__ void mma16816(float* d, const uint32_t* a, const uint32_t* b) {
    asm volatile(
        "mma.sync.aligned.m16n8k16.row.col.f32.bf16.bf16.f32 "
        "{%0,%1,%2,%3}, {%4,%5,%6,%7}, {%8,%9}, {%0,%1,%2,%3};"
        : "+f"(d[0]), "+f"(d[1]), "+f"(d[2]), "+f"(d[3])
        : "r"(a[0]), "r"(a[1]), "r"(a[2]), "r"(a[3]), "r"(b[0]), "r"(b[1]));
}

// ---------------------------------------------------------------------------
// Setup: weight prep, P1 fold, pool zero, DEG zero
// ---------------------------------------------------------------------------
#define SEG1 (256 * 128)
#define SEG2 (64 * 256)
#define SEG3 1024
#define SEG4 (2 * GNUM * 64 + 2 * GNUM)
#define SEG5 (2 * NMAX)
#define SETUP_TOTAL (SEG1 + SEG2 + SEG3 + SEG4 + SEG5)

__global__ void setup_kernel(const float* __restrict__ W1,
                             const float* __restrict__ W2,
                             const float* __restrict__ as1,
                             const float* __restrict__ ad1,
                             __nv_bfloat16* __restrict__ W1TH,
                             __nv_bfloat16* __restrict__ W1TL,
                             __nv_bfloat16* __restrict__ W2TH,
                             __nv_bfloat16* __restrict__ W2TL,
                             float* __restrict__ P1S,
                             float* __restrict__ P1D,
                             float* __restrict__ POOL,
                             float* __restrict__ CNT,
                             int* __restrict__ DEG) {
    int i = blockIdx.x * blockDim.x + threadIdx.x;
    if (i < SEG1) {
        int n = i / 128, k = i % 128;
        float v = W1[(size_t)k * 256 + n];
        __nv_bfloat16 h = __float2bfloat16(v);
        W1TH[i] = h;
        W1TL[i] = __float2bfloat16(v - __bfloat162float(h));
        return;
    }
    i -= SEG1;
    if (i < SEG2) {
        int n = i / 256, k = i % 256;
        float v = W2[(size_t)k * 64 + n];
        __nv_bfloat16 h = __float2bfloat16(v);
        W2TH[i] = h;
        W2TL[i] = __float2bfloat16(v - __bfloat162float(h));
        return;
    }
    i -= SEG2;
    if (i < SEG3) {
        int is_dst = i >> 9;
        int o = i & 511;
        int k = o >> 2, h = o & 3;
        const float* a = is_dst ? ad1 : as1;
        float s = 0.0f;
        #pragma unroll 8
        for (int d = 0; d < 64; d++)
            s += W1[(size_t)k * 256 + h * 64 + d] * a[h * 64 + d];
        (is_dst ? P1D : P1S)[k * 4 + h] = s;
        return;
    }
    i -= SEG3;
    if (i < 2 * GNUM * 64) { POOL[i] = 0.0f; return; }
    i -= 2 * GNUM * 64;
    if (i < 2 * GNUM) { CNT[i] = 0.0f; return; }
    i -= 2 * GNUM;
    if (i < SEG5) DEG[i] = 0;
}

// ---------------------------------------------------------------------------
// CSR build (dual-graph)
// ---------------------------------------------------------------------------
__global__ void hist_kernel(const int* __restrict__ ei0, const int* __restrict__ ei1,
                            int* __restrict__ deg, int E) {
    int g = blockIdx.y;
    const int* ei = g ? ei1 : ei0;
    int i = blockIdx.x * blockDim.x + threadIdx.x;
    if (i < E) atomicAdd(&deg[g * NMAX + ei[E + i]], 1);
}

__global__ void scan_partial_kernel(const int* __restrict__ deg,
                                    int* __restrict__ part, int n) {
    __shared__ int red[256];
    const int g = blockIdx.y;
    const int t = threadIdx.x;
    const int base = blockIdx.x * SCAN_CHUNK + t * 16;
    int s = 0;
    #pragma unroll
    for (int q = 0; q < 16; q++) {
        int i = base + q;
        if (i < n) s += deg[g * NMAX + i];
    }
    red[t] = s;
    __syncthreads();
    #pragma unroll
    for (int off = 128; off >= 1; off >>= 1) {
        if (t < off) red[t] += red[t + off];
        __syncthreads();
    }
    if (t == 0) part[g * (SCAN_NB + 1) + blockIdx.x] = red[0];
}

__global__ void scan_root_kernel(int* __restrict__ part, int nb) {
    int g = blockIdx.x;
    if (threadIdx.x == 0) {
        int* p = part + g * (SCAN_NB + 1);
        int run = 0;
        for (int i = 0; i < nb; i++) {
            int v = p[i];
            p[i] = run;
            run += v;
        }
        p[nb] = run;
    }
}

__global__ void scan_final_kernel(const int* __restrict__ deg,
                                  const int* __restrict__ part,
                                  int* __restrict__ rowptr,
                                  int* __restrict__ cur,
                                  int n, int nb) {
    __shared__ int thr[256];
    const int g = blockIdx.y;
    const int t = threadIdx.x;
    const int base = blockIdx.x * SCAN_CHUNK + t * 16;
    const int* dg = deg + g * NMAX;
    int* rp = rowptr + g * (NMAX + 1);
    int* cu = cur + g * NMAX;
    int s = 0;
    int dloc[16];
    #pragma unroll
    for (int q = 0; q < 16; q++) {
        int i = base + q;
        dloc[q] = (i < n) ? dg[i] : 0;
        s += dloc[q];
    }
    thr[t] = s;
    __syncthreads();
    #pragma unroll
    for (int off = 1; off < 256; off <<= 1) {
        int v = (t >= off) ? thr[t - off] : 0;
        __syncthreads();
        thr[t] += v;
        __syncthreads();
    }
    int offset = part[g * (SCAN_NB + 1) + blockIdx.x] + ((t == 0) ? 0 : thr[t - 1]);
    #pragma unroll
    for (int q = 0; q < 16; q++) {
        int i = base + q;
        if (i < n) {
            rp[i] = offset;
            cu[i] = offset;
            offset += dloc[q];
        }
    }
    if (blockIdx.x == 0 && t == 0) rp[n] = part[g * (SCAN_NB + 1) + nb];
}

// fill CSR + conv1 edge weights (lane-parallel exps), store dst for conv2 pass
__global__ void fill_kernel(const int* __restrict__ ei0, const int* __restrict__ ei1,
                            int* __restrict__ cur,
                            int* __restrict__ ecol, int* __restrict__ edst,
                            const float* __restrict__ AS, const float* __restrict__ AD,
                            float* __restrict__ U1, int E) {
    int g = blockIdx.y;
    const int* ei = g ? ei1 : ei0;
    int i = blockIdx.x * blockDim.x + threadIdx.x;
    if (i >= E) return;
    int s = ei[i];
    int d = ei[E + i];
    int slot = atomicAdd(&cur[g * NMAX + d], 1);
    ecol[(size_t)g * EMAX + slot] = s;
    edst[(size_t)g * EMAX + slot] = d;
    float4 a = *(const float4*)&AS[(size_t)g * NMAX * 4 + s * 4];
    float4 b = *(const float4*)&AD[(size_t)g * NMAX * 4 + d * 4];
    float4 u;
    u.x = __expf(leaky(a.x + b.x));
    u.y = __expf(leaky(a.y + b.y));
    u.z = __expf(leaky(a.z + b.z));
    u.w = __expf(leaky(a.w + b.w));
    *(float4*)&U1[((size_t)g * EMAX + slot) * 4] = u;
}

// conv2 edge weights (lane-parallel, contiguous over CSR slots)
__global__ void w2_kernel(const int* __restrict__ ecol, const int* __restrict__ edst,
                          const float* __restrict__ AS, const float* __restrict__ AD,
                          float* __restrict__ U2, int E) {
    int g = blockIdx.y;
    int j = blockIdx.x * blockDim.x + threadIdx.x;
    if (j >= E) return;
    int s = ecol[(size_t)g * EMAX + j];
    int d = edst[(size_t)g * EMAX + j];
    float u = __expf(leaky(AS[(size_t)g * NMAX * 4 + s * 4] +
                           AD[(size_t)g * NMAX * 4 + d * 4]));
    U2[(size_t)g * EMAX + j] = u;
}

// ---------------------------------------------------------------------------
// conv1 alphas from raw x (fp32 exact) + X16 bf16 conversion (fused).
// ---------------------------------------------------------------------------
__global__ void alphas_x_kernel(const float* __restrict__ x0,
                                const float* __restrict__ x1,
                                const float* __restrict__ P1S,
                                const float* __restrict__ P1D,
                                float* __restrict__ AS,
                                float* __restrict__ AD,
                                __nv_bfloat16* __restrict__ X16,
                                int n) {
    const int g = blockIdx.y;
    const float* x = g ? x1 : x0;
    const int warp = (blockIdx.x * blockDim.x + threadIdx.x) >> 5;
    const int lane = threadIdx.x & 31;
    if (warp >= n) return;
    float4 xv = *(const float4*)&x[(size_t)warp * 128 + lane * 4];
    {
        __nv_bfloat162 p0 = __floats2bfloat162_rn(xv.x, xv.y);
        __nv_bfloat162 p1 = __floats2bfloat162_rn(xv.z, xv.w);
        uint2 u = make_uint2(bf2u(p0), bf2u(p1));
        *(uint2*)&X16[(size_t)g * NMAX * 128 + (size_t)warp * 128 + lane * 4] = u;
    }
    float s[4] = {0.f, 0.f, 0.f, 0.f};
    float d[4] = {0.f, 0.f, 0.f, 0.f};
    const float* xp = (const float*)&xv;
    #pragma unroll
    for (int j = 0; j < 4; j++) {
        float xk = xp[j];
        float4 ps = *(const float4*)&P1S[(lane * 4 + j) * 4];
        float4 pd = *(const float4*)&P1D[(lane * 4 + j) * 4];
        s[0] += xk * ps.x; s[1] += xk * ps.y; s[2] += xk * ps.z; s[3] += xk * ps.w;
        d[0] += xk * pd.x; d[1] += xk * pd.y; d[2] += xk * pd.z; d[3] += xk * pd.w;
    }
    #pragma unroll
    for (int off = 16; off >= 1; off >>= 1) {
        #pragma unroll
        for (int h = 0; h < 4; h++) {
            s[h] += __shfl_xor_sync(0xffffffffu, s[h], off);
            d[h] += __shfl_xor_sync(0xffffffffu, d[h], off);
        }
    }
    if (lane == 0) {
        *(float4*)&AS[(size_t)g * NMAX * 4 + warp * 4] = make_float4(s[0], s[1], s[2], s[3]);
        *(float4*)&AD[(size_t)g * NMAX * 4 + warp * 4] = make_float4(d[0], d[1], d[2], d[3]);
    }
}

// ---------------------------------------------------------------------------
// conv1 aggregation: single pass, precomputed weights, no max shift.
// Warp per dst node; lane owns 4 of 128 dims.
// ---------------------------------------------------------------------------
__global__ void agg_x_kernel(const int* __restrict__ rowptr,
                             const int* __restrict__ ecol,
                             const float* __restrict__ U1,
                             const float* __restrict__ AS,
                             const float* __restrict__ AD,
                             const __nv_bfloat16* __restrict__ X16,
                             __nv_bfloat16* __restrict__ AGG,
                             int n) {
    const int g = blockIdx.y;
    const int* rp = rowptr + g * (NMAX + 1);
    const int* ec = ecol + (size_t)g * EMAX;
    const float* U = U1 + (size_t)g * EMAX * 4;
    const __nv_bfloat16* X = X16 + (size_t)g * NMAX * 128;
    __nv_bfloat16* agg = AGG + (size_t)g * NMAX * 512;

    const int warp = (blockIdx.x * blockDim.x + threadIdx.x) >> 5;
    const int lane = threadIdx.x & 31;
    if (warp >= n) return;
    const int d = warp;
    const int beg = rp[d];
    const int end = rp[d + 1];

    float4 asv = *(const float4*)&AS[(size_t)g * NMAX * 4 + d * 4];
    float4 adv = *(const float4*)&AD[(size_t)g * NMAX * 4 + d * 4];
    float den[4];
    den[0] = __expf(leaky(asv.x + adv.x));
    den[1] = __expf(leaky(asv.y + adv.y));
    den[2] = __expf(leaky(asv.z + adv.z));
    den[3] = __expf(leaky(asv.w + adv.w));

    uint2 ux = *(const uint2*)&X[(size_t)d * 128 + lane * 4];
    float2 xd01 = __bfloat1622float2(*(__nv_bfloat162*)&ux.x);
    float2 xd23 = __bfloat1622float2(*(__nv_bfloat162*)&ux.y);

    float acc[4][4];
    #pragma unroll
    for (int h = 0; h < 4; h++) {
        acc[h][0] = den[h] * xd01.x; acc[h][1] = den[h] * xd01.y;
        acc[h][2] = den[h] * xd23.x; acc[h][3] = den[h] * xd23.y;
    }
    for (int j = beg; j < end; j++) {
        int s = ec[j];
        float4 u = *(const float4*)&U[(size_t)j * 4];
        den[0] += u.x; den[1] += u.y; den[2] += u.z; den[3] += u.w;
        uint2 us = *(const uint2*)&X[(size_t)s * 128 + lane * 4];
        float2 f01 = __bfloat1622float2(*(__nv_bfloat162*)&us.x);
        float2 f23 = __bfloat1622float2(*(__nv_bfloat162*)&us.y);
        acc[0][0] += u.x * f01.x; acc[0][1] += u.x * f01.y; acc[0][2] += u.x * f23.x; acc[0][3] += u.x * f23.y;
        acc[1][0] += u.y * f01.x; acc[1][1] += u.y * f01.y; acc[1][2] += u.y * f23.x; acc[1][3] += u.y * f23.y;
        acc[2][0] += u.z * f01.x; acc[2][1] += u.z * f01.y; acc[2][2] += u.z * f23.x; acc[2][3] += u.z * f23.y;
        acc[3][0] += u.w * f01.x; acc[3][1] += u.w * f01.y; acc[3][2] += u.w * f23.x; acc[3][3] += u.w * f23.y;
    }
    #pragma unroll
    for (int h = 0; h < 4; h++) {
        float inv = 1.0f / (den[h] + 1e-16f);
        __nv_bfloat162 q0 = __floats2bfloat162_rn(acc[h][0] * inv, acc[h][1] * inv);
        __nv_bfloat162 q1 = __floats2bfloat162_rn(acc[h][2] * inv, acc[h][3] * inv);
        uint2 u = make_uint2(bf2u(q0), bf2u(q1));
        *(uint2*)&agg[(size_t)d * 512 + h * 128 + lane * 4] = u;
    }
}

// ---------------------------------------------------------------------------
// GEMM1: OUT[:, h*64:+64] = elu(AGG[:,h,:] @ W1T[h]^T + b1)
// ---------------------------------------------------------------------------
#define SM1_AH 0
#define SM1_BH 34816
#define SM1_BL 52224
#define SM1_TOTAL 69632

__global__ __launch_bounds__(256)
void gemm1_kernel(const __nv_bfloat16* __restrict__ AGG,
                  const __nv_bfloat16* __restrict__ Bhi,
                  const __nv_bfloat16* __restrict__ Blo,
                  const float* __restrict__ bias,
                  float* __restrict__ OUT,
                  int M) {
    extern __shared__ char smem[];
    uint32_t* Ah = (uint32_t*)(smem + SM1_AH);
    uint32_t* Bh = (uint32_t*)(smem + SM1_BH);
    uint32_t* Bl = (uint32_t*)(smem + SM1_BL);

    const int g = blockIdx.z;
    const __nv_bfloat16* A = AGG + (size_t)g * NMAX * 512;
    float* C = OUT + (size_t)g * NMAX * 256;
    const int tid = threadIdx.x;
    const int lane = tid & 31;
    const int wid = tid >> 5;
    const int warp_m = wid & 3;
    const int warp_n = wid >> 2;
    const int h = blockIdx.x;
    const int m0 = blockIdx.y * 128;

    float acc[2][4][4] = {};

    #pragma unroll
    for (int q = 0; q < 8; q++) {
        int idx = q * 256 + tid;
        int r = idx >> 4;
        int c8 = idx & 15;
        int gr = m0 + r;
        uint4 v = make_uint4(0u, 0u, 0u, 0u);
        if (gr < M) v = *(const uint4*)&A[(size_t)gr * 512 + h * 128 + c8 * 8];
        *(uint4*)&Ah[r * 68 + c8 * 4] = v;
    }
    #pragma unroll
    for (int q = 0; q < 4; q++) {
        int idx = q * 256 + tid;
        int r = idx >> 4;
        int c8 = idx & 15;
        uint4 vh = *(const uint4*)&Bhi[(size_t)(h * 64 + r) * 128 + c8 * 8];
        uint4 vl = *(const uint4*)&Blo[(size_t)(h * 64 + r) * 128 + c8 * 8];
        *(uint4*)&Bh[r * 68 + c8 * 4] = vh;
        *(uint4*)&Bl[r * 68 + c8 * 4] = vl;
    }
    __syncthreads();

    #pragma unroll
    for (int ks = 0; ks < 8; ks++) {
        const int kw = ks * 8 + (lane & 3);
        uint32_t ah[2][4], bh[4][2], bl[4][2];
        #pragma unroll
        for (int mt = 0; mt < 2; mt++) {
            int r0 = warp_m * 32 + mt * 16 + (lane >> 2);
            ah[mt][0] = Ah[r0 * 68 + kw];
            ah[mt][1] = Ah[(r0 + 8) * 68 + kw];
            ah[mt][2] = Ah[r0 * 68 + kw + 4];
            ah[mt][3] = Ah[(r0 + 8) * 68 + kw + 4];
        }
        #pragma unroll
        for (int nt = 0; nt < 4; nt++) {
            int n0 = warp_n * 32 + nt * 8 + (lane >> 2);
            bh[nt][0] = Bh[n0 * 68 + kw];
            bh[nt][1] = Bh[n0 * 68 + kw + 4];
            bl[nt][0] = Bl[n0 * 68 + kw];
            bl[nt][1] = Bl[n0 * 68 + kw + 4];
        }
        #pragma unroll
        for (int mt = 0; mt < 2; mt++)
            #pragma unroll
            for (int nt = 0; nt < 4; nt++) {
                mma16816(acc[mt][nt], ah[mt], bh[nt]);
                mma16816(acc[mt][nt], ah[mt], bl[nt]);
            }
    }

    #pragma unroll
    for (int mt = 0; mt < 2; mt++) {
        int r0 = warp_m * 32 + mt * 16 + (lane >> 2);
        #pragma unroll
        for (int nt = 0; nt < 4; nt++) {
            int c0 = warp_n * 32 + nt * 8 + (lane & 3) * 2;
            float b0 = __ldg(&bias[h * 64 + c0]);
            float b1v = __ldg(&bias[h * 64 + c0 + 1]);
            float* a4 = acc[mt][nt];
            float v00 = a4[0] + b0, v01 = a4[1] + b1v;
            float v10 = a4[2] + b0, v11 = a4[3] + b1v;
            v00 = v00 > 0.f ? v00 : (__expf(v00) - 1.f);
            v01 = v01 > 0.f ? v01 : (__expf(v01) - 1.f);
            v10 = v10 > 0.f ? v10 : (__expf(v10) - 1.f);
            v11 = v11 > 0.f ? v11 : (__expf(v11) - 1.f);
            int gr0 = m0 + r0, gr1 = gr0 + 8;
            if (gr0 < M) *(float2*)&C[(size_t)gr0 * 256 + h * 64 + c0] = make_float2(v00, v01);
            if (gr1 < M) *(float2*)&C[(size_t)gr1 * 256 + h * 64 + c0] = make_float2(v10, v11);
        }
    }
}

// ---------------------------------------------------------------------------
// GEMM2: H2(bf16) = OUT @ W2 (K=256, N=64), split-bf16 A, alpha epilogue fp32.
// ---------------------------------------------------------------------------
#define SM_AH 0
#define SM_AL 34816
#define SM_BH 69632
#define SM_BL 87040
#define SM_ALPHA 104448
#define SM_TOTAL 105472

__global__ __launch_bounds__(256, 1)
void gemm2_kernel(const float* __restrict__ OUT,
                  const __nv_bfloat16* __restrict__ Bhi,
                  const __nv_bfloat16* __restrict__ Blo,
                  __nv_bfloat16* __restrict__ H2,
                  const float* __restrict__ a_src,
                  const float* __restrict__ a_dst,
                  float* __restrict__ AS,
                  float* __restrict__ AD,
                  int M) {
    extern __shared__ char smem[];
    uint32_t* Ah = (uint32_t*)(smem + SM_AH);
    uint32_t* Al = (uint32_t*)(smem + SM_AL);
    uint32_t* Bh = (uint32_t*)(smem + SM_BH);
    uint32_t* Bl = (uint32_t*)(smem + SM_BL);
    float* alpha_s = (float*)(smem + SM_ALPHA);
    float* alpha_d = alpha_s + 128;

    const int g = blockIdx.z;
    const float* A = OUT + (size_t)g * NMAX * 256;
    __nv_bfloat16* C = H2 + (size_t)g * NMAX * 64;
    float* ASg = AS + (size_t)g * NMAX * 4;
    float* ADg = AD + (size_t)g * NMAX * 4;
    const int tid = threadIdx.x;
    const int lane = tid & 31;
    const int wid = tid >> 5;
    const int warp_m = wid & 3;
    const int warp_n = wid >> 2;
    const int m0 = blockIdx.y * 128;

    float acc[2][4][4] = {};

    for (int kc = 0; kc < 256; kc += 128) {
        #pragma unroll
        for (int q = 0; q < 16; q++) {
            int idx = q * 256 + tid;
            int r = idx >> 5;
            int c4 = idx & 31;
            int gr = m0 + r;
            float4 v = make_float4(0.f, 0.f, 0.f, 0.f);
            if (gr < M) v = *(const float4*)&A[(size_t)gr * 256 + kc + c4 * 4];
            __nv_bfloat162 hxy = __floats2bfloat162_rn(v.x, v.y);
            __nv_bfloat162 hzw = __floats2bfloat162_rn(v.z, v.w);
            float2 fxy = __bfloat1622float2(hxy);
            float2 fzw = __bfloat1622float2(hzw);
            __nv_bfloat162 lxy = __floats2bfloat162_rn(v.x - fxy.x, v.y - fxy.y);
            __nv_bfloat162 lzw = __floats2bfloat162_rn(v.z - fzw.x, v.w - fzw.y);
            int w = r * 68 + c4 * 2;
            Ah[w] = bf2u(hxy); Ah[w + 1] = bf2u(hzw);
            Al[w] = bf2u(lxy); Al[w + 1] = bf2u(lzw);
        }
        #pragma unroll
        for (int q = 0; q < 4; q++) {
            int idx = q * 256 + tid;
            int r = idx >> 4;
            int c8 = idx & 15;
            uint4 vh = *(const uint4*)&Bhi[(size_t)r * 256 + kc + c8 * 8];
            uint4 vl = *(const uint4*)&Blo[(size_t)r * 256 + kc + c8 * 8];
            *(uint4*)&Bh[r * 68 + c8 * 4] = vh;
            *(uint4*)&Bl[r * 68 + c8 * 4] = vl;
        }
        __syncthreads();

        #pragma unroll
        for (int ks = 0; ks < 8; ks++) {
            const int kw = ks * 8 + (lane & 3);
            uint32_t ah[2][4], al[2][4], bh[4][2], bl[4][2];
            #pragma unroll
            for (int mt = 0; mt < 2; mt++) {
                int r0 = warp_m * 32 + mt * 16 + (lane >> 2);
                ah[mt][0] = Ah[r0 * 68 + kw];
                ah[mt][1] = Ah[(r0 + 8) * 68 + kw];
                ah[mt][2] = Ah[r0 * 68 + kw + 4];
                ah[mt][3] = Ah[(r0 + 8) * 68 + kw + 4];
                al[mt][0] = Al[r0 * 68 + kw];
                al[mt][1] = Al[(r0 + 8) * 68 + kw];
                al[mt][2] = Al[r0 * 68 + kw + 4];
                al[mt][3] = Al[(r0 + 8) * 68 + kw + 4];
            }
            #pragma unroll
            for (int nt = 0; nt < 4; nt++) {
                int n0 = warp_n * 32 + nt * 8 + (lane >> 2);
                bh[nt][0] = Bh[n0 * 68 + kw];
                bh[nt][1] = Bh[n0 * 68 + kw + 4];
                bl[nt][0] = Bl[n0 * 68 + kw];
                bl[nt][1] = Bl[n0 * 68 + kw + 4];
            }
            #pragma unroll
            for (int mt = 0; mt < 2; mt++)
                #pragma unroll
                for (int nt = 0; nt < 4; nt++) {
                    mma16816(acc[mt][nt], ah[mt], bh[nt]);
                    mma16816(acc[mt][nt], ah[mt], bl[nt]);
                    mma16816(acc[mt][nt], al[mt], bh[nt]);
                }
        }
        __syncthreads();
    }

    if (tid < 128) { alpha_s[tid] = 0.0f; alpha_d[tid] = 0.0f; }
    __syncthreads();

    float sp[4] = {0.f, 0.f, 0.f, 0.f};
    float dp[4] = {0.f, 0.f, 0.f, 0.f};
    #pragma unroll
    for (int mt = 0; mt < 2; mt++) {
        int r0 = warp_m * 32 + mt * 16 + (lane >> 2);
        #pragma unroll
        for (int nt = 0; nt < 4; nt++) {
            int c0 = warp_n * 32 + nt * 8 + (lane & 3) * 2;
            float* a4 = acc[mt][nt];
            int gr0 = m0 + r0, gr1 = gr0 + 8;
            if (gr0 < M)
                *(__nv_bfloat162*)&C[(size_t)gr0 * 64 + c0] = __floats2bfloat162_rn(a4[0], a4[1]);
            if (gr1 < M)
                *(__nv_bfloat162*)&C[(size_t)gr1 * 64 + c0] = __floats2bfloat162_rn(a4[2], a4[3]);
            float s0 = __ldg(&a_src[c0]);
            float s1 = __ldg(&a_src[c0 + 1]);
            float d0 = __ldg(&a_dst[c0]);
            float d1 = __ldg(&a_dst[c0 + 1]);
            sp[mt * 2]     += a4[0] * s0 + a4[1] * s1;
            sp[mt * 2 + 1] += a4[2] * s0 + a4[3] * s1;
            dp[mt * 2]     += a4[0] * d0 + a4[1] * d1;
            dp[mt * 2 + 1] += a4[2] * d0 + a4[3] * d1;
        }
    }
    #pragma unroll
    for (int i = 0; i < 4; i++) {
        sp[i] += __shfl_xor_sync(0xffffffffu, sp[i], 1);
        sp[i] += __shfl_xor_sync(0xffffffffu, sp[i], 2);
        dp[i] += __shfl_xor_sync(0xffffffffu, dp[i], 1);
        dp[i] += __shfl_xor_sync(0xffffffffu, dp[i], 2);
    }
    if ((lane & 3) == 0) {
        int r0 = warp_m * 32 + (lane >> 2);
        atomicAdd(&alpha_s[r0],      sp[0]);
        atomicAdd(&alpha_s[r0 + 8],  sp[1]);
        atomicAdd(&alpha_s[r0 + 16], sp[2]);
        atomicAdd(&alpha_s[r0 + 24], sp[3]);
        atomicAdd(&alpha_d[r0],      dp[0]);
        atomicAdd(&alpha_d[r0 + 8],  dp[1]);
        atomicAdd(&alpha_d[r0 + 16], dp[2]);
        atomicAdd(&alpha_d[r0 + 24], dp[3]);
    }
    __syncthreads();
    if (tid < 128) {
        int gr = m0 + tid;
        if (gr < M) {
            ASg[gr * 4] = alpha_s[tid];
            ADg[gr * 4] = alpha_d[tid];
        }
    }
}

// ---------------------------------------------------------------------------
// conv2 aggregation (heads=1, bf16 messages, precomputed weights) + mean pool.
// ---------------------------------------------------------------------------
__global__ void agg2_pool_kernel(const int* __restrict__ rowptr,
                                 const int* __restrict__ ecol,
                                 const float* __restrict__ U2,
                                 const float* __restrict__ AS,
                                 const float* __restrict__ AD,
                                 const __nv_bfloat16* __restrict__ H2,
                                 const float* __restrict__ bias,
                                 const int* __restrict__ bt0,
                                 const int* __restrict__ bt1,
                                 float* __restrict__ POOL,
                                 float* __restrict__ CNT,
                                 int n) {
    const int g = blockIdx.y;
    const int* rp = rowptr + g * (NMAX + 1);
    const int* ec = ecol + (size_t)g * EMAX;
    const float* U = U2 + (size_t)g * EMAX;
    const __nv_bfloat16* H = H2 + (size_t)g * NMAX * 64;
    const int* batch = g ? bt1 : bt0;
    float* pool = POOL + g * GNUM * 64;
    float* cnt = CNT + g * GNUM;

    const int warp = (blockIdx.x * blockDim.x + threadIdx.x) >> 5;
    const int lane = threadIdx.x & 31;
    if (warp >= n) return;
    const int d = warp;
    const int beg = rp[d];
    const int end = rp[d + 1];

    float den = __expf(leaky(AS[(size_t)g * NMAX * 4 + d * 4] +
                             AD[(size_t)g * NMAX * 4 + d * 4]));
    float2 hv = __bfloat1622float2(*(const __nv_bfloat162*)&H[(size_t)d * 64 + lane * 2]);
    float a0 = den * hv.x, a1 = den * hv.y;
    for (int j = beg; j < end; j++) {
        int s = ec[j];
        float u = U[j];
        den += u;
        float2 hs = __bfloat1622float2(*(const __nv_bfloat162*)&H[(size_t)s * 64 + lane * 2]);
        a0 += u * hs.x;
        a1 += u * hs.y;
    }
    float inv = 1.0f / (den + 1e-16f);
    float v0 = a0 * inv + bias[lane * 2];
    float v1 = a1 * inv + bias[lane * 2 + 1];
    v0 = v0 > 0.0f ? v0 : (__expf(v0) - 1.0f);
    v1 = v1 > 0.0f ? v1 : (__expf(v1) - 1.0f);
    int grp = batch[d];
    atomicAdd(&pool[grp * 64 + lane * 2], v0);
    atomicAdd(&pool[grp * 64 + lane * 2 + 1], v1);
    if (lane == 0) atomicAdd(&cnt[grp], 1.0f);
}

__global__ void final_write_kernel(const float* __restrict__ POOL,
                                   const float* __restrict__ CNT,
                                   float* __restrict__ out) {
    int i = blockIdx.x * blockDim.x + threadIdx.x;
    if (i >= 2 * GNUM * 64) return;
    float c = CNT[i >> 6];
    out[i] = POOL[i] / fmaxf(c, 1.0f);
}

// ---------------------------------------------------------------------------
// Launch
// ---------------------------------------------------------------------------
extern "C" void kernel_launch(void* const* d_in, const int* in_sizes, int n_in,
                              void* d_out, int out_size) {
    const float* x1  = (const float*)d_in[0];
    const int*   ei1 = (const int*)d_in[1];
    const int*   bt1 = (const int*)d_in[2];
    const float* x2  = (const float*)d_in[3];
    const int*   ei2 = (const int*)d_in[4];
    const int*   bt2 = (const int*)d_in[5];
    const float* W1  = (const float*)d_in[6];
    const float* as1 = (const float*)d_in[7];
    const float* ad1 = (const float*)d_in[8];
    const float* b1  = (const float*)d_in[9];
    const float* W2  = (const float*)d_in[10];
    const float* as2 = (const float*)d_in[11];
    const float* ad2 = (const float*)d_in[12];
    const float* b2  = (const float*)d_in[13];

    const int n = in_sizes[0] / 128;
    const int e = in_sizes[1] / 2;
    const int nb = cdiv(n, SCAN_CHUNK);

    float *OUT, *AS, *AD, *POOL, *CNT, *P1S, *P1D, *U1, *U2;
    int *DEG, *ROWPTR, *CUR, *ECOL, *EDST, *PART;
    __nv_bfloat16 *X16, *AGG, *H2, *W1TH, *W1TL, *W2TH, *W2TL;
    cudaGetSymbolAddress((void**)&X16,    g_X16);
    cudaGetSymbolAddress((void**)&AGG,    g_AGG);
    cudaGetSymbolAddress((void**)&OUT,    g_OUT);
    cudaGetSymbolAddress((void**)&H2,     g_H2);
    cudaGetSymbolAddress((void**)&AS,     g_AS);
    cudaGetSymbolAddress((void**)&AD,     g_AD);
    cudaGetSymbolAddress((void**)&DEG,    g_DEG);
    cudaGetSymbolAddress((void**)&ROWPTR, g_ROWPTR);
    cudaGetSymbolAddress((void**)&CUR,    g_CUR);
    cudaGetSymbolAddress((void**)&ECOL,   g_ECOL);
    cudaGetSymbolAddress((void**)&EDST,   g_EDST);
    cudaGetSymbolAddress((void**)&U1,     g_U1);
    cudaGetSymbolAddress((void**)&U2,     g_U2);
    cudaGetSymbolAddress((void**)&PART,   g_PART);
    cudaGetSymbolAddress((void**)&POOL,   g_POOL);
    cudaGetSymbolAddress((void**)&CNT,    g_CNT);
    cudaGetSymbolAddress((void**)&P1S,    g_P1S);
    cudaGetSymbolAddress((void**)&P1D,    g_P1D);
    cudaGetSymbolAddress((void**)&W1TH,   g_W1T_HI);
    cudaGetSymbolAddress((void**)&W1TL,   g_W1T_LO);
    cudaGetSymbolAddress((void**)&W2TH,   g_W2T_HI);
    cudaGetSymbolAddress((void**)&W2TL,   g_W2T_LO);

    cudaFuncSetAttribute(gemm1_kernel, cudaFuncAttributeMaxDynamicSharedMemorySize, SM1_TOTAL);
    cudaFuncSetAttribute(gemm2_kernel, cudaFuncAttributeMaxDynamicSharedMemorySize, SM_TOTAL);

    setup_kernel<<<cdiv(SETUP_TOTAL, 256), 256>>>(W1, W2, as1, ad1,
                                                  W1TH, W1TL, W2TH, W2TL,
                                                  P1S, P1D, POOL, CNT, DEG);
    {
        dim3 ga(cdiv(n, 8), 2);
        alphas_x_kernel<<<ga, 256>>>(x1, x2, P1S, P1D, AS, AD, X16, n);
    }
    {
        dim3 ge2(cdiv(e, 256), 2);
        hist_kernel<<<ge2, 256>>>(ei1, ei2, DEG, e);
    }
    {
        dim3 gs2(nb, 2);
        scan_partial_kernel<<<gs2, 256>>>(DEG, PART, n);
        scan_root_kernel<<<2, 32>>>(PART, nb);
        scan_final_kernel<<<gs2, 256>>>(DEG, PART, ROWPTR, CUR, n, nb);
    }
    {
        dim3 ge2(cdiv(e, 256), 2);
        fill_kernel<<<ge2, 256>>>(ei1, ei2, CUR, ECOL, EDST, AS, AD, U1, e);
    }
    {
        dim3 ga(cdiv(n, 8), 2);
        agg_x_kernel<<<ga, 256>>>(ROWPTR, ECOL, U1, AS, AD, X16, AGG, n);
    }
    {
        dim3 gg(4, cdiv(n, 128), 2);
        gemm1_kernel<<<gg, 256, SM1_TOTAL>>>(AGG, W1TH, W1TL, b1, OUT, n);
    }
    {
        dim3 gg(1, cdiv(n, 128), 2);
        gemm2_kernel<<<gg, 256, SM_TOTAL>>>(OUT, W2TH, W2TL, H2, as2, ad2, AS, AD, n);
    }
    {
        dim3 ge2(cdiv(e, 256), 2);
        w2_kernel<<<ge2, 256>>>(ECOL, EDST, AS, AD, U2, e);
    }
    {
        dim3 ga(cdiv(n, 8), 2);
        agg2_pool_kernel<<<ga, 256>>>(ROWPTR, ECOL, U2, AS, AD, H2, b2,
                                      bt1, bt2, POOL, CNT, n);
    }
    final_write_kernel<<<cdiv(2 * GNUM * 64, 256), 256>>>(POOL, CNT, (float*)d_out);
}

// round 10
// speedup vs baseline: 1.0956x; 1.0156x over previous
#include <cuda_runtime.h>
#include <cuda_bf16.h>
#include <cstdint>

// ---------------------------------------------------------------------------
// GATGraphSimilarity: Siamese 2-layer GAT (heads=4 then 1) + mean pool.
// Round 10: fused conv1-GEMM + conv2-GEMM (OUT intermediate lives in smem,
// 204MB DRAM round-trip deleted), alphas+hist merged launch.
// bf16 messages, fp32 weights/alphas/accumulators, max-free softmax.
// ---------------------------------------------------------------------------

#define NMAX 50000
#define EMAX 800000
#define GNUM 64
#define NEG_SLOPE 0.2f
#define SCAN_CHUNK 4096
#define SCAN_NB ((NMAX + SCAN_CHUNK - 1) / SCAN_CHUNK)

__device__ __nv_bfloat16 g_X16[2][(size_t)NMAX * 128];
__device__ __nv_bfloat16 g_AGG[2][(size_t)NMAX * 512];
__device__ __nv_bfloat16 g_H2 [2][(size_t)NMAX * 64];
__device__ float g_AS  [2][NMAX * 4];
__device__ float g_AD  [2][NMAX * 4];
__device__ int   g_DEG [2][NMAX];
__device__ int   g_ROWPTR[2][NMAX + 1];
__device__ int   g_CUR [2][NMAX];
__device__ int   g_ECOL[2][EMAX];
__device__ int   g_EDST[2][EMAX];
__device__ float g_U1  [2][(size_t)EMAX * 4];
__device__ float g_U2  [2][EMAX];
__device__ int   g_PART[2][SCAN_NB + 1];
__device__ float g_POOL[2 * GNUM * 64];
__device__ float g_CNT [2 * GNUM];
__device__ float g_P1S [128 * 4];
__device__ float g_P1D [128 * 4];
__device__ __nv_bfloat16 g_W1T_HI[256 * 128];
__device__ __nv_bfloat16 g_W1T_LO[256 * 128];
__device__ __nv_bfloat16 g_W2T_HI[64 * 256];
__device__ __nv_bfloat16 g_W2T_LO[64 * 256];

static inline int cdiv(int a, int b) { return (a + b - 1) / b; }

__device__ __forceinline__ float leaky(float v) {
    return v > 0.0f ? v : NEG_SLOPE * v;
}

__device__ __forceinline__ uint32_t bf2u(__nv_bfloat162 v) {
    return *reinterpret_cast<uint32_t*>(&v);
}

__device__ __forceinline__ void mma16816(float* d, const uint32_t* a, const uint32_t* b) {
    asm volatile(
        "mma.sync.aligned.m16n8k16.row.col.f32.bf16.bf16.f32 "
        "{%0,%1,%2,%3}, {%4,%5,%6,%7}, {%8,%9}, {%0,%1,%2,%3};"
        : "+f"(d[0]), "+f"(d[1]), "+f"(d[2]), "+f"(d[3])
        : "r"(a[0]), "r"(a[1]), "r"(a[2]), "r"(a[3]), "r"(b[0]), "r"(b[1]));
}

// ---------------------------------------------------------------------------
// Setup: weight prep, P1 fold, pool zero, DEG zero
// ---------------------------------------------------------------------------
#define SEG1 (256 * 128)
#define SEG2 (64 * 256)
#define SEG3 1024
#define SEG4 (2 * GNUM * 64 + 2 * GNUM)
#define SEG5 (2 * NMAX)
#define SETUP_TOTAL (SEG1 + SEG2 + SEG3 + SEG4 + SEG5)

__global__ void setup_kernel(const float* __restrict__ W1,
                             const float* __restrict__ W2,
                             const float* __restrict__ as1,
                             const float* __restrict__ ad1,
                             __nv_bfloat16* __restrict__ W1TH,
                             __nv_bfloat16* __restrict__ W1TL,
                             __nv_bfloat16* __restrict__ W2TH,
                             __nv_bfloat16* __restrict__ W2TL,
                             float* __restrict__ P1S,
                             float* __restrict__ P1D,
                             float* __restrict__ POOL,
                             float* __restrict__ CNT,
                             int* __restrict__ DEG) {
    int i = blockIdx.x * blockDim.x + threadIdx.x;
    if (i < SEG1) {
        int n = i / 128, k = i % 128;
        float v = W1[(size_t)k * 256 + n];
        __nv_bfloat16 h = __float2bfloat16(v);
        W1TH[i] = h;
        W1TL[i] = __float2bfloat16(v - __bfloat162float(h));
        return;
    }
    i -= SEG1;
    if (i < SEG2) {
        int n = i / 256, k = i % 256;
        float v = W2[(size_t)k * 64 + n];
        __nv_bfloat16 h = __float2bfloat16(v);
        W2TH[i] = h;
        W2TL[i] = __float2bfloat16(v - __bfloat162float(h));
        return;
    }
    i -= SEG2;
    if (i < SEG3) {
        int is_dst = i >> 9;
        int o = i & 511;
        int k = o >> 2, h = o & 3;
        const float* a = is_dst ? ad1 : as1;
        float s = 0.0f;
        #pragma unroll 8
        for (int d = 0; d < 64; d++)
            s += W1[(size_t)k * 256 + h * 64 + d] * a[h * 64 + d];
        (is_dst ? P1D : P1S)[k * 4 + h] = s;
        return;
    }
    i -= SEG3;
    if (i < 2 * GNUM * 64) { POOL[i] = 0.0f; return; }
    i -= 2 * GNUM * 64;
    if (i < 2 * GNUM) { CNT[i] = 0.0f; return; }
    i -= 2 * GNUM;
    if (i < SEG5) DEG[i] = 0;
}

// ---------------------------------------------------------------------------
// Stage1: alphas+X16 (parts 0,1) and degree histogram (parts 2,3), one launch.
// ---------------------------------------------------------------------------
__global__ void stage1_kernel(const float* __restrict__ x0,
                              const float* __restrict__ x1,
                              const float* __restrict__ P1S,
                              const float* __restrict__ P1D,
                              float* __restrict__ AS,
                              float* __restrict__ AD,
                              __nv_bfloat16* __restrict__ X16,
                              const int* __restrict__ ei0,
                              const int* __restrict__ ei1,
                              int* __restrict__ deg,
                              int n, int E) {
    const int part = blockIdx.y;
    if (part >= 2) {
        // degree histogram
        int g = part - 2;
        const int* ei = g ? ei1 : ei0;
        int i = blockIdx.x * blockDim.x + threadIdx.x;
        if (i < E) atomicAdd(&deg[g * NMAX + ei[E + i]], 1);
        return;
    }
    const int g = part;
    const float* x = g ? x1 : x0;
    const int warp = (blockIdx.x * blockDim.x + threadIdx.x) >> 5;
    const int lane = threadIdx.x & 31;
    if (warp >= n) return;
    float4 xv = *(const float4*)&x[(size_t)warp * 128 + lane * 4];
    {
        __nv_bfloat162 p0 = __floats2bfloat162_rn(xv.x, xv.y);
        __nv_bfloat162 p1 = __floats2bfloat162_rn(xv.z, xv.w);
        uint2 u = make_uint2(bf2u(p0), bf2u(p1));
        *(uint2*)&X16[(size_t)g * NMAX * 128 + (size_t)warp * 128 + lane * 4] = u;
    }
    float s[4] = {0.f, 0.f, 0.f, 0.f};
    float d[4] = {0.f, 0.f, 0.f, 0.f};
    const float* xp = (const float*)&xv;
    #pragma unroll
    for (int j = 0; j < 4; j++) {
        float xk = xp[j];
        float4 ps = *(const float4*)&P1S[(lane * 4 + j) * 4];
        float4 pd = *(const float4*)&P1D[(lane * 4 + j) * 4];
        s[0] += xk * ps.x; s[1] += xk * ps.y; s[2] += xk * ps.z; s[3] += xk * ps.w;
        d[0] += xk * pd.x; d[1] += xk * pd.y; d[2] += xk * pd.z; d[3] += xk * pd.w;
    }
    #pragma unroll
    for (int off = 16; off >= 1; off >>= 1) {
        #pragma unroll
        for (int h = 0; h < 4; h++) {
            s[h] += __shfl_xor_sync(0xffffffffu, s[h], off);
            d[h] += __shfl_xor_sync(0xffffffffu, d[h], off);
        }
    }
    if (lane == 0) {
        *(float4*)&AS[(size_t)g * NMAX * 4 + warp * 4] = make_float4(s[0], s[1], s[2], s[3]);
        *(float4*)&AD[(size_t)g * NMAX * 4 + warp * 4] = make_float4(d[0], d[1], d[2], d[3]);
    }
}

// ---------------------------------------------------------------------------
// CSR scan
// ---------------------------------------------------------------------------
__global__ void scan_partial_kernel(const int* __restrict__ deg,
                                    int* __restrict__ part, int n) {
    __shared__ int red[256];
    const int g = blockIdx.y;
    const int t = threadIdx.x;
    const int base = blockIdx.x * SCAN_CHUNK + t * 16;
    int s = 0;
    #pragma unroll
    for (int q = 0; q < 16; q++) {
        int i = base + q;
        if (i < n) s += deg[g * NMAX + i];
    }
    red[t] = s;
    __syncthreads();
    #pragma unroll
    for (int off = 128; off >= 1; off >>= 1) {
        if (t < off) red[t] += red[t + off];
        __syncthreads();
    }
    if (t == 0) part[g * (SCAN_NB + 1) + blockIdx.x] = red[0];
}

__global__ void scan_root_kernel(int* __restrict__ part, int nb) {
    int g = blockIdx.x;
    if (threadIdx.x == 0) {
        int* p = part + g * (SCAN_NB + 1);
        int run = 0;
        for (int i = 0; i < nb; i++) {
            int v = p[i];
            p[i] = run;
            run += v;
        }
        p[nb] = run;
    }
}

__global__ void scan_final_kernel(const int* __restrict__ deg,
                                  const int* __restrict__ part,
                                  int* __restrict__ rowptr,
                                  int* __restrict__ cur,
                                  int n, int nb) {
    __shared__ int thr[256];
    const int g = blockIdx.y;
    const int t = threadIdx.x;
    const int base = blockIdx.x * SCAN_CHUNK + t * 16;
    const int* dg = deg + g * NMAX;
    int* rp = rowptr + g * (NMAX + 1);
    int* cu = cur + g * NMAX;
    int s = 0;
    int dloc[16];
    #pragma unroll
    for (int q = 0; q < 16; q++) {
        int i = base + q;
        dloc[q] = (i < n) ? dg[i] : 0;
        s += dloc[q];
    }
    thr[t] = s;
    __syncthreads();
    #pragma unroll
    for (int off = 1; off < 256; off <<= 1) {
        int v = (t >= off) ? thr[t - off] : 0;
        __syncthreads();
        thr[t] += v;
        __syncthreads();
    }
    int offset = part[g * (SCAN_NB + 1) + blockIdx.x] + ((t == 0) ? 0 : thr[t - 1]);
    #pragma unroll
    for (int q = 0; q < 16; q++) {
        int i = base + q;
        if (i < n) {
            rp[i] = offset;
            cu[i] = offset;
            offset += dloc[q];
        }
    }
    if (blockIdx.x == 0 && t == 0) rp[n] = part[g * (SCAN_NB + 1) + nb];
}

// fill CSR + conv1 edge weights, store dst for conv2 weight pass
__global__ void fill_kernel(const int* __restrict__ ei0, const int* __restrict__ ei1,
                            int* __restrict__ cur,
                            int* __restrict__ ecol, int* __restrict__ edst,
                            const float* __restrict__ AS, const float* __restrict__ AD,
                            float* __restrict__ U1, int E) {
    int g = blockIdx.y;
    const int* ei = g ? ei1 : ei0;
    int i = blockIdx.x * blockDim.x + threadIdx.x;
    if (i >= E) return;
    int s = ei[i];
    int d = ei[E + i];
    int slot = atomicAdd(&cur[g * NMAX + d], 1);
    ecol[(size_t)g * EMAX + slot] = s;
    edst[(size_t)g * EMAX + slot] = d;
    float4 a = *(const float4*)&AS[(size_t)g * NMAX * 4 + s * 4];
    float4 b = *(const float4*)&AD[(size_t)g * NMAX * 4 + d * 4];
    float4 u;
    u.x = __expf(leaky(a.x + b.x));
    u.y = __expf(leaky(a.y + b.y));
    u.z = __expf(leaky(a.z + b.z));
    u.w = __expf(leaky(a.w + b.w));
    *(float4*)&U1[((size_t)g * EMAX + slot) * 4] = u;
}

__global__ void w2_kernel(const int* __restrict__ ecol, const int* __restrict__ edst,
                          const float* __restrict__ AS, const float* __restrict__ AD,
                          float* __restrict__ U2, int E) {
    int g = blockIdx.y;
    int j = blockIdx.x * blockDim.x + threadIdx.x;
    if (j >= E) return;
    int s = ecol[(size_t)g * EMAX + j];
    int d = edst[(size_t)g * EMAX + j];
    float u = __expf(leaky(AS[(size_t)g * NMAX * 4 + s * 4] +
                           AD[(size_t)g * NMAX * 4 + d * 4]));
    U2[(size_t)g * EMAX + j] = u;
}

// ---------------------------------------------------------------------------
// conv1 aggregation: single pass, precomputed weights.
// ---------------------------------------------------------------------------
__global__ void agg_x_kernel(const int* __restrict__ rowptr,
                             const int* __restrict__ ecol,
                             const float* __restrict__ U1,
                             const float* __restrict__ AS,
                             const float* __restrict__ AD,
                             const __nv_bfloat16* __restrict__ X16,
                             __nv_bfloat16* __restrict__ AGG,
                             int n) {
    const int g = blockIdx.y;
    const int* rp = rowptr + g * (NMAX + 1);
    const int* ec = ecol + (size_t)g * EMAX;
    const float* U = U1 + (size_t)g * EMAX * 4;
    const __nv_bfloat16* X = X16 + (size_t)g * NMAX * 128;
    __nv_bfloat16* agg = AGG + (size_t)g * NMAX * 512;

    const int warp = (blockIdx.x * blockDim.x + threadIdx.x) >> 5;
    const int lane = threadIdx.x & 31;
    if (warp >= n) return;
    const int d = warp;
    const int beg = rp[d];
    const int end = rp[d + 1];

    float4 asv = *(const float4*)&AS[(size_t)g * NMAX * 4 + d * 4];
    float4 adv = *(const float4*)&AD[(size_t)g * NMAX * 4 + d * 4];
    float den[4];
    den[0] = __expf(leaky(asv.x + adv.x));
    den[1] = __expf(leaky(asv.y + adv.y));
    den[2] = __expf(leaky(asv.z + adv.z));
    den[3] = __expf(leaky(asv.w + adv.w));

    uint2 ux = *(const uint2*)&X[(size_t)d * 128 + lane * 4];
    float2 xd01 = __bfloat1622float2(*(__nv_bfloat162*)&ux.x);
    float2 xd23 = __bfloat1622float2(*(__nv_bfloat162*)&ux.y);

    float acc[4][4];
    #pragma unroll
    for (int h = 0; h < 4; h++) {
        acc[h][0] = den[h] * xd01.x; acc[h][1] = den[h] * xd01.y;
        acc[h][2] = den[h] * xd23.x; acc[h][3] = den[h] * xd23.y;
    }
    for (int j = beg; j < end; j++) {
        int s = ec[j];
        float4 u = *(const float4*)&U[(size_t)j * 4];
        den[0] += u.x; den[1] += u.y; den[2] += u.z; den[3] += u.w;
        uint2 us = *(const uint2*)&X[(size_t)s * 128 + lane * 4];
        float2 f01 = __bfloat1622float2(*(__nv_bfloat162*)&us.x);
        float2 f23 = __bfloat1622float2(*(__nv_bfloat162*)&us.y);
        acc[0][0] += u.x * f01.x; acc[0][1] += u.x * f01.y; acc[0][2] += u.x * f23.x; acc[0][3] += u.x * f23.y;
        acc[1][0] += u.y * f01.x; acc[1][1] += u.y * f01.y; acc[1][2] += u.y * f23.x; acc[1][3] += u.y * f23.y;
        acc[2][0] += u.z * f01.x; acc[2][1] += u.z * f01.y; acc[2][2] += u.z * f23.x; acc[2][3] += u.z * f23.y;
        acc[3][0] += u.w * f01.x; acc[3][1] += u.w * f01.y; acc[3][2] += u.w * f23.x; acc[3][3] += u.w * f23.y;
    }
    #pragma unroll
    for (int h = 0; h < 4; h++) {
        float inv = 1.0f / (den[h] + 1e-16f);
        __nv_bfloat162 q0 = __floats2bfloat162_rn(acc[h][0] * inv, acc[h][1] * inv);
        __nv_bfloat162 q1 = __floats2bfloat162_rn(acc[h][2] * inv, acc[h][3] * inv);
        uint2 u = make_uint2(bf2u(q0), bf2u(q1));
        *(uint2*)&agg[(size_t)d * 512 + h * 128 + lane * 4] = u;
    }
}

// ---------------------------------------------------------------------------
// FUSED GEMM: per 128-row tile, loop over 4 heads:
//   gemm1 (AGG[:,h,:] @ W1T[h]^T, 2-term) -> bias+ELU -> O hi/lo in smem ->
//   gemm2 accumulate (O @ W2T[:, h*64:+64]^T, 3-term).
// Epilogue: alpha dot-products (fp32) + H2 bf16 write.
// ---------------------------------------------------------------------------
#define SMF_A     0       // 128 x 68 words  (AGG chunk bf16)       34816
#define SMF_B1H   34816   // 64 x 68                                 17408
#define SMF_B1L   52224   // 64 x 68                                 17408
#define SMF_OH    69632   // 128 x 36 words  (O hi bf16)             18432
#define SMF_OL    88064   // 128 x 36                                18432
#define SMF_B2H   106496  // 64 x 36                                  9216
#define SMF_B2L   115712  // 64 x 36                                  9216
#define SMF_ALPHA 124928  // 256 floats                                1024
#define SMF_TOTAL 125952

__global__ __launch_bounds__(256, 1)
void gemm_fused_kernel(const __nv_bfloat16* __restrict__ AGG,
                       const __nv_bfloat16* __restrict__ B1hi,
                       const __nv_bfloat16* __restrict__ B1lo,
                       const float* __restrict__ bias1,
                       const __nv_bfloat16* __restrict__ B2hi,
                       const __nv_bfloat16* __restrict__ B2lo,
                       __nv_bfloat16* __restrict__ H2,
                       const float* __restrict__ a_src,
                       const float* __restrict__ a_dst,
                       float* __restrict__ AS,
                       float* __restrict__ AD,
                       int M) {
    extern __shared__ char smem[];
    uint32_t* Asm = (uint32_t*)(smem + SMF_A);
    uint32_t* B1h = (uint32_t*)(smem + SMF_B1H);
    uint32_t* B1l = (uint32_t*)(smem + SMF_B1L);
    uint32_t* Oh  = (uint32_t*)(smem + SMF_OH);
    uint32_t* Ol  = (uint32_t*)(smem + SMF_OL);
    uint32_t* B2h = (uint32_t*)(smem + SMF_B2H);
    uint32_t* B2l = (uint32_t*)(smem + SMF_B2L);
    float* alpha_s = (float*)(smem + SMF_ALPHA);
    float* alpha_d = alpha_s + 128;

    const int g = blockIdx.y;
    const __nv_bfloat16* A = AGG + (size_t)g * NMAX * 512;
    __nv_bfloat16* C = H2 + (size_t)g * NMAX * 64;
    float* ASg = AS + (size_t)g * NMAX * 4;
    float* ADg = AD + (size_t)g * NMAX * 4;
    const int tid = threadIdx.x;
    const int lane = tid & 31;
    const int wid = tid >> 5;
    const int warp_m = wid & 3;
    const int warp_n = wid >> 2;
    const int m0 = blockIdx.x * 128;

    float acc2[2][4][4] = {};

    for (int h = 0; h < 4; h++) {
        if (h) __syncthreads();   // protect smem reuse across heads

        // ---- loads: AGG chunk (8 uint4/thr), W1 head (4), W2 chunk (2) ----
        #pragma unroll
        for (int q = 0; q < 8; q++) {
            int idx = q * 256 + tid;
            int r = idx >> 4;
            int c8 = idx & 15;
            int gr = m0 + r;
            uint4 v = make_uint4(0u, 0u, 0u, 0u);
            if (gr < M) v = *(const uint4*)&A[(size_t)gr * 512 + h * 128 + c8 * 8];
            *(uint4*)&Asm[r * 68 + c8 * 4] = v;
        }
        #pragma unroll
        for (int q = 0; q < 4; q++) {
            int idx = q * 256 + tid;
            int r = idx >> 4;
            int c8 = idx & 15;
            uint4 vh = *(const uint4*)&B1hi[(size_t)(h * 64 + r) * 128 + c8 * 8];
            uint4 vl = *(const uint4*)&B1lo[(size_t)(h * 64 + r) * 128 + c8 * 8];
            *(uint4*)&B1h[r * 68 + c8 * 4] = vh;
            *(uint4*)&B1l[r * 68 + c8 * 4] = vl;
        }
        #pragma unroll
        for (int q = 0; q < 2; q++) {
            int idx = q * 256 + tid;
            int r = idx >> 3;
            int c8 = idx & 7;
            uint4 vh = *(const uint4*)&B2hi[(size_t)r * 256 + h * 64 + c8 * 8];
            uint4 vl = *(const uint4*)&B2lo[(size_t)r * 256 + h * 64 + c8 * 8];
            *(uint4*)&B2h[r * 36 + c8 * 4] = vh;
            *(uint4*)&B2l[r * 36 + c8 * 4] = vl;
        }
        __syncthreads();

        // ---- gemm1: acc1 = AGG_chunk @ W1T[h]^T (2-term) ----
        float acc1[2][4][4] = {};
        #pragma unroll
        for (int ks = 0; ks < 8; ks++) {
            const int kw = ks * 8 + (lane & 3);
            uint32_t ah[2][4], bh[4][2], bl[4][2];
            #pragma unroll
            for (int mt = 0; mt < 2; mt++) {
                int r0 = warp_m * 32 + mt * 16 + (lane >> 2);
                ah[mt][0] = Asm[r0 * 68 + kw];
                ah[mt][1] = Asm[(r0 + 8) * 68 + kw];
                ah[mt][2] = Asm[r0 * 68 + kw + 4];
                ah[mt][3] = Asm[(r0 + 8) * 68 + kw + 4];
            }
            #pragma unroll
            for (int nt = 0; nt < 4; nt++) {
                int n0 = warp_n * 32 + nt * 8 + (lane >> 2);
                bh[nt][0] = B1h[n0 * 68 + kw];
                bh[nt][1] = B1h[n0 * 68 + kw + 4];
                bl[nt][0] = B1l[n0 * 68 + kw];
                bl[nt][1] = B1l[n0 * 68 + kw + 4];
            }
            #pragma unroll
            for (int mt = 0; mt < 2; mt++)
                #pragma unroll
                for (int nt = 0; nt < 4; nt++) {
                    mma16816(acc1[mt][nt], ah[mt], bh[nt]);
                    mma16816(acc1[mt][nt], ah[mt], bl[nt]);
                }
        }

        // ---- bias + ELU, split hi/lo into O smem ----
        #pragma unroll
        for (int mt = 0; mt < 2; mt++) {
            int r0 = warp_m * 32 + mt * 16 + (lane >> 2);
            #pragma unroll
            for (int nt = 0; nt < 4; nt++) {
                int c0 = warp_n * 32 + nt * 8 + (lane & 3) * 2;
                float b0 = __ldg(&bias1[h * 64 + c0]);
                float b1v = __ldg(&bias1[h * 64 + c0 + 1]);
                float* a4 = acc1[mt][nt];
                float v00 = a4[0] + b0, v01 = a4[1] + b1v;
                float v10 = a4[2] + b0, v11 = a4[3] + b1v;
                v00 = v00 > 0.f ? v00 : (__expf(v00) - 1.f);
                v01 = v01 > 0.f ? v01 : (__expf(v01) - 1.f);
                v10 = v10 > 0.f ? v10 : (__expf(v10) - 1.f);
                v11 = v11 > 0.f ? v11 : (__expf(v11) - 1.f);
                int w = warp_n * 16 + nt * 4 + (lane & 3);   // c0 >> 1
                __nv_bfloat162 h0 = __floats2bfloat162_rn(v00, v01);
                __nv_bfloat162 h1 = __floats2bfloat162_rn(v10, v11);
                float2 f0 = __bfloat1622float2(h0);
                float2 f1 = __bfloat1622float2(h1);
                __nv_bfloat162 l0 = __floats2bfloat162_rn(v00 - f0.x, v01 - f0.y);
                __nv_bfloat162 l1 = __floats2bfloat162_rn(v10 - f1.x, v11 - f1.y);
                Oh[r0 * 36 + w] = bf2u(h0);
                Oh[(r0 + 8) * 36 + w] = bf2u(h1);
                Ol[r0 * 36 + w] = bf2u(l0);
                Ol[(r0 + 8) * 36 + w] = bf2u(l1);
            }
        }
        __syncthreads();

        // ---- gemm2 accumulate: acc2 += O @ W2T_chunk^T (3-term) ----
        #pragma unroll
        for (int ks = 0; ks < 4; ks++) {
            const int kw = ks * 8 + (lane & 3);
            uint32_t aoh[2][4], aol[2][4], bh[4][2], bl[4][2];
            #pragma unroll
            for (int mt = 0; mt < 2; mt++) {
                int r0 = warp_m * 32 + mt * 16 + (lane >> 2);
                aoh[mt][0] = Oh[r0 * 36 + kw];
                aoh[mt][1] = Oh[(r0 + 8) * 36 + kw];
                aoh[mt][2] = Oh[r0 * 36 + kw + 4];
                aoh[mt][3] = Oh[(r0 + 8) * 36 + kw + 4];
                aol[mt][0] = Ol[r0 * 36 + kw];
                aol[mt][1] = Ol[(r0 + 8) * 36 + kw];
                aol[mt][2] = Ol[r0 * 36 + kw + 4];
                aol[mt][3] = Ol[(r0 + 8) * 36 + kw + 4];
            }
            #pragma unroll
            for (int nt = 0; nt < 4; nt++) {
                int n0 = warp_n * 32 + nt * 8 + (lane >> 2);
                bh[nt][0] = B2h[n0 * 36 + kw];
                bh[nt][1] = B2h[n0 * 36 + kw + 4];
                bl[nt][0] = B2l[n0 * 36 + kw];
                bl[nt][1] = B2l[n0 * 36 + kw + 4];
            }
            #pragma unroll
            for (int mt = 0; mt < 2; mt++)
                #pragma unroll
                for (int nt = 0; nt < 4; nt++) {
                    mma16816(acc2[mt][nt], aoh[mt], bh[nt]);
                    mma16816(acc2[mt][nt], aoh[mt], bl[nt]);
                    mma16816(acc2[mt][nt], aol[mt], bh[nt]);
                }
        }
    }

    // ---- epilogue: H2 write + conv2 alpha dot-products ----
    __syncthreads();
    if (tid < 128) { alpha_s[tid] = 0.0f; alpha_d[tid] = 0.0f; }
    __syncthreads();

    float sp[4] = {0.f, 0.f, 0.f, 0.f};
    float dp[4] = {0.f, 0.f, 0.f, 0.f};
    #pragma unroll
    for (int mt = 0; mt < 2; mt++) {
        int r0 = warp_m * 32 + mt * 16 + (lane >> 2);
        #pragma unroll
        for (int nt = 0; nt < 4; nt++) {
            int c0 = warp_n * 32 + nt * 8 + (lane & 3) * 2;
            float* a4 = acc2[mt][nt];
            int gr0 = m0 + r0, gr1 = gr0 + 8;
            if (gr0 < M)
                *(__nv_bfloat162*)&C[(size_t)gr0 * 64 + c0] = __floats2bfloat162_rn(a4[0], a4[1]);
            if (gr1 < M)
                *(__nv_bfloat162*)&C[(size_t)gr1 * 64 + c0] = __floats2bfloat162_rn(a4[2], a4[3]);
            float s0 = __ldg(&a_src[c0]);
            float s1 = __ldg(&a_src[c0 + 1]);
            float d0 = __ldg(&a_dst[c0]);
            float d1 = __ldg(&a_dst[c0 + 1]);
            sp[mt * 2]     += a4[0] * s0 + a4[1] * s1;
            sp[mt * 2 + 1] += a4[2] * s0 + a4[3] * s1;
            dp[mt * 2]     += a4[0] * d0 + a4[1] * d1;
            dp[mt * 2 + 1] += a4[2] * d0 + a4[3] * d1;
        }
    }
    #pragma unroll
    for (int i = 0; i < 4; i++) {
        sp[i] += __shfl_xor_sync(0xffffffffu, sp[i], 1);
        sp[i] += __shfl_xor_sync(0xffffffffu, sp[i], 2);
        dp[i] += __shfl_xor_sync(0xffffffffu, dp[i], 1);
        dp[i] += __shfl_xor_sync(0xffffffffu, dp[i], 2);
    }
    if ((lane & 3) == 0) {
        int r0 = warp_m * 32 + (lane >> 2);
        atomicAdd(&alpha_s[r0],      sp[0]);
        atomicAdd(&alpha_s[r0 + 8],  sp[1]);
        atomicAdd(&alpha_s[r0 + 16], sp[2]);
        atomicAdd(&alpha_s[r0 + 24], sp[3]);
        atomicAdd(&alpha_d[r0],      dp[0]);
        atomicAdd(&alpha_d[r0 + 8],  dp[1]);
        atomicAdd(&alpha_d[r0 + 16], dp[2]);
        atomicAdd(&alpha_d[r0 + 24], dp[3]);
    }
    __syncthreads();
    if (tid < 128) {
        int gr = m0 + tid;
        if (gr < M) {
            ASg[gr * 4] = alpha_s[tid];
            ADg[gr * 4] = alpha_d[tid];
        }
    }
}

// ---------------------------------------------------------------------------
// conv2 aggregation (heads=1, bf16 messages, precomputed weights) + mean pool.
// ---------------------------------------------------------------------------
__global__ void agg2_pool_kernel(const int* __restrict__ rowptr,
                                 const int* __restrict__ ecol,
                                 const float* __restrict__ U2,
                                 const float* __restrict__ AS,
                                 const float* __restrict__ AD,
                                 const __nv_bfloat16* __restrict__ H2,
                                 const float* __restrict__ bias,
                                 const int* __restrict__ bt0,
                                 const int* __restrict__ bt1,
                                 float* __restrict__ POOL,
                                 float* __restrict__ CNT,
                                 int n) {
    const int g = blockIdx.y;
    const int* rp = rowptr + g * (NMAX + 1);
    const int* ec = ecol + (size_t)g * EMAX;
    const float* U = U2 + (size_t)g * EMAX;
    const __nv_bfloat16* H = H2 + (size_t)g * NMAX * 64;
    const int* batch = g ? bt1 : bt0;
    float* pool = POOL + g * GNUM * 64;
    float* cnt = CNT + g * GNUM;

    const int warp = (blockIdx.x * blockDim.x + threadIdx.x) >> 5;
    const int lane = threadIdx.x & 31;
    if (warp >= n) return;
    const int d = warp;
    const int beg = rp[d];
    const int end = rp[d + 1];

    float den = __expf(leaky(AS[(size_t)g * NMAX * 4 + d * 4] +
                             AD[(size_t)g * NMAX * 4 + d * 4]));
    float2 hv = __bfloat1622float2(*(const __nv_bfloat162*)&H[(size_t)d * 64 + lane * 2]);
    float a0 = den * hv.x, a1 = den * hv.y;
    for (int j = beg; j < end; j++) {
        int s = ec[j];
        float u = U[j];
        den += u;
        float2 hs = __bfloat1622float2(*(const __nv_bfloat162*)&H[(size_t)s * 64 + lane * 2]);
        a0 += u * hs.x;
        a1 += u * hs.y;
    }
    float inv = 1.0f / (den + 1e-16f);
    float v0 = a0 * inv + bias[lane * 2];
    float v1 = a1 * inv + bias[lane * 2 + 1];
    v0 = v0 > 0.0f ? v0 : (__expf(v0) - 1.0f);
    v1 = v1 > 0.0f ? v1 : (__expf(v1) - 1.0f);
    int grp = batch[d];
    atomicAdd(&pool[grp * 64 + lane * 2], v0);
    atomicAdd(&pool[grp * 64 + lane * 2 + 1], v1);
    if (lane == 0) atomicAdd(&cnt[grp], 1.0f);
}

__global__ void final_write_kernel(const float* __restrict__ POOL,
                                   const float* __restrict__ CNT,
                                   float* __restrict__ out) {
    int i = blockIdx.x * blockDim.x + threadIdx.x;
    if (i >= 2 * GNUM * 64) return;
    float c = CNT[i >> 6];
    out[i] = POOL[i] / fmaxf(c, 1.0f);
}

// ---------------------------------------------------------------------------
// Launch
// ---------------------------------------------------------------------------
extern "C" void kernel_launch(void* const* d_in, const int* in_sizes, int n_in,
                              void* d_out, int out_size) {
    const float* x1  = (const float*)d_in[0];
    const int*   ei1 = (const int*)d_in[1];
    const int*   bt1 = (const int*)d_in[2];
    const float* x2  = (const float*)d_in[3];
    const int*   ei2 = (const int*)d_in[4];
    const int*   bt2 = (const int*)d_in[5];
    const float* W1  = (const float*)d_in[6];
    const float* as1 = (const float*)d_in[7];
    const float* ad1 = (const float*)d_in[8];
    const float* b1  = (const float*)d_in[9];
    const float* W2  = (const float*)d_in[10];
    const float* as2 = (const float*)d_in[11];
    const float* ad2 = (const float*)d_in[12];
    const float* b2  = (const float*)d_in[13];

    const int n = in_sizes[0] / 128;
    const int e = in_sizes[1] / 2;
    const int nb = cdiv(n, SCAN_CHUNK);

    float *AS, *AD, *POOL, *CNT, *P1S, *P1D, *U1, *U2;
    int *DEG, *ROWPTR, *CUR, *ECOL, *EDST, *PART;
    __nv_bfloat16 *X16, *AGG, *H2, *W1TH, *W1TL, *W2TH, *W2TL;
    cudaGetSymbolAddress((void**)&X16,    g_X16);
    cudaGetSymbolAddress((void**)&AGG,    g_AGG);
    cudaGetSymbolAddress((void**)&H2,     g_H2);
    cudaGetSymbolAddress((void**)&AS,     g_AS);
    cudaGetSymbolAddress((void**)&AD,     g_AD);
    cudaGetSymbolAddress((void**)&DEG,    g_DEG);
    cudaGetSymbolAddress((void**)&ROWPTR, g_ROWPTR);
    cudaGetSymbolAddress((void**)&CUR,    g_CUR);
    cudaGetSymbolAddress((void**)&ECOL,   g_ECOL);
    cudaGetSymbolAddress((void**)&EDST,   g_EDST);
    cudaGetSymbolAddress((void**)&U1,     g_U1);
    cudaGetSymbolAddress((void**)&U2,     g_U2);
    cudaGetSymbolAddress((void**)&PART,   g_PART);
    cudaGetSymbolAddress((void**)&POOL,   g_POOL);
    cudaGetSymbolAddress((void**)&CNT,    g_CNT);
    cudaGetSymbolAddress((void**)&P1S,    g_P1S);
    cudaGetSymbolAddress((void**)&P1D,    g_P1D);
    cudaGetSymbolAddress((void**)&W1TH,   g_W1T_HI);
    cudaGetSymbolAddress((void**)&W1TL,   g_W1T_LO);
    cudaGetSymbolAddress((void**)&W2TH,   g_W2T_HI);
    cudaGetSymbolAddress((void**)&W2TL,   g_W2T_LO);

    cudaFuncSetAttribute(gemm_fused_kernel,
                         cudaFuncAttributeMaxDynamicSharedMemorySize, SMF_TOTAL);

    setup_kernel<<<cdiv(SETUP_TOTAL, 256), 256>>>(W1, W2, as1, ad1,
                                                  W1TH, W1TL, W2TH, W2TL,
                                                  P1S, P1D, POOL, CNT, DEG);
    {
        // parts 0,1: alphas+X16 (needs grid.x = cdiv(n*32,256)); parts 2,3: hist
        int gx = cdiv(n, 8);
        if (gx < cdiv(e, 256)) gx = cdiv(e, 256);
        dim3 gs(gx, 4);
        stage1_kernel<<<gs, 256>>>(x1, x2, P1S, P1D, AS, AD, X16,
                                   ei1, ei2, DEG, n, e);
    }
    {
        dim3 gs2(nb, 2);
        scan_partial_kernel<<<gs2, 256>>>(DEG, PART, n);
        scan_root_kernel<<<2, 32>>>(PART, nb);
        scan_final_kernel<<<gs2, 256>>>(DEG, PART, ROWPTR, CUR, n, nb);
    }
    {
        dim3 ge2(cdiv(e, 256), 2);
        fill_kernel<<<ge2, 256>>>(ei1, ei2, CUR, ECOL, EDST, AS, AD, U1, e);
    }
    {
        dim3 ga(cdiv(n, 8), 2);
        agg_x_kernel<<<ga, 256>>>(ROWPTR, ECOL, U1, AS, AD, X16, AGG, n);
    }
    {
        dim3 gg(cdiv(n, 128), 2);
        gemm_fused_kernel<<<gg, 256, SMF_TOTAL>>>(AGG, W1TH, W1TL, b1,
                                                  W2TH, W2TL, H2,
                                                  as2, ad2, AS, AD, n);
    }
    {
        dim3 ge2(cdiv(e, 256), 2);
        w2_kernel<<<ge2, 256>>>(ECOL, EDST, AS, AD, U2, e);
    }
    {
        dim3 ga(cdiv(n, 8), 2);
        agg2_pool_kernel<<<ga, 256>>>(ROWPTR, ECOL, U2, AS, AD, H2, b2,
                                      bt1, bt2, POOL, CNT, n);
    }
    final_write_kernel<<<cdiv(2 * GNUM * 64, 256), 256>>>(POOL, CNT, (float*)d_out);
}

// round 11
// speedup vs baseline: 1.1479x; 1.0478x over previous
#include <cuda_runtime.h>
#include <cuda_bf16.h>
#include <cstdint>

// ---------------------------------------------------------------------------
// GATGraphSimilarity: Siamese 2-layer GAT (heads=4 then 1) + mean pool.
// Round 11: decoupled-lookback single-kernel scan, conv2 edge weights
// computed in-warp (w2/U2/EDST deleted), agg_x MLP x2. 8 launches total.
// ---------------------------------------------------------------------------

#define NMAX 50000
#define EMAX 800000
#define GNUM 64
#define NEG_SLOPE 0.2f
#define SCAN_CHUNK 4096
#define SCAN_NB ((NMAX + SCAN_CHUNK - 1) / SCAN_CHUNK)

__device__ __nv_bfloat16 g_X16[2][(size_t)NMAX * 128];
__device__ __nv_bfloat16 g_AGG[2][(size_t)NMAX * 512];
__device__ __nv_bfloat16 g_H2 [2][(size_t)NMAX * 64];
__device__ float g_AS  [2][NMAX * 4];
__device__ float g_AD  [2][NMAX * 4];
__device__ int   g_DEG [2][NMAX];
__device__ int   g_ROWPTR[2][NMAX + 1];
__device__ int   g_CUR [2][NMAX];
__device__ int   g_ECOL[2][EMAX];
__device__ float g_U1  [2][(size_t)EMAX * 4];
__device__ unsigned long long g_LOOK[2][SCAN_NB];   // lookback state (flag<<32|val)
__device__ float g_POOL[2 * GNUM * 64];
__device__ float g_CNT [2 * GNUM];
__device__ float g_P1S [128 * 4];
__device__ float g_P1D [128 * 4];
__device__ __nv_bfloat16 g_W1T_HI[256 * 128];
__device__ __nv_bfloat16 g_W1T_LO[256 * 128];
__device__ __nv_bfloat16 g_W2T_HI[64 * 256];
__device__ __nv_bfloat16 g_W2T_LO[64 * 256];

static inline int cdiv(int a, int b) { return (a + b - 1) / b; }

__device__ __forceinline__ float leaky(float v) {
    return v > 0.0f ? v : NEG_SLOPE * v;
}

__device__ __forceinline__ uint32_t bf2u(__nv_bfloat162 v) {
    return *reinterpret_cast<uint32_t*>(&v);
}

__device__ __forceinline__ void mma16816(float* d, const uint32_t* a, const uint32_t* b) {
    asm volatile(
        "mma.sync.aligned.m16n8k16.row.col.f32.bf16.bf16.f32 "
        "{%0,%1,%2,%3}, {%4,%5,%6,%7}, {%8,%9}, {%0,%1,%2,%3};"
        : "+f"(d[0]), "+f"(d[1]), "+f"(d[2]), "+f"(d[3])
        : "r"(a[0]), "r"(a[1]), "r"(a[2]), "r"(a[3]), "r"(b[0]), "r"(b[1]));
}

// ---------------------------------------------------------------------------
// Setup: weight prep, P1 fold, pool/DEG/LOOK zero
// ---------------------------------------------------------------------------
#define SEG1 (256 * 128)
#define SEG2 (64 * 256)
#define SEG3 1024
#define SEG4 (2 * GNUM * 64 + 2 * GNUM)
#define SEG5 (2 * NMAX)
#define SEG6 (2 * SCAN_NB)
#define SETUP_TOTAL (SEG1 + SEG2 + SEG3 + SEG4 + SEG5 + SEG6)

__global__ void setup_kernel(const float* __restrict__ W1,
                             const float* __restrict__ W2,
                             const float* __restrict__ as1,
                             const float* __restrict__ ad1,
                             __nv_bfloat16* __restrict__ W1TH,
                             __nv_bfloat16* __restrict__ W1TL,
                             __nv_bfloat16* __restrict__ W2TH,
                             __nv_bfloat16* __restrict__ W2TL,
                             float* __restrict__ P1S,
                             float* __restrict__ P1D,
                             float* __restrict__ POOL,
                             float* __restrict__ CNT,
                             int* __restrict__ DEG,
                             unsigned long long* __restrict__ LOOK) {
    int i = blockIdx.x * blockDim.x + threadIdx.x;
    if (i < SEG1) {
        int n = i / 128, k = i % 128;
        float v = W1[(size_t)k * 256 + n];
        __nv_bfloat16 h = __float2bfloat16(v);
        W1TH[i] = h;
        W1TL[i] = __float2bfloat16(v - __bfloat162float(h));
        return;
    }
    i -= SEG1;
    if (i < SEG2) {
        int n = i / 256, k = i % 256;
        float v = W2[(size_t)k * 64 + n];
        __nv_bfloat16 h = __float2bfloat16(v);
        W2TH[i] = h;
        W2TL[i] = __float2bfloat16(v - __bfloat162float(h));
        return;
    }
    i -= SEG2;
    if (i < SEG3) {
        int is_dst = i >> 9;
        int o = i & 511;
        int k = o >> 2, h = o & 3;
        const float* a = is_dst ? ad1 : as1;
        float s = 0.0f;
        #pragma unroll 8
        for (int d = 0; d < 64; d++)
            s += W1[(size_t)k * 256 + h * 64 + d] * a[h * 64 + d];
        (is_dst ? P1D : P1S)[k * 4 + h] = s;
        return;
    }
    i -= SEG3;
    if (i < 2 * GNUM * 64) { POOL[i] = 0.0f; return; }
    i -= 2 * GNUM * 64;
    if (i < 2 * GNUM) { CNT[i] = 0.0f; return; }
    i -= 2 * GNUM;
    if (i < SEG5) { DEG[i] = 0; return; }
    i -= SEG5;
    if (i < SEG6) LOOK[i] = 0ULL;
}

// ---------------------------------------------------------------------------
// Stage1: alphas+X16 (parts 0,1) and degree histogram (parts 2,3).
// ---------------------------------------------------------------------------
__global__ void stage1_kernel(const float* __restrict__ x0,
                              const float* __restrict__ x1,
                              const float* __restrict__ P1S,
                              const float* __restrict__ P1D,
                              float* __restrict__ AS,
                              float* __restrict__ AD,
                              __nv_bfloat16* __restrict__ X16,
                              const int* __restrict__ ei0,
                              const int* __restrict__ ei1,
                              int* __restrict__ deg,
                              int n, int E) {
    const int part = blockIdx.y;
    if (part >= 2) {
        int g = part - 2;
        const int* ei = g ? ei1 : ei0;
        int i = blockIdx.x * blockDim.x + threadIdx.x;
        if (i < E) atomicAdd(&deg[g * NMAX + ei[E + i]], 1);
        return;
    }
    const int g = part;
    const float* x = g ? x1 : x0;
    const int warp = (blockIdx.x * blockDim.x + threadIdx.x) >> 5;
    const int lane = threadIdx.x & 31;
    if (warp >= n) return;
    float4 xv = *(const float4*)&x[(size_t)warp * 128 + lane * 4];
    {
        __nv_bfloat162 p0 = __floats2bfloat162_rn(xv.x, xv.y);
        __nv_bfloat162 p1 = __floats2bfloat162_rn(xv.z, xv.w);
        uint2 u = make_uint2(bf2u(p0), bf2u(p1));
        *(uint2*)&X16[(size_t)g * NMAX * 128 + (size_t)warp * 128 + lane * 4] = u;
    }
    float s[4] = {0.f, 0.f, 0.f, 0.f};
    float d[4] = {0.f, 0.f, 0.f, 0.f};
    const float* xp = (const float*)&xv;
    #pragma unroll
    for (int j = 0; j < 4; j++) {
        float xk = xp[j];
        float4 ps = *(const float4*)&P1S[(lane * 4 + j) * 4];
        float4 pd = *(const float4*)&P1D[(lane * 4 + j) * 4];
        s[0] += xk * ps.x; s[1] += xk * ps.y; s[2] += xk * ps.z; s[3] += xk * ps.w;
        d[0] += xk * pd.x; d[1] += xk * pd.y; d[2] += xk * pd.z; d[3] += xk * pd.w;
    }
    #pragma unroll
    for (int off = 16; off >= 1; off >>= 1) {
        #pragma unroll
        for (int h = 0; h < 4; h++) {
            s[h] += __shfl_xor_sync(0xffffffffu, s[h], off);
            d[h] += __shfl_xor_sync(0xffffffffu, d[h], off);
        }
    }
    if (lane == 0) {
        *(float4*)&AS[(size_t)g * NMAX * 4 + warp * 4] = make_float4(s[0], s[1], s[2], s[3]);
        *(float4*)&AD[(size_t)g * NMAX * 4 + warp * 4] = make_float4(d[0], d[1], d[2], d[3]);
    }
}

// ---------------------------------------------------------------------------
// Single-kernel decoupled-lookback scan: deg -> rowptr (exclusive), cur copy.
// LOOK word: (flag << 32) | value. flag 1 = aggregate, 2 = inclusive prefix.
// ---------------------------------------------------------------------------
__global__ void scan_lookback_kernel(const int* __restrict__ deg,
                                     int* __restrict__ rowptr,
                                     int* __restrict__ cur,
                                     unsigned long long* __restrict__ LOOK,
                                     int n, int nb) {
    __shared__ int thr[256];
    __shared__ int sh_P;
    const int g = blockIdx.y;
    const int b = blockIdx.x;
    const int t = threadIdx.x;
    const int base = b * SCAN_CHUNK + t * 16;
    const int* dg = deg + g * NMAX;
    int* rp = rowptr + g * (NMAX + 1);
    int* cu = cur + g * NMAX;
    unsigned long long* look = LOOK + g * SCAN_NB;

    int s = 0;
    int dloc[16];
    #pragma unroll
    for (int q = 0; q < 16; q++) {
        int i = base + q;
        dloc[q] = (i < n) ? dg[i] : 0;
        s += dloc[q];
    }
    thr[t] = s;
    __syncthreads();
    #pragma unroll
    for (int off = 1; off < 256; off <<= 1) {
        int v = (t >= off) ? thr[t - off] : 0;
        __syncthreads();
        thr[t] += v;
        __syncthreads();
    }
    const int total = thr[255];

    if (t == 0) {
        int P = 0;
        if (b == 0) {
            atomicExch(&look[0], (2ULL << 32) | (unsigned int)total);
        } else {
            atomicExch(&look[b], (1ULL << 32) | (unsigned int)total);
            int i = b - 1;
            while (true) {
                unsigned long long w;
                do { w = atomicAdd(&look[i], 0ULL); } while ((w >> 32) == 0ULL);
                int v = (int)(w & 0xffffffffULL);
                P += v;
                if ((w >> 32) == 2ULL) break;
                i--;
            }
            atomicExch(&look[b], (2ULL << 32) | (unsigned int)(P + total));
        }
        sh_P = P;
    }
    __syncthreads();

    int offset = sh_P + ((t == 0) ? 0 : thr[t - 1]);
    #pragma unroll
    for (int q = 0; q < 16; q++) {
        int i = base + q;
        if (i < n) {
            rp[i] = offset;
            cu[i] = offset;
            offset += dloc[q];
        }
    }
    if (b == nb - 1 && t == 255) rp[n] = offset;   // inclusive total
}

// fill CSR + conv1 edge weights (lane-parallel exps)
__global__ void fill_kernel(const int* __restrict__ ei0, const int* __restrict__ ei1,
                            int* __restrict__ cur,
                            int* __restrict__ ecol,
                            const float* __restrict__ AS, const float* __restrict__ AD,
                            float* __restrict__ U1, int E) {
    int g = blockIdx.y;
    const int* ei = g ? ei1 : ei0;
    int i = blockIdx.x * blockDim.x + threadIdx.x;
    if (i >= E) return;
    int s = ei[i];
    int d = ei[E + i];
    int slot = atomicAdd(&cur[g * NMAX + d], 1);
    ecol[(size_t)g * EMAX + slot] = s;
    float4 a = *(const float4*)&AS[(size_t)g * NMAX * 4 + s * 4];
    float4 b = *(const float4*)&AD[(size_t)g * NMAX * 4 + d * 4];
    float4 u;
    u.x = __expf(leaky(a.x + b.x));
    u.y = __expf(leaky(a.y + b.y));
    u.z = __expf(leaky(a.z + b.z));
    u.w = __expf(leaky(a.w + b.w));
    *(float4*)&U1[((size_t)g * EMAX + slot) * 4] = u;
}

// ---------------------------------------------------------------------------
// conv1 aggregation: single pass, precomputed weights, MLP x2 unroll.
// ---------------------------------------------------------------------------
__global__ void agg_x_kernel(const int* __restrict__ rowptr,
                             const int* __restrict__ ecol,
                             const float* __restrict__ U1,
                             const float* __restrict__ AS,
                             const float* __restrict__ AD,
                             const __nv_bfloat16* __restrict__ X16,
                             __nv_bfloat16* __restrict__ AGG,
                             int n) {
    const int g = blockIdx.y;
    const int* rp = rowptr + g * (NMAX + 1);
    const int* ec = ecol + (size_t)g * EMAX;
    const float* U = U1 + (size_t)g * EMAX * 4;
    const __nv_bfloat16* X = X16 + (size_t)g * NMAX * 128;
    __nv_bfloat16* agg = AGG + (size_t)g * NMAX * 512;

    const int warp = (blockIdx.x * blockDim.x + threadIdx.x) >> 5;
    const int lane = threadIdx.x & 31;
    if (warp >= n) return;
    const int d = warp;
    const int beg = rp[d];
    const int end = rp[d + 1];

    float4 asv = *(const float4*)&AS[(size_t)g * NMAX * 4 + d * 4];
    float4 adv = *(const float4*)&AD[(size_t)g * NMAX * 4 + d * 4];
    float den[4];
    den[0] = __expf(leaky(asv.x + adv.x));
    den[1] = __expf(leaky(asv.y + adv.y));
    den[2] = __expf(leaky(asv.z + adv.z));
    den[3] = __expf(leaky(asv.w + adv.w));

    uint2 ux = *(const uint2*)&X[(size_t)d * 128 + lane * 4];
    float2 xd01 = __bfloat1622float2(*(__nv_bfloat162*)&ux.x);
    float2 xd23 = __bfloat1622float2(*(__nv_bfloat162*)&ux.y);

    float acc[4][4];
    #pragma unroll
    for (int h = 0; h < 4; h++) {
        acc[h][0] = den[h] * xd01.x; acc[h][1] = den[h] * xd01.y;
        acc[h][2] = den[h] * xd23.x; acc[h][3] = den[h] * xd23.y;
    }

    int j = beg;
    for (; j + 2 <= end; j += 2) {
        int s0 = ec[j];
        int s1 = ec[j + 1];
        float4 u0 = *(const float4*)&U[(size_t)j * 4];
        float4 u1 = *(const float4*)&U[(size_t)(j + 1) * 4];
        uint2 q0 = *(const uint2*)&X[(size_t)s0 * 128 + lane * 4];
        uint2 q1 = *(const uint2*)&X[(size_t)s1 * 128 + lane * 4];
        den[0] += u0.x + u1.x; den[1] += u0.y + u1.y;
        den[2] += u0.z + u1.z; den[3] += u0.w + u1.w;
        float2 a01 = __bfloat1622float2(*(__nv_bfloat162*)&q0.x);
        float2 a23 = __bfloat1622float2(*(__nv_bfloat162*)&q0.y);
        float2 b01 = __bfloat1622float2(*(__nv_bfloat162*)&q1.x);
        float2 b23 = __bfloat1622float2(*(__nv_bfloat162*)&q1.y);
        acc[0][0] += u0.x * a01.x + u1.x * b01.x;
        acc[0][1] += u0.x * a01.y + u1.x * b01.y;
        acc[0][2] += u0.x * a23.x + u1.x * b23.x;
        acc[0][3] += u0.x * a23.y + u1.x * b23.y;
        acc[1][0] += u0.y * a01.x + u1.y * b01.x;
        acc[1][1] += u0.y * a01.y + u1.y * b01.y;
        acc[1][2] += u0.y * a23.x + u1.y * b23.x;
        acc[1][3] += u0.y * a23.y + u1.y * b23.y;
        acc[2][0] += u0.z * a01.x + u1.z * b01.x;
        acc[2][1] += u0.z * a01.y + u1.z * b01.y;
        acc[2][2] += u0.z * a23.x + u1.z * b23.x;
        acc[2][3] += u0.z * a23.y + u1.z * b23.y;
        acc[3][0] += u0.w * a01.x + u1.w * b01.x;
        acc[3][1] += u0.w * a01.y + u1.w * b01.y;
        acc[3][2] += u0.w * a23.x + u1.w * b23.x;
        acc[3][3] += u0.w * a23.y + u1.w * b23.y;
    }
    if (j < end) {
        int s0 = ec[j];
        float4 u0 = *(const float4*)&U[(size_t)j * 4];
        uint2 q0 = *(const uint2*)&X[(size_t)s0 * 128 + lane * 4];
        den[0] += u0.x; den[1] += u0.y; den[2] += u0.z; den[3] += u0.w;
        float2 a01 = __bfloat1622float2(*(__nv_bfloat162*)&q0.x);
        float2 a23 = __bfloat1622float2(*(__nv_bfloat162*)&q0.y);
        acc[0][0] += u0.x * a01.x; acc[0][1] += u0.x * a01.y;
        acc[0][2] += u0.x * a23.x; acc[0][3] += u0.x * a23.y;
        acc[1][0] += u0.y * a01.x; acc[1][1] += u0.y * a01.y;
        acc[1][2] += u0.y * a23.x; acc[1][3] += u0.y * a23.y;
        acc[2][0] += u0.z * a01.x; acc[2][1] += u0.z * a01.y;
        acc[2][2] += u0.z * a23.x; acc[2][3] += u0.z * a23.y;
        acc[3][0] += u0.w * a01.x; acc[3][1] += u0.w * a01.y;
        acc[3][2] += u0.w * a23.x; acc[3][3] += u0.w * a23.y;
    }

    #pragma unroll
    for (int h = 0; h < 4; h++) {
        float inv = 1.0f / (den[h] + 1e-16f);
        __nv_bfloat162 q0 = __floats2bfloat162_rn(acc[h][0] * inv, acc[h][1] * inv);
        __nv_bfloat162 q1 = __floats2bfloat162_rn(acc[h][2] * inv, acc[h][3] * inv);
        uint2 u = make_uint2(bf2u(q0), bf2u(q1));
        *(uint2*)&agg[(size_t)d * 512 + h * 128 + lane * 4] = u;
    }
}

// ---------------------------------------------------------------------------
// FUSED GEMM (unchanged from round 10)
// ---------------------------------------------------------------------------
#define SMF_A     0
#define SMF_B1H   34816
#define SMF_B1L   52224
#define SMF_OH    69632
#define SMF_OL    88064
#define SMF_B2H   106496
#define SMF_B2L   115712
#define SMF_ALPHA 124928
#define SMF_TOTAL 125952

__global__ __launch_bounds__(256, 1)
void gemm_fused_kernel(const __nv_bfloat16* __restrict__ AGG,
                       const __nv_bfloat16* __restrict__ B1hi,
                       const __nv_bfloat16* __restrict__ B1lo,
                       const float* __restrict__ bias1,
                       const __nv_bfloat16* __restrict__ B2hi,
                       const __nv_bfloat16* __restrict__ B2lo,
                       __nv_bfloat16* __restrict__ H2,
                       const float* __restrict__ a_src,
                       const float* __restrict__ a_dst,
                       float* __restrict__ AS,
                       float* __restrict__ AD,
                       int M) {
    extern __shared__ char smem[];
    uint32_t* Asm = (uint32_t*)(smem + SMF_A);
    uint32_t* B1h = (uint32_t*)(smem + SMF_B1H);
    uint32_t* B1l = (uint32_t*)(smem + SMF_B1L);
    uint32_t* Oh  = (uint32_t*)(smem + SMF_OH);
    uint32_t* Ol  = (uint32_t*)(smem + SMF_OL);
    uint32_t* B2h = (uint32_t*)(smem + SMF_B2H);
    uint32_t* B2l = (uint32_t*)(smem + SMF_B2L);
    float* alpha_s = (float*)(smem + SMF_ALPHA);
    float* alpha_d = alpha_s + 128;

    const int g = blockIdx.y;
    const __nv_bfloat16* A = AGG + (size_t)g * NMAX * 512;
    __nv_bfloat16* C = H2 + (size_t)g * NMAX * 64;
    float* ASg = AS + (size_t)g * NMAX * 4;
    float* ADg = AD + (size_t)g * NMAX * 4;
    const int tid = threadIdx.x;
    const int lane = tid & 31;
    const int wid = tid >> 5;
    const int warp_m = wid & 3;
    const int warp_n = wid >> 2;
    const int m0 = blockIdx.x * 128;

    float acc2[2][4][4] = {};

    for (int h = 0; h < 4; h++) {
        if (h) __syncthreads();

        #pragma unroll
        for (int q = 0; q < 8; q++) {
            int idx = q * 256 + tid;
            int r = idx >> 4;
            int c8 = idx & 15;
            int gr = m0 + r;
            uint4 v = make_uint4(0u, 0u, 0u, 0u);
            if (gr < M) v = *(const uint4*)&A[(size_t)gr * 512 + h * 128 + c8 * 8];
            *(uint4*)&Asm[r * 68 + c8 * 4] = v;
        }
        #pragma unroll
        for (int q = 0; q < 4; q++) {
            int idx = q * 256 + tid;
            int r = idx >> 4;
            int c8 = idx & 15;
            uint4 vh = *(const uint4*)&B1hi[(size_t)(h * 64 + r) * 128 + c8 * 8];
            uint4 vl = *(const uint4*)&B1lo[(size_t)(h * 64 + r) * 128 + c8 * 8];
            *(uint4*)&B1h[r * 68 + c8 * 4] = vh;
            *(uint4*)&B1l[r * 68 + c8 * 4] = vl;
        }
        #pragma unroll
        for (int q = 0; q < 2; q++) {
            int idx = q * 256 + tid;
            int r = idx >> 3;
            int c8 = idx & 7;
            uint4 vh = *(const uint4*)&B2hi[(size_t)r * 256 + h * 64 + c8 * 8];
            uint4 vl = *(const uint4*)&B2lo[(size_t)r * 256 + h * 64 + c8 * 8];
            *(uint4*)&B2h[r * 36 + c8 * 4] = vh;
            *(uint4*)&B2l[r * 36 + c8 * 4] = vl;
        }
        __syncthreads();

        float acc1[2][4][4] = {};
        #pragma unroll
        for (int ks = 0; ks < 8; ks++) {
            const int kw = ks * 8 + (lane & 3);
            uint32_t ah[2][4], bh[4][2], bl[4][2];
            #pragma unroll
            for (int mt = 0; mt < 2; mt++) {
                int r0 = warp_m * 32 + mt * 16 + (lane >> 2);
                ah[mt][0] = Asm[r0 * 68 + kw];
                ah[mt][1] = Asm[(r0 + 8) * 68 + kw];
                ah[mt][2] = Asm[r0 * 68 + kw + 4];
                ah[mt][3] = Asm[(r0 + 8) * 68 + kw + 4];
            }
            #pragma unroll
            for (int nt = 0; nt < 4; nt++) {
                int n0 = warp_n * 32 + nt * 8 + (lane >> 2);
                bh[nt][0] = B1h[n0 * 68 + kw];
                bh[nt][1] = B1h[n0 * 68 + kw + 4];
                bl[nt][0] = B1l[n0 * 68 + kw];
                bl[nt][1] = B1l[n0 * 68 + kw + 4];
            }
            #pragma unroll
            for (int mt = 0; mt < 2; mt++)
                #pragma unroll
                for (int nt = 0; nt < 4; nt++) {
                    mma16816(acc1[mt][nt], ah[mt], bh[nt]);
                    mma16816(acc1[mt][nt], ah[mt], bl[nt]);
                }
        }

        #pragma unroll
        for (int mt = 0; mt < 2; mt++) {
            int r0 = warp_m * 32 + mt * 16 + (lane >> 2);
            #pragma unroll
            for (int nt = 0; nt < 4; nt++) {
                int c0 = warp_n * 32 + nt * 8 + (lane & 3) * 2;
                float b0 = __ldg(&bias1[h * 64 + c0]);
                float b1v = __ldg(&bias1[h * 64 + c0 + 1]);
                float* a4 = acc1[mt][nt];
                float v00 = a4[0] + b0, v01 = a4[1] + b1v;
                float v10 = a4[2] + b0, v11 = a4[3] + b1v;
                v00 = v00 > 0.f ? v00 : (__expf(v00) - 1.f);
                v01 = v01 > 0.f ? v01 : (__expf(v01) - 1.f);
                v10 = v10 > 0.f ? v10 : (__expf(v10) - 1.f);
                v11 = v11 > 0.f ? v11 : (__expf(v11) - 1.f);
                int w = warp_n * 16 + nt * 4 + (lane & 3);
                __nv_bfloat162 h0 = __floats2bfloat162_rn(v00, v01);
                __nv_bfloat162 h1 = __floats2bfloat162_rn(v10, v11);
                float2 f0 = __bfloat1622float2(h0);
                float2 f1 = __bfloat1622float2(h1);
                __nv_bfloat162 l0 = __floats2bfloat162_rn(v00 - f0.x, v01 - f0.y);
                __nv_bfloat162 l1 = __floats2bfloat162_rn(v10 - f1.x, v11 - f1.y);
                Oh[r0 * 36 + w] = bf2u(h0);
                Oh[(r0 + 8) * 36 + w] = bf2u(h1);
                Ol[r0 * 36 + w] = bf2u(l0);
                Ol[(r0 + 8) * 36 + w] = bf2u(l1);
            }
        }
        __syncthreads();

        #pragma unroll
        for (int ks = 0; ks < 4; ks++) {
            const int kw = ks * 8 + (lane & 3);
            uint32_t aoh[2][4], aol[2][4], bh[4][2], bl[4][2];
            #pragma unroll
            for (int mt = 0; mt < 2; mt++) {
                int r0 = warp_m * 32 + mt * 16 + (lane >> 2);
                aoh[mt][0] = Oh[r0 * 36 + kw];
                aoh[mt][1] = Oh[(r0 + 8) * 36 + kw];
                aoh[mt][2] = Oh[r0 * 36 + kw + 4];
                aoh[mt][3] = Oh[(r0 + 8) * 36 + kw + 4];
                aol[mt][0] = Ol[r0 * 36 + kw];
                aol[mt][1] = Ol[(r0 + 8) * 36 + kw];
                aol[mt][2] = Ol[r0 * 36 + kw + 4];
                aol[mt][3] = Ol[(r0 + 8) * 36 + kw + 4];
            }
            #pragma unroll
            for (int nt = 0; nt < 4; nt++) {
                int n0 = warp_n * 32 + nt * 8 + (lane >> 2);
                bh[nt][0] = B2h[n0 * 36 + kw];
                bh[nt][1] = B2h[n0 * 36 + kw + 4];
                bl[nt][0] = B2l[n0 * 36 + kw];
                bl[nt][1] = B2l[n0 * 36 + kw + 4];
            }
            #pragma unroll
            for (int mt = 0; mt < 2; mt++)
                #pragma unroll
                for (int nt = 0; nt < 4; nt++) {
                    mma16816(acc2[mt][nt], aoh[mt], bh[nt]);
                    mma16816(acc2[mt][nt], aoh[mt], bl[nt]);
                    mma16816(acc2[mt][nt], aol[mt], bh[nt]);
                }
        }
    }

    __syncthreads();
    if (tid < 128) { alpha_s[tid] = 0.0f; alpha_d[tid] = 0.0f; }
    __syncthreads();

    float sp[4] = {0.f, 0.f, 0.f, 0.f};
    float dp[4] = {0.f, 0.f, 0.f, 0.f};
    #pragma unroll
    for (int mt = 0; mt < 2; mt++) {
        int r0 = warp_m * 32 + mt * 16 + (lane >> 2);
        #pragma unroll
        for (int nt = 0; nt < 4; nt++) {
            int c0 = warp_n * 32 + nt * 8 + (lane & 3) * 2;
            float* a4 = acc2[mt][nt];
            int gr0 = m0 + r0, gr1 = gr0 + 8;
            if (gr0 < M)
                *(__nv_bfloat162*)&C[(size_t)gr0 * 64 + c0] = __floats2bfloat162_rn(a4[0], a4[1]);
            if (gr1 < M)
                *(__nv_bfloat162*)&C[(size_t)gr1 * 64 + c0] = __floats2bfloat162_rn(a4[2], a4[3]);
            float s0 = __ldg(&a_src[c0]);
            float s1 = __ldg(&a_src[c0 + 1]);
            float d0 = __ldg(&a_dst[c0]);
            float d1 = __ldg(&a_dst[c0 + 1]);
            sp[mt * 2]     += a4[0] * s0 + a4[1] * s1;
            sp[mt * 2 + 1] += a4[2] * s0 + a4[3] * s1;
            dp[mt * 2]     += a4[0] * d0 + a4[1] * d1;
            dp[mt * 2 + 1] += a4[2] * d0 + a4[3] * d1;
        }
    }
    #pragma unroll
    for (int i = 0; i < 4; i++) {
        sp[i] += __shfl_xor_sync(0xffffffffu, sp[i], 1);
        sp[i] += __shfl_xor_sync(0xffffffffu, sp[i], 2);
        dp[i] += __shfl_xor_sync(0xffffffffu, dp[i], 1);
        dp[i] += __shfl_xor_sync(0xffffffffu, dp[i], 2);
    }
    if ((lane & 3) == 0) {
        int r0 = warp_m * 32 + (lane >> 2);
        atomicAdd(&alpha_s[r0],      sp[0]);
        atomicAdd(&alpha_s[r0 + 8],  sp[1]);
        atomicAdd(&alpha_s[r0 + 16], sp[2]);
        atomicAdd(&alpha_s[r0 + 24], sp[3]);
        atomicAdd(&alpha_d[r0],      dp[0]);
        atomicAdd(&alpha_d[r0 + 8],  dp[1]);
        atomicAdd(&alpha_d[r0 + 16], dp[2]);
        atomicAdd(&alpha_d[r0 + 24], dp[3]);
    }
    __syncthreads();
    if (tid < 128) {
        int gr = m0 + tid;
        if (gr < M) {
            ASg[gr * 4] = alpha_s[tid];
            ADg[gr * 4] = alpha_d[tid];
        }
    }
}

// ---------------------------------------------------------------------------
// conv2 aggregation with in-warp lane-parallel edge weights + mean pool.
// ---------------------------------------------------------------------------
__global__ void agg2_pool_kernel(const int* __restrict__ rowptr,
                                 const int* __restrict__ ecol,
                                 const float* __restrict__ AS,
                                 const float* __restrict__ AD,
                                 const __nv_bfloat16* __restrict__ H2,
                                 const float* __restrict__ bias,
                                 const int* __restrict__ bt0,
                                 const int* __restrict__ bt1,
                                 float* __restrict__ POOL,
                                 float* __restrict__ CNT,
                                 int n) {
    const int g = blockIdx.y;
    const int* rp = rowptr + g * (NMAX + 1);
    const int* ec = ecol + (size_t)g * EMAX;
    const float* as = AS + (size_t)g * NMAX * 4;
    const __nv_bfloat16* H = H2 + (size_t)g * NMAX * 64;
    const int* batch = g ? bt1 : bt0;
    float* pool = POOL + g * GNUM * 64;
    float* cnt = CNT + g * GNUM;

    const int warp = (blockIdx.x * blockDim.x + threadIdx.x) >> 5;
    const int lane = threadIdx.x & 31;
    if (warp >= n) return;
    const int d = warp;
    const int beg = rp[d];
    const int end = rp[d + 1];

    float ad_d = AD[(size_t)g * NMAX * 4 + d * 4];
    float den = __expf(leaky(as[d * 4] + ad_d));
    float2 hv = __bfloat1622float2(*(const __nv_bfloat162*)&H[(size_t)d * 64 + lane * 2]);
    float a0 = den * hv.x, a1 = den * hv.y;

    for (int jb = beg; jb < end; jb += 32) {
        int m = end - jb;
        if (m > 32) m = 32;
        int s = 0;
        float u = 0.0f;
        if (lane < m) {
            s = ec[jb + lane];
            u = __expf(leaky(as[s * 4] + ad_d));
        }
        for (int k = 0; k < m; k++) {
            int ss = __shfl_sync(0xffffffffu, s, k);
            float uk = __shfl_sync(0xffffffffu, u, k);
            den += uk;
            float2 hs = __bfloat1622float2(*(const __nv_bfloat162*)&H[(size_t)ss * 64 + lane * 2]);
            a0 += uk * hs.x;
            a1 += uk * hs.y;
        }
    }
    float inv = 1.0f / (den + 1e-16f);
    float v0 = a0 * inv + bias[lane * 2];
    float v1 = a1 * inv + bias[lane * 2 + 1];
    v0 = v0 > 0.0f ? v0 : (__expf(v0) - 1.0f);
    v1 = v1 > 0.0f ? v1 : (__expf(v1) - 1.0f);
    int grp = batch[d];
    atomicAdd(&pool[grp * 64 + lane * 2], v0);
    atomicAdd(&pool[grp * 64 + lane * 2 + 1], v1);
    if (lane == 0) atomicAdd(&cnt[grp], 1.0f);
}

__global__ void final_write_kernel(const float* __restrict__ POOL,
                                   const float* __restrict__ CNT,
                                   float* __restrict__ out) {
    int i = blockIdx.x * blockDim.x + threadIdx.x;
    if (i >= 2 * GNUM * 64) return;
    float c = CNT[i >> 6];
    out[i] = POOL[i] / fmaxf(c, 1.0f);
}

// ---------------------------------------------------------------------------
// Launch
// ---------------------------------------------------------------------------
extern "C" void kernel_launch(void* const* d_in, const int* in_sizes, int n_in,
                              void* d_out, int out_size) {
    const float* x1  = (const float*)d_in[0];
    const int*   ei1 = (const int*)d_in[1];
    const int*   bt1 = (const int*)d_in[2];
    const float* x2  = (const float*)d_in[3];
    const int*   ei2 = (const int*)d_in[4];
    const int*   bt2 = (const int*)d_in[5];
    const float* W1  = (const float*)d_in[6];
    const float* as1 = (const float*)d_in[7];
    const float* ad1 = (const float*)d_in[8];
    const float* b1  = (const float*)d_in[9];
    const float* W2  = (const float*)d_in[10];
    const float* as2 = (const float*)d_in[11];
    const float* ad2 = (const float*)d_in[12];
    const float* b2  = (const float*)d_in[13];

    const int n = in_sizes[0] / 128;
    const int e = in_sizes[1] / 2;
    const int nb = cdiv(n, SCAN_CHUNK);

    float *AS, *AD, *POOL, *CNT, *P1S, *P1D, *U1;
    int *DEG, *ROWPTR, *CUR, *ECOL;
    unsigned long long* LOOK;
    __nv_bfloat16 *X16, *AGG, *H2, *W1TH, *W1TL, *W2TH, *W2TL;
    cudaGetSymbolAddress((void**)&X16,    g_X16);
    cudaGetSymbolAddress((void**)&AGG,    g_AGG);
    cudaGetSymbolAddress((void**)&H2,     g_H2);
    cudaGetSymbolAddress((void**)&AS,     g_AS);
    cudaGetSymbolAddress((void**)&AD,     g_AD);
    cudaGetSymbolAddress((void**)&DEG,    g_DEG);
    cudaGetSymbolAddress((void**)&ROWPTR, g_ROWPTR);
    cudaGetSymbolAddress((void**)&CUR,    g_CUR);
    cudaGetSymbolAddress((void**)&ECOL,   g_ECOL);
    cudaGetSymbolAddress((void**)&U1,     g_U1);
    cudaGetSymbolAddress((void**)&LOOK,   g_LOOK);
    cudaGetSymbolAddress((void**)&POOL,   g_POOL);
    cudaGetSymbolAddress((void**)&CNT,    g_CNT);
    cudaGetSymbolAddress((void**)&P1S,    g_P1S);
    cudaGetSymbolAddress((void**)&P1D,    g_P1D);
    cudaGetSymbolAddress((void**)&W1TH,   g_W1T_HI);
    cudaGetSymbolAddress((void**)&W1TL,   g_W1T_LO);
    cudaGetSymbolAddress((void**)&W2TH,   g_W2T_HI);
    cudaGetSymbolAddress((void**)&W2TL,   g_W2T_LO);

    cudaFuncSetAttribute(gemm_fused_kernel,
                         cudaFuncAttributeMaxDynamicSharedMemorySize, SMF_TOTAL);

    setup_kernel<<<cdiv(SETUP_TOTAL, 256), 256>>>(W1, W2, as1, ad1,
                                                  W1TH, W1TL, W2TH, W2TL,
                                                  P1S, P1D, POOL, CNT, DEG, LOOK);
    {
        int gx = cdiv(n, 8);
        if (gx < cdiv(e, 256)) gx = cdiv(e, 256);
        dim3 gs(gx, 4);
        stage1_kernel<<<gs, 256>>>(x1, x2, P1S, P1D, AS, AD, X16,
                                   ei1, ei2, DEG, n, e);
    }
    {
        dim3 gs2(nb, 2);
        scan_lookback_kernel<<<gs2, 256>>>(DEG, ROWPTR, CUR, LOOK, n, nb);
    }
    {
        dim3 ge2(cdiv(e, 256), 2);
        fill_kernel<<<ge2, 256>>>(ei1, ei2, CUR, ECOL, AS, AD, U1, e);
    }
    {
        dim3 ga(cdiv(n, 8), 2);
        agg_x_kernel<<<ga, 256>>>(ROWPTR, ECOL, U1, AS, AD, X16, AGG, n);
    }
    {
        dim3 gg(cdiv(n, 128), 2);
        gemm_fused_kernel<<<gg, 256, SMF_TOTAL>>>(AGG, W1TH, W1TL, b1,
                                                  W2TH, W2TL, H2,
                                                  as2, ad2, AS, AD, n);
    }
    {
        dim3 ga(cdiv(n, 8), 2);
        agg2_pool_kernel<<<ga, 256>>>(ROWPTR, ECOL, AS, AD, H2, b2,
                                      bt1, bt2, POOL, CNT, n);
    }
    final_write_kernel<<<cdiv(2 * GNUM * 64, 256), 256>>>(POOL, CNT, (float*)d_out);
}

// round 12
// speedup vs baseline: 1.1964x; 1.0422x over previous
#include <cuda_runtime.h>
#include <cuda_bf16.h>
#include <cstdint>

// ---------------------------------------------------------------------------
// GATGraphSimilarity: Siamese 2-layer GAT (heads=4 then 1) + mean pool.
// Round 12: fill_kernel reduced to pure CSR scatter (was L2-bound at 40us);
// conv1 edge weights computed in agg_x via smem-staged lane-parallel exps
// (U1 buffer deleted). Everything else as round 11.
// ---------------------------------------------------------------------------

#define NMAX 50000
#define EMAX 800000
#define GNUM 64
#define NEG_SLOPE 0.2f
#define SCAN_CHUNK 4096
#define SCAN_NB ((NMAX + SCAN_CHUNK - 1) / SCAN_CHUNK)

__device__ __nv_bfloat16 g_X16[2][(size_t)NMAX * 128];
__device__ __nv_bfloat16 g_AGG[2][(size_t)NMAX * 512];
__device__ __nv_bfloat16 g_H2 [2][(size_t)NMAX * 64];
__device__ float g_AS  [2][NMAX * 4];
__device__ float g_AD  [2][NMAX * 4];
__device__ int   g_DEG [2][NMAX];
__device__ int   g_ROWPTR[2][NMAX + 1];
__device__ int   g_CUR [2][NMAX];
__device__ int   g_ECOL[2][EMAX];
__device__ unsigned long long g_LOOK[2][SCAN_NB];
__device__ float g_POOL[2 * GNUM * 64];
__device__ float g_CNT [2 * GNUM];
__device__ float g_P1S [128 * 4];
__device__ float g_P1D [128 * 4];
__device__ __nv_bfloat16 g_W1T_HI[256 * 128];
__device__ __nv_bfloat16 g_W1T_LO[256 * 128];
__device__ __nv_bfloat16 g_W2T_HI[64 * 256];
__device__ __nv_bfloat16 g_W2T_LO[64 * 256];

static inline int cdiv(int a, int b) { return (a + b - 1) / b; }

__device__ __forceinline__ float leaky(float v) {
    return v > 0.0f ? v : NEG_SLOPE * v;
}

__device__ __forceinline__ uint32_t bf2u(__nv_bfloat162 v) {
    return *reinterpret_cast<uint32_t*>(&v);
}

__device__ __forceinline__ void mma16816(float* d, const uint32_t* a, const uint32_t* b) {
    asm volatile(
        "mma.sync.aligned.m16n8k16.row.col.f32.bf16.bf16.f32 "
        "{%0,%1,%2,%3}, {%4,%5,%6,%7}, {%8,%9}, {%0,%1,%2,%3};"
        : "+f"(d[0]), "+f"(d[1]), "+f"(d[2]), "+f"(d[3])
        : "r"(a[0]), "r"(a[1]), "r"(a[2]), "r"(a[3]), "r"(b[0]), "r"(b[1]));
}

// ---------------------------------------------------------------------------
// Setup
// ---------------------------------------------------------------------------
#define SEG1 (256 * 128)
#define SEG2 (64 * 256)
#define SEG3 1024
#define SEG4 (2 * GNUM * 64 + 2 * GNUM)
#define SEG5 (2 * NMAX)
#define SEG6 (2 * SCAN_NB)
#define SETUP_TOTAL (SEG1 + SEG2 + SEG3 + SEG4 + SEG5 + SEG6)

__global__ void setup_kernel(const float* __restrict__ W1,
                             const float* __restrict__ W2,
                             const float* __restrict__ as1,
                             const float* __restrict__ ad1,
                             __nv_bfloat16* __restrict__ W1TH,
                             __nv_bfloat16* __restrict__ W1TL,
                             __nv_bfloat16* __restrict__ W2TH,
                             __nv_bfloat16* __restrict__ W2TL,
                             float* __restrict__ P1S,
                             float* __restrict__ P1D,
                             float* __restrict__ POOL,
                             float* __restrict__ CNT,
                             int* __restrict__ DEG,
                             unsigned long long* __restrict__ LOOK) {
    int i = blockIdx.x * blockDim.x + threadIdx.x;
    if (i < SEG1) {
        int n = i / 128, k = i % 128;
        float v = W1[(size_t)k * 256 + n];
        __nv_bfloat16 h = __float2bfloat16(v);
        W1TH[i] = h;
        W1TL[i] = __float2bfloat16(v - __bfloat162float(h));
        return;
    }
    i -= SEG1;
    if (i < SEG2) {
        int n = i / 256, k = i % 256;
        float v = W2[(size_t)k * 64 + n];
        __nv_bfloat16 h = __float2bfloat16(v);
        W2TH[i] = h;
        W2TL[i] = __float2bfloat16(v - __bfloat162float(h));
        return;
    }
    i -= SEG2;
    if (i < SEG3) {
        int is_dst = i >> 9;
        int o = i & 511;
        int k = o >> 2, h = o & 3;
        const float* a = is_dst ? ad1 : as1;
        float s = 0.0f;
        #pragma unroll 8
        for (int d = 0; d < 64; d++)
            s += W1[(size_t)k * 256 + h * 64 + d] * a[h * 64 + d];
        (is_dst ? P1D : P1S)[k * 4 + h] = s;
        return;
    }
    i -= SEG3;
    if (i < 2 * GNUM * 64) { POOL[i] = 0.0f; return; }
    i -= 2 * GNUM * 64;
    if (i < 2 * GNUM) { CNT[i] = 0.0f; return; }
    i -= 2 * GNUM;
    if (i < SEG5) { DEG[i] = 0; return; }
    i -= SEG5;
    if (i < SEG6) LOOK[i] = 0ULL;
}

// ---------------------------------------------------------------------------
// Stage1: alphas+X16 (parts 0,1) and degree histogram (parts 2,3).
// ---------------------------------------------------------------------------
__global__ void stage1_kernel(const float* __restrict__ x0,
                              const float* __restrict__ x1,
                              const float* __restrict__ P1S,
                              const float* __restrict__ P1D,
                              float* __restrict__ AS,
                              float* __restrict__ AD,
                              __nv_bfloat16* __restrict__ X16,
                              const int* __restrict__ ei0,
                              const int* __restrict__ ei1,
                              int* __restrict__ deg,
                              int n, int E) {
    const int part = blockIdx.y;
    if (part >= 2) {
        int g = part - 2;
        const int* ei = g ? ei1 : ei0;
        int i = blockIdx.x * blockDim.x + threadIdx.x;
        if (i < E) atomicAdd(&deg[g * NMAX + ei[E + i]], 1);
        return;
    }
    const int g = part;
    const float* x = g ? x1 : x0;
    const int warp = (blockIdx.x * blockDim.x + threadIdx.x) >> 5;
    const int lane = threadIdx.x & 31;
    if (warp >= n) return;
    float4 xv = *(const float4*)&x[(size_t)warp * 128 + lane * 4];
    {
        __nv_bfloat162 p0 = __floats2bfloat162_rn(xv.x, xv.y);
        __nv_bfloat162 p1 = __floats2bfloat162_rn(xv.z, xv.w);
        uint2 u = make_uint2(bf2u(p0), bf2u(p1));
        *(uint2*)&X16[(size_t)g * NMAX * 128 + (size_t)warp * 128 + lane * 4] = u;
    }
    float s[4] = {0.f, 0.f, 0.f, 0.f};
    float d[4] = {0.f, 0.f, 0.f, 0.f};
    const float* xp = (const float*)&xv;
    #pragma unroll
    for (int j = 0; j < 4; j++) {
        float xk = xp[j];
        float4 ps = *(const float4*)&P1S[(lane * 4 + j) * 4];
        float4 pd = *(const float4*)&P1D[(lane * 4 + j) * 4];
        s[0] += xk * ps.x; s[1] += xk * ps.y; s[2] += xk * ps.z; s[3] += xk * ps.w;
        d[0] += xk * pd.x; d[1] += xk * pd.y; d[2] += xk * pd.z; d[3] += xk * pd.w;
    }
    #pragma unroll
    for (int off = 16; off >= 1; off >>= 1) {
        #pragma unroll
        for (int h = 0; h < 4; h++) {
            s[h] += __shfl_xor_sync(0xffffffffu, s[h], off);
            d[h] += __shfl_xor_sync(0xffffffffu, d[h], off);
        }
    }
    if (lane == 0) {
        *(float4*)&AS[(size_t)g * NMAX * 4 + warp * 4] = make_float4(s[0], s[1], s[2], s[3]);
        *(float4*)&AD[(size_t)g * NMAX * 4 + warp * 4] = make_float4(d[0], d[1], d[2], d[3]);
    }
}

// ---------------------------------------------------------------------------
// Decoupled-lookback scan (unchanged)
// ---------------------------------------------------------------------------
__global__ void scan_lookback_kernel(const int* __restrict__ deg,
                                     int* __restrict__ rowptr,
                                     int* __restrict__ cur,
                                     unsigned long long* __restrict__ LOOK,
                                     int n, int nb) {
    __shared__ int thr[256];
    __shared__ int sh_P;
    const int g = blockIdx.y;
    const int b = blockIdx.x;
    const int t = threadIdx.x;
    const int base = b * SCAN_CHUNK + t * 16;
    const int* dg = deg + g * NMAX;
    int* rp = rowptr + g * (NMAX + 1);
    int* cu = cur + g * NMAX;
    unsigned long long* look = LOOK + g * SCAN_NB;

    int s = 0;
    int dloc[16];
    #pragma unroll
    for (int q = 0; q < 16; q++) {
        int i = base + q;
        dloc[q] = (i < n) ? dg[i] : 0;
        s += dloc[q];
    }
    thr[t] = s;
    __syncthreads();
    #pragma unroll
    for (int off = 1; off < 256; off <<= 1) {
        int v = (t >= off) ? thr[t - off] : 0;
        __syncthreads();
        thr[t] += v;
        __syncthreads();
    }
    const int total = thr[255];

    if (t == 0) {
        int P = 0;
        if (b == 0) {
            atomicExch(&look[0], (2ULL << 32) | (unsigned int)total);
        } else {
            atomicExch(&look[b], (1ULL << 32) | (unsigned int)total);
            int i = b - 1;
            while (true) {
                unsigned long long w;
                do { w = atomicAdd(&look[i], 0ULL); } while ((w >> 32) == 0ULL);
                int v = (int)(w & 0xffffffffULL);
                P += v;
                if ((w >> 32) == 2ULL) break;
                i--;
            }
            atomicExch(&look[b], (2ULL << 32) | (unsigned int)(P + total));
        }
        sh_P = P;
    }
    __syncthreads();

    int offset = sh_P + ((t == 0) ? 0 : thr[t - 1]);
    #pragma unroll
    for (int q = 0; q < 16; q++) {
        int i = base + q;
        if (i < n) {
            rp[i] = offset;
            cu[i] = offset;
            offset += dloc[q];
        }
    }
    if (b == nb - 1 && t == 255) rp[n] = offset;
}

// fill CSR: pure scatter (weights computed later, in-warp)
__global__ void fill_kernel(const int* __restrict__ ei0, const int* __restrict__ ei1,
                            int* __restrict__ cur,
                            int* __restrict__ ecol, int E) {
    int g = blockIdx.y;
    const int* ei = g ? ei1 : ei0;
    int i = blockIdx.x * blockDim.x + threadIdx.x;
    if (i >= E) return;
    int s = ei[i];
    int d = ei[E + i];
    int slot = atomicAdd(&cur[g * NMAX + d], 1);
    ecol[(size_t)g * EMAX + slot] = s;
}

// ---------------------------------------------------------------------------
// conv1 aggregation: smem-staged lane-parallel edge weights, then gather+FMA.
// ---------------------------------------------------------------------------
__global__ void agg_x_kernel(const int* __restrict__ rowptr,
                             const int* __restrict__ ecol,
                             const float* __restrict__ AS,
                             const float* __restrict__ AD,
                             const __nv_bfloat16* __restrict__ X16,
                             __nv_bfloat16* __restrict__ AGG,
                             int n) {
    __shared__ int    sh_s[8][32];
    __shared__ float4 sh_u[8][32];

    const int g = blockIdx.y;
    const int* rp = rowptr + g * (NMAX + 1);
    const int* ec = ecol + (size_t)g * EMAX;
    const float* as = AS + (size_t)g * NMAX * 4;
    const __nv_bfloat16* X = X16 + (size_t)g * NMAX * 128;
    __nv_bfloat16* agg = AGG + (size_t)g * NMAX * 512;

    const int w = threadIdx.x >> 5;
    const int warp = (blockIdx.x * blockDim.x + threadIdx.x) >> 5;
    const int lane = threadIdx.x & 31;
    if (warp >= n) return;
    const int d = warp;
    const int beg = rp[d];
    const int end = rp[d + 1];

    float4 asv = *(const float4*)&as[d * 4];
    float4 adv = *(const float4*)&AD[(size_t)g * NMAX * 4 + d * 4];
    float den[4];
    den[0] = __expf(leaky(asv.x + adv.x));
    den[1] = __expf(leaky(asv.y + adv.y));
    den[2] = __expf(leaky(asv.z + adv.z));
    den[3] = __expf(leaky(asv.w + adv.w));

    uint2 ux = *(const uint2*)&X[(size_t)d * 128 + lane * 4];
    float2 xd01 = __bfloat1622float2(*(__nv_bfloat162*)&ux.x);
    float2 xd23 = __bfloat1622float2(*(__nv_bfloat162*)&ux.y);

    float acc[4][4];
    #pragma unroll
    for (int h = 0; h < 4; h++) {
        acc[h][0] = den[h] * xd01.x; acc[h][1] = den[h] * xd01.y;
        acc[h][2] = den[h] * xd23.x; acc[h][3] = den[h] * xd23.y;
    }

    for (int jb = beg; jb < end; jb += 32) {
        int m = end - jb;
        if (m > 32) m = 32;
        if (lane < m) {
            int s = ec[jb + lane];
            float4 a = *(const float4*)&as[s * 4];
            float4 u;
            u.x = __expf(leaky(a.x + adv.x));
            u.y = __expf(leaky(a.y + adv.y));
            u.z = __expf(leaky(a.z + adv.z));
            u.w = __expf(leaky(a.w + adv.w));
            sh_s[w][lane] = s;
            sh_u[w][lane] = u;
        }
        __syncwarp();
        #pragma unroll 2
        for (int k = 0; k < m; k++) {
            int ss = sh_s[w][k];
            float4 u = sh_u[w][k];
            den[0] += u.x; den[1] += u.y; den[2] += u.z; den[3] += u.w;
            uint2 q = *(const uint2*)&X[(size_t)ss * 128 + lane * 4];
            float2 f01 = __bfloat1622float2(*(__nv_bfloat162*)&q.x);
            float2 f23 = __bfloat1622float2(*(__nv_bfloat162*)&q.y);
            acc[0][0] += u.x * f01.x; acc[0][1] += u.x * f01.y;
            acc[0][2] += u.x * f23.x; acc[0][3] += u.x * f23.y;
            acc[1][0] += u.y * f01.x; acc[1][1] += u.y * f01.y;
            acc[1][2] += u.y * f23.x; acc[1][3] += u.y * f23.y;
            acc[2][0] += u.z * f01.x; acc[2][1] += u.z * f01.y;
            acc[2][2] += u.z * f23.x; acc[2][3] += u.z * f23.y;
            acc[3][0] += u.w * f01.x; acc[3][1] += u.w * f01.y;
            acc[3][2] += u.w * f23.x; acc[3][3] += u.w * f23.y;
        }
        __syncwarp();
    }

    // den[h] is identical across lanes (each lane summed all staged u's)
    #pragma unroll
    for (int h = 0; h < 4; h++) {
        float inv = 1.0f / (den[h] + 1e-16f);
        __nv_bfloat162 q0 = __floats2bfloat162_rn(acc[h][0] * inv, acc[h][1] * inv);
        __nv_bfloat162 q1 = __floats2bfloat162_rn(acc[h][2] * inv, acc[h][3] * inv);
        uint2 u = make_uint2(bf2u(q0), bf2u(q1));
        *(uint2*)&agg[(size_t)d * 512 + h * 128 + lane * 4] = u;
    }
}

// ---------------------------------------------------------------------------
// FUSED GEMM (unchanged)
// ---------------------------------------------------------------------------
#define SMF_A     0
#define SMF_B1H   34816
#define SMF_B1L   52224
#define SMF_OH    69632
#define SMF_OL    88064
#define SMF_B2H   106496
#define SMF_B2L   115712
#define SMF_ALPHA 124928
#define SMF_TOTAL 125952

__global__ __launch_bounds__(256, 1)
void gemm_fused_kernel(const __nv_bfloat16* __restrict__ AGG,
                       const __nv_bfloat16* __restrict__ B1hi,
                       const __nv_bfloat16* __restrict__ B1lo,
                       const float* __restrict__ bias1,
                       const __nv_bfloat16* __restrict__ B2hi,
                       const __nv_bfloat16* __restrict__ B2lo,
                       __nv_bfloat16* __restrict__ H2,
                       const float* __restrict__ a_src,
                       const float* __restrict__ a_dst,
                       float* __restrict__ AS,
                       float* __restrict__ AD,
                       int M) {
    extern __shared__ char smem[];
    uint32_t* Asm = (uint32_t*)(smem + SMF_A);
    uint32_t* B1h = (uint32_t*)(smem + SMF_B1H);
    uint32_t* B1l = (uint32_t*)(smem + SMF_B1L);
    uint32_t* Oh  = (uint32_t*)(smem + SMF_OH);
    uint32_t* Ol  = (uint32_t*)(smem + SMF_OL);
    uint32_t* B2h = (uint32_t*)(smem + SMF_B2H);
    uint32_t* B2l = (uint32_t*)(smem + SMF_B2L);
    float* alpha_s = (float*)(smem + SMF_ALPHA);
    float* alpha_d = alpha_s + 128;

    const int g = blockIdx.y;
    const __nv_bfloat16* A = AGG + (size_t)g * NMAX * 512;
    __nv_bfloat16* C = H2 + (size_t)g * NMAX * 64;
    float* ASg = AS + (size_t)g * NMAX * 4;
    float* ADg = AD + (size_t)g * NMAX * 4;
    const int tid = threadIdx.x;
    const int lane = tid & 31;
    const int wid = tid >> 5;
    const int warp_m = wid & 3;
    const int warp_n = wid >> 2;
    const int m0 = blockIdx.x * 128;

    float acc2[2][4][4] = {};

    for (int h = 0; h < 4; h++) {
        if (h) __syncthreads();

        #pragma unroll
        for (int q = 0; q < 8; q++) {
            int idx = q * 256 + tid;
            int r = idx >> 4;
            int c8 = idx & 15;
            int gr = m0 + r;
            uint4 v = make_uint4(0u, 0u, 0u, 0u);
            if (gr < M) v = *(const uint4*)&A[(size_t)gr * 512 + h * 128 + c8 * 8];
            *(uint4*)&Asm[r * 68 + c8 * 4] = v;
        }
        #pragma unroll
        for (int q = 0; q < 4; q++) {
            int idx = q * 256 + tid;
            int r = idx >> 4;
            int c8 = idx & 15;
            uint4 vh = *(const uint4*)&B1hi[(size_t)(h * 64 + r) * 128 + c8 * 8];
            uint4 vl = *(const uint4*)&B1lo[(size_t)(h * 64 + r) * 128 + c8 * 8];
            *(uint4*)&B1h[r * 68 + c8 * 4] = vh;
            *(uint4*)&B1l[r * 68 + c8 * 4] = vl;
        }
        #pragma unroll
        for (int q = 0; q < 2; q++) {
            int idx = q * 256 + tid;
            int r = idx >> 3;
            int c8 = idx & 7;
            uint4 vh = *(const uint4*)&B2hi[(size_t)r * 256 + h * 64 + c8 * 8];
            uint4 vl = *(const uint4*)&B2lo[(size_t)r * 256 + h * 64 + c8 * 8];
            *(uint4*)&B2h[r * 36 + c8 * 4] = vh;
            *(uint4*)&B2l[r * 36 + c8 * 4] = vl;
        }
        __syncthreads();

        float acc1[2][4][4] = {};
        #pragma unroll
        for (int ks = 0; ks < 8; ks++) {
            const int kw = ks * 8 + (lane & 3);
            uint32_t ah[2][4], bh[4][2], bl[4][2];
            #pragma unroll
            for (int mt = 0; mt < 2; mt++) {
                int r0 = warp_m * 32 + mt * 16 + (lane >> 2);
                ah[mt][0] = Asm[r0 * 68 + kw];
                ah[mt][1] = Asm[(r0 + 8) * 68 + kw];
                ah[mt][2] = Asm[r0 * 68 + kw + 4];
                ah[mt][3] = Asm[(r0 + 8) * 68 + kw + 4];
            }
            #pragma unroll
            for (int nt = 0; nt < 4; nt++) {
                int n0 = warp_n * 32 + nt * 8 + (lane >> 2);
                bh[nt][0] = B1h[n0 * 68 + kw];
                bh[nt][1] = B1h[n0 * 68 + kw + 4];
                bl[nt][0] = B1l[n0 * 68 + kw];
                bl[nt][1] = B1l[n0 * 68 + kw + 4];
            }
            #pragma unroll
            for (int mt = 0; mt < 2; mt++)
                #pragma unroll
                for (int nt = 0; nt < 4; nt++) {
                    mma16816(acc1[mt][nt], ah[mt], bh[nt]);
                    mma16816(acc1[mt][nt], ah[mt], bl[nt]);
                }
        }

        #pragma unroll
        for (int mt = 0; mt < 2; mt++) {
            int r0 = warp_m * 32 + mt * 16 + (lane >> 2);
            #pragma unroll
            for (int nt = 0; nt < 4; nt++) {
                int c0 = warp_n * 32 + nt * 8 + (lane & 3) * 2;
                float b0 = __ldg(&bias1[h * 64 + c0]);
                float b1v = __ldg(&bias1[h * 64 + c0 + 1]);
                float* a4 = acc1[mt][nt];
                float v00 = a4[0] + b0, v01 = a4[1] + b1v;
                float v10 = a4[2] + b0, v11 = a4[3] + b1v;
                v00 = v00 > 0.f ? v00 : (__expf(v00) - 1.f);
                v01 = v01 > 0.f ? v01 : (__expf(v01) - 1.f);
                v10 = v10 > 0.f ? v10 : (__expf(v10) - 1.f);
                v11 = v11 > 0.f ? v11 : (__expf(v11) - 1.f);
                int w = warp_n * 16 + nt * 4 + (lane & 3);
                __nv_bfloat162 h0 = __floats2bfloat162_rn(v00, v01);
                __nv_bfloat162 h1 = __floats2bfloat162_rn(v10, v11);
                float2 f0 = __bfloat1622float2(h0);
                float2 f1 = __bfloat1622float2(h1);
                __nv_bfloat162 l0 = __floats2bfloat162_rn(v00 - f0.x, v01 - f0.y);
                __nv_bfloat162 l1 = __floats2bfloat162_rn(v10 - f1.x, v11 - f1.y);
                Oh[r0 * 36 + w] = bf2u(h0);
                Oh[(r0 + 8) * 36 + w] = bf2u(h1);
                Ol[r0 * 36 + w] = bf2u(l0);
                Ol[(r0 + 8) * 36 + w] = bf2u(l1);
            }
        }
        __syncthreads();

        #pragma unroll
        for (int ks = 0; ks < 4; ks++) {
            const int kw = ks * 8 + (lane & 3);
            uint32_t aoh[2][4], aol[2][4], bh[4][2], bl[4][2];
            #pragma unroll
            for (int mt = 0; mt < 2; mt++) {
                int r0 = warp_m * 32 + mt * 16 + (lane >> 2);
                aoh[mt][0] = Oh[r0 * 36 + kw];
                aoh[mt][1] = Oh[(r0 + 8) * 36 + kw];
                aoh[mt][2] = Oh[r0 * 36 + kw + 4];
                aoh[mt][3] = Oh[(r0 + 8) * 36 + kw + 4];
                aol[mt][0] = Ol[r0 * 36 + kw];
                aol[mt][1] = Ol[(r0 + 8) * 36 + kw];
                aol[mt][2] = Ol[r0 * 36 + kw + 4];
                aol[mt][3] = Ol[(r0 + 8) * 36 + kw + 4];
            }
            #pragma unroll
            for (int nt = 0; nt < 4; nt++) {
                int n0 = warp_n * 32 + nt * 8 + (lane >> 2);
                bh[nt][0] = B2h[n0 * 36 + kw];
                bh[nt][1] = B2h[n0 * 36 + kw + 4];
                bl[nt][0] = B2l[n0 * 36 + kw];
                bl[nt][1] = B2l[n0 * 36 + kw + 4];
            }
            #pragma unroll
            for (int mt = 0; mt < 2; mt++)
                #pragma unroll
                for (int nt = 0; nt < 4; nt++) {
                    mma16816(acc2[mt][nt], aoh[mt], bh[nt]);
                    mma16816(acc2[mt][nt], aoh[mt], bl[nt]);
                    mma16816(acc2[mt][nt], aol[mt], bh[nt]);
                }
        }
    }

    __syncthreads();
    if (tid < 128) { alpha_s[tid] = 0.0f; alpha_d[tid] = 0.0f; }
    __syncthreads();

    float sp[4] = {0.f, 0.f, 0.f, 0.f};
    float dp[4] = {0.f, 0.f, 0.f, 0.f};
    #pragma unroll
    for (int mt = 0; mt < 2; mt++) {
        int r0 = warp_m * 32 + mt * 16 + (lane >> 2);
        #pragma unroll
        for (int nt = 0; nt < 4; nt++) {
            int c0 = warp_n * 32 + nt * 8 + (lane & 3) * 2;
            float* a4 = acc2[mt][nt];
            int gr0 = m0 + r0, gr1 = gr0 + 8;
            if (gr0 < M)
                *(__nv_bfloat162*)&C[(size_t)gr0 * 64 + c0] = __floats2bfloat162_rn(a4[0], a4[1]);
            if (gr1 < M)
                *(__nv_bfloat162*)&C[(size_t)gr1 * 64 + c0] = __floats2bfloat162_rn(a4[2], a4[3]);
            float s0 = __ldg(&a_src[c0]);
            float s1 = __ldg(&a_src[c0 + 1]);
            float d0 = __ldg(&a_dst[c0]);
            float d1 = __ldg(&a_dst[c0 + 1]);
            sp[mt * 2]     += a4[0] * s0 + a4[1] * s1;
            sp[mt * 2 + 1] += a4[2] * s0 + a4[3] * s1;
            dp[mt * 2]     += a4[0] * d0 + a4[1] * d1;
            dp[mt * 2 + 1] += a4[2] * d0 + a4[3] * d1;
        }
    }
    #pragma unroll
    for (int i = 0; i < 4; i++) {
        sp[i] += __shfl_xor_sync(0xffffffffu, sp[i], 1);
        sp[i] += __shfl_xor_sync(0xffffffffu, sp[i], 2);
        dp[i] += __shfl_xor_sync(0xffffffffu, dp[i], 1);
        dp[i] += __shfl_xor_sync(0xffffffffu, dp[i], 2);
    }
    if ((lane & 3) == 0) {
        int r0 = warp_m * 32 + (lane >> 2);
        atomicAdd(&alpha_s[r0],      sp[0]);
        atomicAdd(&alpha_s[r0 + 8],  sp[1]);
        atomicAdd(&alpha_s[r0 + 16], sp[2]);
        atomicAdd(&alpha_s[r0 + 24], sp[3]);
        atomicAdd(&alpha_d[r0],      dp[0]);
        atomicAdd(&alpha_d[r0 + 8],  dp[1]);
        atomicAdd(&alpha_d[r0 + 16], dp[2]);
        atomicAdd(&alpha_d[r0 + 24], dp[3]);
    }
    __syncthreads();
    if (tid < 128) {
        int gr = m0 + tid;
        if (gr < M) {
            ASg[gr * 4] = alpha_s[tid];
            ADg[gr * 4] = alpha_d[tid];
        }
    }
}

// ---------------------------------------------------------------------------
// conv2 aggregation with in-warp lane-parallel edge weights + mean pool.
// ---------------------------------------------------------------------------
__global__ void agg2_pool_kernel(const int* __restrict__ rowptr,
                                 const int* __restrict__ ecol,
                                 const float* __restrict__ AS,
                                 const float* __restrict__ AD,
                                 const __nv_bfloat16* __restrict__ H2,
                                 const float* __restrict__ bias,
                                 const int* __restrict__ bt0,
                                 const int* __restrict__ bt1,
                                 float* __restrict__ POOL,
                                 float* __restrict__ CNT,
                                 int n) {
    const int g = blockIdx.y;
    const int* rp = rowptr + g * (NMAX + 1);
    const int* ec = ecol + (size_t)g * EMAX;
    const float* as = AS + (size_t)g * NMAX * 4;
    const __nv_bfloat16* H = H2 + (size_t)g * NMAX * 64;
    const int* batch = g ? bt1 : bt0;
    float* pool = POOL + g * GNUM * 64;
    float* cnt = CNT + g * GNUM;

    const int warp = (blockIdx.x * blockDim.x + threadIdx.x) >> 5;
    const int lane = threadIdx.x & 31;
    if (warp >= n) return;
    const int d = warp;
    const int beg = rp[d];
    const int end = rp[d + 1];

    float ad_d = AD[(size_t)g * NMAX * 4 + d * 4];
    float den = __expf(leaky(as[d * 4] + ad_d));
    float2 hv = __bfloat1622float2(*(const __nv_bfloat162*)&H[(size_t)d * 64 + lane * 2]);
    float a0 = den * hv.x, a1 = den * hv.y;

    for (int jb = beg; jb < end; jb += 32) {
        int m = end - jb;
        if (m > 32) m = 32;
        int s = 0;
        float u = 0.0f;
        if (lane < m) {
            s = ec[jb + lane];
            u = __expf(leaky(as[s * 4] + ad_d));
        }
        for (int k = 0; k < m; k++) {
            int ss = __shfl_sync(0xffffffffu, s, k);
            float uk = __shfl_sync(0xffffffffu, u, k);
            den += uk;
            float2 hs = __bfloat1622float2(*(const __nv_bfloat162*)&H[(size_t)ss * 64 + lane * 2]);
            a0 += uk * hs.x;
            a1 += uk * hs.y;
        }
    }
    float inv = 1.0f / (den + 1e-16f);
    float v0 = a0 * inv + bias[lane * 2];
    float v1 = a1 * inv + bias[lane * 2 + 1];
    v0 = v0 > 0.0f ? v0 : (__expf(v0) - 1.0f);
    v1 = v1 > 0.0f ? v1 : (__expf(v1) - 1.0f);
    int grp = batch[d];
    atomicAdd(&pool[grp * 64 + lane * 2], v0);
    atomicAdd(&pool[grp * 64 + lane * 2 + 1], v1);
    if (lane == 0) atomicAdd(&cnt[grp], 1.0f);
}

__global__ void final_write_kernel(const float* __restrict__ POOL,
                                   const float* __restrict__ CNT,
                                   float* __restrict__ out) {
    int i = blockIdx.x * blockDim.x + threadIdx.x;
    if (i >= 2 * GNUM * 64) return;
    float c = CNT[i >> 6];
    out[i] = POOL[i] / fmaxf(c, 1.0f);
}

// ---------------------------------------------------------------------------
// Launch
// ---------------------------------------------------------------------------
extern "C" void kernel_launch(void* const* d_in, const int* in_sizes, int n_in,
                              void* d_out, int out_size) {
    const float* x1  = (const float*)d_in[0];
    const int*   ei1 = (const int*)d_in[1];
    const int*   bt1 = (const int*)d_in[2];
    const float* x2  = (const float*)d_in[3];
    const int*   ei2 = (const int*)d_in[4];
    const int*   bt2 = (const int*)d_in[5];
    const float* W1  = (const float*)d_in[6];
    const float* as1 = (const float*)d_in[7];
    const float* ad1 = (const float*)d_in[8];
    const float* b1  = (const float*)d_in[9];
    const float* W2  = (const float*)d_in[10];
    const float* as2 = (const float*)d_in[11];
    const float* ad2 = (const float*)d_in[12];
    const float* b2  = (const float*)d_in[13];

    const int n = in_sizes[0] / 128;
    const int e = in_sizes[1] / 2;
    const int nb = cdiv(n, SCAN_CHUNK);

    float *AS, *AD, *POOL, *CNT, *P1S, *P1D;
    int *DEG, *ROWPTR, *CUR, *ECOL;
    unsigned long long* LOOK;
    __nv_bfloat16 *X16, *AGG, *H2, *W1TH, *W1TL, *W2TH, *W2TL;
    cudaGetSymbolAddress((void**)&X16,    g_X16);
    cudaGetSymbolAddress((void**)&AGG,    g_AGG);
    cudaGetSymbolAddress((void**)&H2,     g_H2);
    cudaGetSymbolAddress((void**)&AS,     g_AS);
    cudaGetSymbolAddress((void**)&AD,     g_AD);
    cudaGetSymbolAddress((void**)&DEG,    g_DEG);
    cudaGetSymbolAddress((void**)&ROWPTR, g_ROWPTR);
    cudaGetSymbolAddress((void**)&CUR,    g_CUR);
    cudaGetSymbolAddress((void**)&ECOL,   g_ECOL);
    cudaGetSymbolAddress((void**)&LOOK,   g_LOOK);
    cudaGetSymbolAddress((void**)&POOL,   g_POOL);
    cudaGetSymbolAddress((void**)&CNT,    g_CNT);
    cudaGetSymbolAddress((void**)&P1S,    g_P1S);
    cudaGetSymbolAddress((void**)&P1D,    g_P1D);
    cudaGetSymbolAddress((void**)&W1TH,   g_W1T_HI);
    cudaGetSymbolAddress((void**)&W1TL,   g_W1T_LO);
    cudaGetSymbolAddress((void**)&W2TH,   g_W2T_HI);
    cudaGetSymbolAddress((void**)&W2TL,   g_W2T_LO);

    cudaFuncSetAttribute(gemm_fused_kernel,
                         cudaFuncAttributeMaxDynamicSharedMemorySize, SMF_TOTAL);

    setup_kernel<<<cdiv(SETUP_TOTAL, 256), 256>>>(W1, W2, as1, ad1,
                                                  W1TH, W1TL, W2TH, W2TL,
                                                  P1S, P1D, POOL, CNT, DEG, LOOK);
    {
        int gx = cdiv(n, 8);
        if (gx < cdiv(e, 256)) gx = cdiv(e, 256);
        dim3 gs(gx, 4);
        stage1_kernel<<<gs, 256>>>(x1, x2, P1S, P1D, AS, AD, X16,
                                   ei1, ei2, DEG, n, e);
    }
    {
        dim3 gs2(nb, 2);
        scan_lookback_kernel<<<gs2, 256>>>(DEG, ROWPTR, CUR, LOOK, n, nb);
    }
    {
        dim3 ge2(cdiv(e, 256), 2);
        fill_kernel<<<ge2, 256>>>(ei1, ei2, CUR, ECOL, e);
    }
    {
        dim3 ga(cdiv(n, 8), 2);
        agg_x_kernel<<<ga, 256>>>(ROWPTR, ECOL, AS, AD, X16, AGG, n);
    }
    {
        dim3 gg(cdiv(n, 128), 2);
        gemm_fused_kernel<<<gg, 256, SMF_TOTAL>>>(AGG, W1TH, W1TL, b1,
                                                  W2TH, W2TL, H2,
                                                  as2, ad2, AS, AD, n);
    }
    {
        dim3 ga(cdiv(n, 8), 2);
        agg2_pool_kernel<<<ga, 256>>>(ROWPTR, ECOL, AS, AD, H2, b2,
                                      bt1, bt2, POOL, CNT, n);
    }
    final_write_kernel<<<cdiv(2 * GNUM * 64, 256), 256>>>(POOL, CNT, (float*)d_out);
}

// round 13
// speedup vs baseline: 1.1982x; 1.0015x over previous
#include <cuda_runtime.h>
#include <cuda_bf16.h>
#include <cstdint>

// ---------------------------------------------------------------------------
// GATGraphSimilarity: Siamese 2-layer GAT (heads=4 then 1) + mean pool.
// Round 13: edge ranks captured from the histogram atomic (fill is atomic-free,
// CUR deleted), cp.async double-buffered A prefetch in the fused GEMM.
// ---------------------------------------------------------------------------

#define NMAX 50000
#define EMAX 800000
#define GNUM 64
#define NEG_SLOPE 0.2f
#define SCAN_CHUNK 4096
#define SCAN_NB ((NMAX + SCAN_CHUNK - 1) / SCAN_CHUNK)

__device__ __nv_bfloat16 g_X16[2][(size_t)NMAX * 128];
__device__ __nv_bfloat16 g_AGG[2][(size_t)NMAX * 512];
__device__ __nv_bfloat16 g_H2 [2][(size_t)NMAX * 64];
__device__ float g_AS  [2][NMAX * 4];
__device__ float g_AD  [2][NMAX * 4];
__device__ int   g_DEG [2][NMAX];
__device__ int   g_ROWPTR[2][NMAX + 1];
__device__ int   g_ECOL[2][EMAX];
__device__ int   g_EIDX[2][EMAX];
__device__ unsigned long long g_LOOK[2][SCAN_NB];
__device__ float g_POOL[2 * GNUM * 64];
__device__ float g_CNT [2 * GNUM];
__device__ float g_P1S [128 * 4];
__device__ float g_P1D [128 * 4];
__device__ __nv_bfloat16 g_W1T_HI[256 * 128];
__device__ __nv_bfloat16 g_W1T_LO[256 * 128];
__device__ __nv_bfloat16 g_W2T_HI[64 * 256];
__device__ __nv_bfloat16 g_W2T_LO[64 * 256];

static inline int cdiv(int a, int b) { return (a + b - 1) / b; }

__device__ __forceinline__ float leaky(float v) {
    return v > 0.0f ? v : NEG_SLOPE * v;
}

__device__ __forceinline__ uint32_t bf2u(__nv_bfloat162 v) {
    return *reinterpret_cast<uint32_t*>(&v);
}

__device__ __forceinline__ uint32_t smem_u32(const void* p) {
    uint32_t a;
    asm("{ .reg .u64 t; cvta.to.shared.u64 t, %1; cvt.u32.u64 %0, t; }"
        : "=r"(a) : "l"(p));
    return a;
}

__device__ __forceinline__ void cp_async16(uint32_t sa, const void* gp, int src_bytes) {
    asm volatile("cp.async.cg.shared.global [%0], [%1], 16, %2;"
                 :: "r"(sa), "l"(gp), "r"(src_bytes));
}
#define CP_COMMIT() asm volatile("cp.async.commit_group;" ::: "memory")

__device__ __forceinline__ void mma16816(float* d, const uint32_t* a, const uint32_t* b) {
    asm volatile(
        "mma.sync.aligned.m16n8k16.row.col.f32.bf16.bf16.f32 "
        "{%0,%1,%2,%3}, {%4,%5,%6,%7}, {%8,%9}, {%0,%1,%2,%3};"
        : "+f"(d[0]), "+f"(d[1]), "+f"(d[2]), "+f"(d[3])
        : "r"(a[0]), "r"(a[1]), "r"(a[2]), "r"(a[3]), "r"(b[0]), "r"(b[1]));
}

// ---------------------------------------------------------------------------
// Setup
// ---------------------------------------------------------------------------
#define SEG1 (256 * 128)
#define SEG2 (64 * 256)
#define SEG3 1024
#define SEG4 (2 * GNUM * 64 + 2 * GNUM)
#define SEG5 (2 * NMAX)
#define SEG6 (2 * SCAN_NB)
#define SETUP_TOTAL (SEG1 + SEG2 + SEG3 + SEG4 + SEG5 + SEG6)

__global__ void setup_kernel(const float* __restrict__ W1,
                             const float* __restrict__ W2,
                             const float* __restrict__ as1,
                             const float* __restrict__ ad1,
                             __nv_bfloat16* __restrict__ W1TH,
                             __nv_bfloat16* __restrict__ W1TL,
                             __nv_bfloat16* __restrict__ W2TH,
                             __nv_bfloat16* __restrict__ W2TL,
                             float* __restrict__ P1S,
                             float* __restrict__ P1D,
                             float* __restrict__ POOL,
                             float* __restrict__ CNT,
                             int* __restrict__ DEG,
                             unsigned long long* __restrict__ LOOK) {
    int i = blockIdx.x * blockDim.x + threadIdx.x;
    if (i < SEG1) {
        int n = i / 128, k = i % 128;
        float v = W1[(size_t)k * 256 + n];
        __nv_bfloat16 h = __float2bfloat16(v);
        W1TH[i] = h;
        W1TL[i] = __float2bfloat16(v - __bfloat162float(h));
        return;
    }
    i -= SEG1;
    if (i < SEG2) {
        int n = i / 256, k = i % 256;
        float v = W2[(size_t)k * 64 + n];
        __nv_bfloat16 h = __float2bfloat16(v);
        W2TH[i] = h;
        W2TL[i] = __float2bfloat16(v - __bfloat162float(h));
        return;
    }
    i -= SEG2;
    if (i < SEG3) {
        int is_dst = i >> 9;
        int o = i & 511;
        int k = o >> 2, h = o & 3;
        const float* a = is_dst ? ad1 : as1;
        float s = 0.0f;
        #pragma unroll 8
        for (int d = 0; d < 64; d++)
            s += W1[(size_t)k * 256 + h * 64 + d] * a[h * 64 + d];
        (is_dst ? P1D : P1S)[k * 4 + h] = s;
        return;
    }
    i -= SEG3;
    if (i < 2 * GNUM * 64) { POOL[i] = 0.0f; return; }
    i -= 2 * GNUM * 64;
    if (i < 2 * GNUM) { CNT[i] = 0.0f; return; }
    i -= 2 * GNUM;
    if (i < SEG5) { DEG[i] = 0; return; }
    i -= SEG5;
    if (i < SEG6) LOOK[i] = 0ULL;
}

// ---------------------------------------------------------------------------
// Stage1: alphas+X16 (parts 0,1); degree histogram + edge ranks (parts 2,3).
// ---------------------------------------------------------------------------
__global__ void stage1_kernel(const float* __restrict__ x0,
                              const float* __restrict__ x1,
                              const float* __restrict__ P1S,
                              const float* __restrict__ P1D,
                              float* __restrict__ AS,
                              float* __restrict__ AD,
                              __nv_bfloat16* __restrict__ X16,
                              const int* __restrict__ ei0,
                              const int* __restrict__ ei1,
                              int* __restrict__ deg,
                              int* __restrict__ eidx,
                              int n, int E) {
    const int part = blockIdx.y;
    if (part >= 2) {
        int g = part - 2;
        const int* ei = g ? ei1 : ei0;
        int i = blockIdx.x * blockDim.x + threadIdx.x;
        if (i < E) {
            int rank = atomicAdd(&deg[g * NMAX + ei[E + i]], 1);
            eidx[(size_t)g * EMAX + i] = rank;
        }
        return;
    }
    const int g = part;
    const float* x = g ? x1 : x0;
    const int warp = (blockIdx.x * blockDim.x + threadIdx.x) >> 5;
    const int lane = threadIdx.x & 31;
    if (warp >= n) return;
    float4 xv = *(const float4*)&x[(size_t)warp * 128 + lane * 4];
    {
        __nv_bfloat162 p0 = __floats2bfloat162_rn(xv.x, xv.y);
        __nv_bfloat162 p1 = __floats2bfloat162_rn(xv.z, xv.w);
        uint2 u = make_uint2(bf2u(p0), bf2u(p1));
        *(uint2*)&X16[(size_t)g * NMAX * 128 + (size_t)warp * 128 + lane * 4] = u;
    }
    float s[4] = {0.f, 0.f, 0.f, 0.f};
    float d[4] = {0.f, 0.f, 0.f, 0.f};
    const float* xp = (const float*)&xv;
    #pragma unroll
    for (int j = 0; j < 4; j++) {
        float xk = xp[j];
        float4 ps = *(const float4*)&P1S[(lane * 4 + j) * 4];
        float4 pd = *(const float4*)&P1D[(lane * 4 + j) * 4];
        s[0] += xk * ps.x; s[1] += xk * ps.y; s[2] += xk * ps.z; s[3] += xk * ps.w;
        d[0] += xk * pd.x; d[1] += xk * pd.y; d[2] += xk * pd.z; d[3] += xk * pd.w;
    }
    #pragma unroll
    for (int off = 16; off >= 1; off >>= 1) {
        #pragma unroll
        for (int h = 0; h < 4; h++) {
            s[h] += __shfl_xor_sync(0xffffffffu, s[h], off);
            d[h] += __shfl_xor_sync(0xffffffffu, d[h], off);
        }
    }
    if (lane == 0) {
        *(float4*)&AS[(size_t)g * NMAX * 4 + warp * 4] = make_float4(s[0], s[1], s[2], s[3]);
        *(float4*)&AD[(size_t)g * NMAX * 4 + warp * 4] = make_float4(d[0], d[1], d[2], d[3]);
    }
}

// ---------------------------------------------------------------------------
// Decoupled-lookback scan: deg -> rowptr (exclusive).
// ---------------------------------------------------------------------------
__global__ void scan_lookback_kernel(const int* __restrict__ deg,
                                     int* __restrict__ rowptr,
                                     unsigned long long* __restrict__ LOOK,
                                     int n, int nb) {
    __shared__ int thr[256];
    __shared__ int sh_P;
    const int g = blockIdx.y;
    const int b = blockIdx.x;
    const int t = threadIdx.x;
    const int base = b * SCAN_CHUNK + t * 16;
    const int* dg = deg + g * NMAX;
    int* rp = rowptr + g * (NMAX + 1);
    unsigned long long* look = LOOK + g * SCAN_NB;

    int s = 0;
    int dloc[16];
    #pragma unroll
    for (int q = 0; q < 16; q++) {
        int i = base + q;
        dloc[q] = (i < n) ? dg[i] : 0;
        s += dloc[q];
    }
    thr[t] = s;
    __syncthreads();
    #pragma unroll
    for (int off = 1; off < 256; off <<= 1) {
        int v = (t >= off) ? thr[t - off] : 0;
        __syncthreads();
        thr[t] += v;
        __syncthreads();
    }
    const int total = thr[255];

    if (t == 0) {
        int P = 0;
        if (b == 0) {
            atomicExch(&look[0], (2ULL << 32) | (unsigned int)total);
        } else {
            atomicExch(&look[b], (1ULL << 32) | (unsigned int)total);
            int i = b - 1;
            while (true) {
                unsigned long long w;
                do { w = atomicAdd(&look[i], 0ULL); } while ((w >> 32) == 0ULL);
                int v = (int)(w & 0xffffffffULL);
                P += v;
                if ((w >> 32) == 2ULL) break;
                i--;
            }
            atomicExch(&look[b], (2ULL << 32) | (unsigned int)(P + total));
        }
        sh_P = P;
    }
    __syncthreads();

    int offset = sh_P + ((t == 0) ? 0 : thr[t - 1]);
    #pragma unroll
    for (int q = 0; q < 16; q++) {
        int i = base + q;
        if (i < n) {
            rp[i] = offset;
            offset += dloc[q];
        }
    }
    if (b == nb - 1 && t == 255) rp[n] = offset;
}

// fill CSR: atomic-free scatter using precomputed ranks
__global__ void fill_kernel(const int* __restrict__ ei0, const int* __restrict__ ei1,
                            const int* __restrict__ rowptr,
                            const int* __restrict__ eidx,
                            int* __restrict__ ecol, int E) {
    int g = blockIdx.y;
    const int* ei = g ? ei1 : ei0;
    int i = blockIdx.x * blockDim.x + threadIdx.x;
    if (i >= E) return;
    int s = ei[i];
    int d = ei[E + i];
    int slot = rowptr[g * (NMAX + 1) + d] + eidx[(size_t)g * EMAX + i];
    ecol[(size_t)g * EMAX + slot] = s;
}

// ---------------------------------------------------------------------------
// conv1 aggregation: smem-staged lane-parallel edge weights, then gather+FMA.
// ---------------------------------------------------------------------------
__global__ void agg_x_kernel(const int* __restrict__ rowptr,
                             const int* __restrict__ ecol,
                             const float* __restrict__ AS,
                             const float* __restrict__ AD,
                             const __nv_bfloat16* __restrict__ X16,
                             __nv_bfloat16* __restrict__ AGG,
                             int n) {
    __shared__ int    sh_s[8][32];
    __shared__ float4 sh_u[8][32];

    const int g = blockIdx.y;
    const int* rp = rowptr + g * (NMAX + 1);
    const int* ec = ecol + (size_t)g * EMAX;
    const float* as = AS + (size_t)g * NMAX * 4;
    const __nv_bfloat16* X = X16 + (size_t)g * NMAX * 128;
    __nv_bfloat16* agg = AGG + (size_t)g * NMAX * 512;

    const int w = threadIdx.x >> 5;
    const int warp = (blockIdx.x * blockDim.x + threadIdx.x) >> 5;
    const int lane = threadIdx.x & 31;
    if (warp >= n) return;
    const int d = warp;
    const int beg = rp[d];
    const int end = rp[d + 1];

    float4 asv = *(const float4*)&as[d * 4];
    float4 adv = *(const float4*)&AD[(size_t)g * NMAX * 4 + d * 4];
    float den[4];
    den[0] = __expf(leaky(asv.x + adv.x));
    den[1] = __expf(leaky(asv.y + adv.y));
    den[2] = __expf(leaky(asv.z + adv.z));
    den[3] = __expf(leaky(asv.w + adv.w));

    uint2 ux = *(const uint2*)&X[(size_t)d * 128 + lane * 4];
    float2 xd01 = __bfloat1622float2(*(__nv_bfloat162*)&ux.x);
    float2 xd23 = __bfloat1622float2(*(__nv_bfloat162*)&ux.y);

    float acc[4][4];
    #pragma unroll
    for (int h = 0; h < 4; h++) {
        acc[h][0] = den[h] * xd01.x; acc[h][1] = den[h] * xd01.y;
        acc[h][2] = den[h] * xd23.x; acc[h][3] = den[h] * xd23.y;
    }

    for (int jb = beg; jb < end; jb += 32) {
        int m = end - jb;
        if (m > 32) m = 32;
        if (lane < m) {
            int s = ec[jb + lane];
            float4 a = *(const float4*)&as[s * 4];
            float4 u;
            u.x = __expf(leaky(a.x + adv.x));
            u.y = __expf(leaky(a.y + adv.y));
            u.z = __expf(leaky(a.z + adv.z));
            u.w = __expf(leaky(a.w + adv.w));
            sh_s[w][lane] = s;
            sh_u[w][lane] = u;
        }
        __syncwarp();
        #pragma unroll 2
        for (int k = 0; k < m; k++) {
            int ss = sh_s[w][k];
            float4 u = sh_u[w][k];
            den[0] += u.x; den[1] += u.y; den[2] += u.z; den[3] += u.w;
            uint2 q = *(const uint2*)&X[(size_t)ss * 128 + lane * 4];
            float2 f01 = __bfloat1622float2(*(__nv_bfloat162*)&q.x);
            float2 f23 = __bfloat1622float2(*(__nv_bfloat162*)&q.y);
            acc[0][0] += u.x * f01.x; acc[0][1] += u.x * f01.y;
            acc[0][2] += u.x * f23.x; acc[0][3] += u.x * f23.y;
            acc[1][0] += u.y * f01.x; acc[1][1] += u.y * f01.y;
            acc[1][2] += u.y * f23.x; acc[1][3] += u.y * f23.y;
            acc[2][0] += u.z * f01.x; acc[2][1] += u.z * f01.y;
            acc[2][2] += u.z * f23.x; acc[2][3] += u.z * f23.y;
            acc[3][0] += u.w * f01.x; acc[3][1] += u.w * f01.y;
            acc[3][2] += u.w * f23.x; acc[3][3] += u.w * f23.y;
        }
        __syncwarp();
    }

    #pragma unroll
    for (int h = 0; h < 4; h++) {
        float inv = 1.0f / (den[h] + 1e-16f);
        __nv_bfloat162 q0 = __floats2bfloat162_rn(acc[h][0] * inv, acc[h][1] * inv);
        __nv_bfloat162 q1 = __floats2bfloat162_rn(acc[h][2] * inv, acc[h][3] * inv);
        uint2 u = make_uint2(bf2u(q0), bf2u(q1));
        *(uint2*)&agg[(size_t)d * 512 + h * 128 + lane * 4] = u;
    }
}

// ---------------------------------------------------------------------------
// FUSED GEMM with cp.async double-buffered A prefetch.
// ---------------------------------------------------------------------------
#define SMF_A0    0
#define SMF_A1    34816
#define SMF_B1H   69632
#define SMF_B1L   87040
#define SMF_OH    104448
#define SMF_OL    122880
#define SMF_B2H   141312
#define SMF_B2L   150528
#define SMF_ALPHA 159744
#define SMF_TOTAL 160768

__global__ __launch_bounds__(256, 1)
void gemm_fused_kernel(const __nv_bfloat16* __restrict__ AGG,
                       const __nv_bfloat16* __restrict__ B1hi,
                       const __nv_bfloat16* __restrict__ B1lo,
                       const float* __restrict__ bias1,
                       const __nv_bfloat16* __restrict__ B2hi,
                       const __nv_bfloat16* __restrict__ B2lo,
                       __nv_bfloat16* __restrict__ H2,
                       const float* __restrict__ a_src,
                       const float* __restrict__ a_dst,
                       float* __restrict__ AS,
                       float* __restrict__ AD,
                       int M) {
    extern __shared__ char smem[];
    uint32_t* B1h = (uint32_t*)(smem + SMF_B1H);
    uint32_t* B1l = (uint32_t*)(smem + SMF_B1L);
    uint32_t* Oh  = (uint32_t*)(smem + SMF_OH);
    uint32_t* Ol  = (uint32_t*)(smem + SMF_OL);
    uint32_t* B2h = (uint32_t*)(smem + SMF_B2H);
    uint32_t* B2l = (uint32_t*)(smem + SMF_B2L);
    float* alpha_s = (float*)(smem + SMF_ALPHA);
    float* alpha_d = alpha_s + 128;
    const uint32_t sb = smem_u32(smem);

    const int g = blockIdx.y;
    const __nv_bfloat16* A = AGG + (size_t)g * NMAX * 512;
    __nv_bfloat16* C = H2 + (size_t)g * NMAX * 64;
    float* ASg = AS + (size_t)g * NMAX * 4;
    float* ADg = AD + (size_t)g * NMAX * 4;
    const int tid = threadIdx.x;
    const int lane = tid & 31;
    const int wid = tid >> 5;
    const int warp_m = wid & 3;
    const int warp_n = wid >> 2;
    const int m0 = blockIdx.x * 128;

    // issue cp.async for head hh's A tile into buffer (hh&1)
    auto issue_A = [&](int hh) {
        uint32_t dst_base = sb + ((hh & 1) ? SMF_A1 : SMF_A0);
        #pragma unroll
        for (int q = 0; q < 8; q++) {
            int idx = q * 256 + tid;
            int r = idx >> 4;
            int c8 = idx & 15;
            int gr = m0 + r;
            int valid = (gr < M) ? 16 : 0;
            const void* gp = &A[(size_t)(gr < M ? gr : 0) * 512 + hh * 128 + c8 * 8];
            cp_async16(dst_base + (uint32_t)(r * 68 + c8 * 4) * 4, gp, valid);
        }
        CP_COMMIT();
    };

    float acc2[2][4][4] = {};
    issue_A(0);

    for (int h = 0; h < 4; h++) {
        if (h) __syncthreads();   // all reads of smem buffers from prev head done
        if (h < 3) issue_A(h + 1);

        // weights (L2-hot)
        #pragma unroll
        for (int q = 0; q < 4; q++) {
            int idx = q * 256 + tid;
            int r = idx >> 4;
            int c8 = idx & 15;
            uint4 vh = *(const uint4*)&B1hi[(size_t)(h * 64 + r) * 128 + c8 * 8];
            uint4 vl = *(const uint4*)&B1lo[(size_t)(h * 64 + r) * 128 + c8 * 8];
            *(uint4*)&B1h[r * 68 + c8 * 4] = vh;
            *(uint4*)&B1l[r * 68 + c8 * 4] = vl;
        }
        #pragma unroll
        for (int q = 0; q < 2; q++) {
            int idx = q * 256 + tid;
            int r = idx >> 3;
            int c8 = idx & 7;
            uint4 vh = *(const uint4*)&B2hi[(size_t)r * 256 + h * 64 + c8 * 8];
            uint4 vl = *(const uint4*)&B2lo[(size_t)r * 256 + h * 64 + c8 * 8];
            *(uint4*)&B2h[r * 36 + c8 * 4] = vh;
            *(uint4*)&B2l[r * 36 + c8 * 4] = vl;
        }
        // wait for A(h): 1 group still in flight when A(h+1) was just issued
        if (h < 3) asm volatile("cp.async.wait_group 1;" ::: "memory");
        else       asm volatile("cp.async.wait_group 0;" ::: "memory");
        __syncthreads();

        uint32_t* Asm = (uint32_t*)(smem + ((h & 1) ? SMF_A1 : SMF_A0));

        float acc1[2][4][4] = {};
        #pragma unroll
        for (int ks = 0; ks < 8; ks++) {
            const int kw = ks * 8 + (lane & 3);
            uint32_t ah[2][4], bh[4][2], bl[4][2];
            #pragma unroll
            for (int mt = 0; mt < 2; mt++) {
                int r0 = warp_m * 32 + mt * 16 + (lane >> 2);
                ah[mt][0] = Asm[r0 * 68 + kw];
                ah[mt][1] = Asm[(r0 + 8) * 68 + kw];
                ah[mt][2] = Asm[r0 * 68 + kw + 4];
                ah[mt][3] = Asm[(r0 + 8) * 68 + kw + 4];
            }
            #pragma unroll
            for (int nt = 0; nt < 4; nt++) {
                int n0 = warp_n * 32 + nt * 8 + (lane >> 2);
                bh[nt][0] = B1h[n0 * 68 + kw];
                bh[nt][1] = B1h[n0 * 68 + kw + 4];
                bl[nt][0] = B1l[n0 * 68 + kw];
                bl[nt][1] = B1l[n0 * 68 + kw + 4];
            }
            #pragma unroll
            for (int mt = 0; mt < 2; mt++)
                #pragma unroll
                for (int nt = 0; nt < 4; nt++) {
                    mma16816(acc1[mt][nt], ah[mt], bh[nt]);
                    mma16816(acc1[mt][nt], ah[mt], bl[nt]);
                }
        }

        #pragma unroll
        for (int mt = 0; mt < 2; mt++) {
            int r0 = warp_m * 32 + mt * 16 + (lane >> 2);
            #pragma unroll
            for (int nt = 0; nt < 4; nt++) {
                int c0 = warp_n * 32 + nt * 8 + (lane & 3) * 2;
                float b0 = __ldg(&bias1[h * 64 + c0]);
                float b1v = __ldg(&bias1[h * 64 + c0 + 1]);
                float* a4 = acc1[mt][nt];
                float v00 = a4[0] + b0, v01 = a4[1] + b1v;
                float v10 = a4[2] + b0, v11 = a4[3] + b1v;
                v00 = v00 > 0.f ? v00 : (__expf(v00) - 1.f);
                v01 = v01 > 0.f ? v01 : (__expf(v01) - 1.f);
                v10 = v10 > 0.f ? v10 : (__expf(v10) - 1.f);
                v11 = v11 > 0.f ? v11 : (__expf(v11) - 1.f);
                int w = warp_n * 16 + nt * 4 + (lane & 3);
                __nv_bfloat162 h0 = __floats2bfloat162_rn(v00, v01);
                __nv_bfloat162 h1 = __floats2bfloat162_rn(v10, v11);
                float2 f0 = __bfloat1622float2(h0);
                float2 f1 = __bfloat1622float2(h1);
                __nv_bfloat162 l0 = __floats2bfloat162_rn(v00 - f0.x, v01 - f0.y);
                __nv_bfloat162 l1 = __floats2bfloat162_rn(v10 - f1.x, v11 - f1.y);
                Oh[r0 * 36 + w] = bf2u(h0);
                Oh[(r0 + 8) * 36 + w] = bf2u(h1);
                Ol[r0 * 36 + w] = bf2u(l0);
                Ol[(r0 + 8) * 36 + w] = bf2u(l1);
            }
        }
        __syncthreads();

        #pragma unroll
        for (int ks = 0; ks < 4; ks++) {
            const int kw = ks * 8 + (lane & 3);
            uint32_t aoh[2][4], aol[2][4], bh[4][2], bl[4][2];
            #pragma unroll
            for (int mt = 0; mt < 2; mt++) {
                int r0 = warp_m * 32 + mt * 16 + (lane >> 2);
                aoh[mt][0] = Oh[r0 * 36 + kw];
                aoh[mt][1] = Oh[(r0 + 8) * 36 + kw];
                aoh[mt][2] = Oh[r0 * 36 + kw + 4];
                aoh[mt][3] = Oh[(r0 + 8) * 36 + kw + 4];
                aol[mt][0] = Ol[r0 * 36 + kw];
                aol[mt][1] = Ol[(r0 + 8) * 36 + kw];
                aol[mt][2] = Ol[r0 * 36 + kw + 4];
                aol[mt][3] = Ol[(r0 + 8) * 36 + kw + 4];
            }
            #pragma unroll
            for (int nt = 0; nt < 4; nt++) {
                int n0 = warp_n * 32 + nt * 8 + (lane >> 2);
                bh[nt][0] = B2h[n0 * 36 + kw];
                bh[nt][1] = B2h[n0 * 36 + kw + 4];
                bl[nt][0] = B2l[n0 * 36 + kw];
                bl[nt][1] = B2l[n0 * 36 + kw + 4];
            }
            #pragma unroll
            for (int mt = 0; mt < 2; mt++)
                #pragma unroll
                for (int nt = 0; nt < 4; nt++) {
                    mma16816(acc2[mt][nt], aoh[mt], bh[nt]);
                    mma16816(acc2[mt][nt], aoh[mt], bl[nt]);
                    mma16816(acc2[mt][nt], aol[mt], bh[nt]);
                }
        }
    }

    __syncthreads();
    if (tid < 128) { alpha_s[tid] = 0.0f; alpha_d[tid] = 0.0f; }
    __syncthreads();

    float sp[4] = {0.f, 0.f, 0.f, 0.f};
    float dp[4] = {0.f, 0.f, 0.f, 0.f};
    #pragma unroll
    for (int mt = 0; mt < 2; mt++) {
        int r0 = warp_m * 32 + mt * 16 + (lane >> 2);
        #pragma unroll
        for (int nt = 0; nt < 4; nt++) {
            int c0 = warp_n * 32 + nt * 8 + (lane & 3) * 2;
            float* a4 = acc2[mt][nt];
            int gr0 = m0 + r0, gr1 = gr0 + 8;
            if (gr0 < M)
                *(__nv_bfloat162*)&C[(size_t)gr0 * 64 + c0] = __floats2bfloat162_rn(a4[0], a4[1]);
            if (gr1 < M)
                *(__nv_bfloat162*)&C[(size_t)gr1 * 64 + c0] = __floats2bfloat162_rn(a4[2], a4[3]);
            float s0 = __ldg(&a_src[c0]);
            float s1 = __ldg(&a_src[c0 + 1]);
            float d0 = __ldg(&a_dst[c0]);
            float d1 = __ldg(&a_dst[c0 + 1]);
            sp[mt * 2]     += a4[0] * s0 + a4[1] * s1;
            sp[mt * 2 + 1] += a4[2] * s0 + a4[3] * s1;
            dp[mt * 2]     += a4[0] * d0 + a4[1] * d1;
            dp[mt * 2 + 1] += a4[2] * d0 + a4[3] * d1;
        }
    }
    #pragma unroll
    for (int i = 0; i < 4; i++) {
        sp[i] += __shfl_xor_sync(0xffffffffu, sp[i], 1);
        sp[i] += __shfl_xor_sync(0xffffffffu, sp[i], 2);
        dp[i] += __shfl_xor_sync(0xffffffffu, dp[i], 1);
        dp[i] += __shfl_xor_sync(0xffffffffu, dp[i], 2);
    }
    if ((lane & 3) == 0) {
        int r0 = warp_m * 32 + (lane >> 2);
        atomicAdd(&alpha_s[r0],      sp[0]);
        atomicAdd(&alpha_s[r0 + 8],  sp[1]);
        atomicAdd(&alpha_s[r0 + 16], sp[2]);
        atomicAdd(&alpha_s[r0 + 24], sp[3]);
        atomicAdd(&alpha_d[r0],      dp[0]);
        atomicAdd(&alpha_d[r0 + 8],  dp[1]);
        atomicAdd(&alpha_d[r0 + 16], dp[2]);
        atomicAdd(&alpha_d[r0 + 24], dp[3]);
    }
    __syncthreads();
    if (tid < 128) {
        int gr = m0 + tid;
        if (gr < M) {
            ASg[gr * 4] = alpha_s[tid];
            ADg[gr * 4] = alpha_d[tid];
        }
    }
}

// ---------------------------------------------------------------------------
// conv2 aggregation with in-warp lane-parallel edge weights + mean pool.
// ---------------------------------------------------------------------------
__global__ void agg2_pool_kernel(const int* __restrict__ rowptr,
                                 const int* __restrict__ ecol,
                                 const float* __restrict__ AS,
                                 const float* __restrict__ AD,
                                 const __nv_bfloat16* __restrict__ H2,
                                 const float* __restrict__ bias,
                                 const int* __restrict__ bt0,
                                 const int* __restrict__ bt1,
                                 float* __restrict__ POOL,
                                 float* __restrict__ CNT,
                                 int n) {
    const int g = blockIdx.y;
    const int* rp = rowptr + g * (NMAX + 1);
    const int* ec = ecol + (size_t)g * EMAX;
    const float* as = AS + (size_t)g * NMAX * 4;
    const __nv_bfloat16* H = H2 + (size_t)g * NMAX * 64;
    const int* batch = g ? bt1 : bt0;
    float* pool = POOL + g * GNUM * 64;
    float* cnt = CNT + g * GNUM;

    const int warp = (blockIdx.x * blockDim.x + threadIdx.x) >> 5;
    const int lane = threadIdx.x & 31;
    if (warp >= n) return;
    const int d = warp;
    const int beg = rp[d];
    const int end = rp[d + 1];

    float ad_d = AD[(size_t)g * NMAX * 4 + d * 4];
    float den = __expf(leaky(as[d * 4] + ad_d));
    float2 hv = __bfloat1622float2(*(const __nv_bfloat162*)&H[(size_t)d * 64 + lane * 2]);
    float a0 = den * hv.x, a1 = den * hv.y;

    for (int jb = beg; jb < end; jb += 32) {
        int m = end - jb;
        if (m > 32) m = 32;
        int s = 0;
        float u = 0.0f;
        if (lane < m) {
            s = ec[jb + lane];
            u = __expf(leaky(as[s * 4] + ad_d));
        }
        for (int k = 0; k < m; k++) {
            int ss = __shfl_sync(0xffffffffu, s, k);
            float uk = __shfl_sync(0xffffffffu, u, k);
            den += uk;
            float2 hs = __bfloat1622float2(*(const __nv_bfloat162*)&H[(size_t)ss * 64 + lane * 2]);
            a0 += uk * hs.x;
            a1 += uk * hs.y;
        }
    }
    float inv = 1.0f / (den + 1e-16f);
    float v0 = a0 * inv + bias[lane * 2];
    float v1 = a1 * inv + bias[lane * 2 + 1];
    v0 = v0 > 0.0f ? v0 : (__expf(v0) - 1.0f);
    v1 = v1 > 0.0f ? v1 : (__expf(v1) - 1.0f);
    int grp = batch[d];
    atomicAdd(&pool[grp * 64 + lane * 2], v0);
    atomicAdd(&pool[grp * 64 + lane * 2 + 1], v1);
    if (lane == 0) atomicAdd(&cnt[grp], 1.0f);
}

__global__ void final_write_kernel(const float* __restrict__ POOL,
                                   const float* __restrict__ CNT,
                                   float* __restrict__ out) {
    int i = blockIdx.x * blockDim.x + threadIdx.x;
    if (i >= 2 * GNUM * 64) return;
    float c = CNT[i >> 6];
    out[i] = POOL[i] / fmaxf(c, 1.0f);
}

// ---------------------------------------------------------------------------
// Launch
// ---------------------------------------------------------------------------
extern "C" void kernel_launch(void* const* d_in, const int* in_sizes, int n_in,
                              void* d_out, int out_size) {
    const float* x1  = (const float*)d_in[0];
    const int*   ei1 = (const int*)d_in[1];
    const int*   bt1 = (const int*)d_in[2];
    const float* x2  = (const float*)d_in[3];
    const int*   ei2 = (const int*)d_in[4];
    const int*   bt2 = (const int*)d_in[5];
    const float* W1  = (const float*)d_in[6];
    const float* as1 = (const float*)d_in[7];
    const float* ad1 = (const float*)d_in[8];
    const float* b1  = (const float*)d_in[9];
    const float* W2  = (const float*)d_in[10];
    const float* as2 = (const float*)d_in[11];
    const float* ad2 = (const float*)d_in[12];
    const float* b2  = (const float*)d_in[13];

    const int n = in_sizes[0] / 128;
    const int e = in_sizes[1] / 2;
    const int nb = cdiv(n, SCAN_CHUNK);

    float *AS, *AD, *POOL, *CNT, *P1S, *P1D;
    int *DEG, *ROWPTR, *ECOL, *EIDX;
    unsigned long long* LOOK;
    __nv_bfloat16 *X16, *AGG, *H2, *W1TH, *W1TL, *W2TH, *W2TL;
    cudaGetSymbolAddress((void**)&X16,    g_X16);
    cudaGetSymbolAddress((void**)&AGG,    g_AGG);
    cudaGetSymbolAddress((void**)&H2,     g_H2);
    cudaGetSymbolAddress((void**)&AS,     g_AS);
    cudaGetSymbolAddress((void**)&AD,     g_AD);
    cudaGetSymbolAddress((void**)&DEG,    g_DEG);
    cudaGetSymbolAddress((void**)&ROWPTR, g_ROWPTR);
    cudaGetSymbolAddress((void**)&ECOL,   g_ECOL);
    cudaGetSymbolAddress((void**)&EIDX,   g_EIDX);
    cudaGetSymbolAddress((void**)&LOOK,   g_LOOK);
    cudaGetSymbolAddress((void**)&POOL,   g_POOL);
    cudaGetSymbolAddress((void**)&CNT,    g_CNT);
    cudaGetSymbolAddress((void**)&P1S,    g_P1S);
    cudaGetSymbolAddress((void**)&P1D,    g_P1D);
    cudaGetSymbolAddress((void**)&W1TH,   g_W1T_HI);
    cudaGetSymbolAddress((void**)&W1TL,   g_W1T_LO);
    cudaGetSymbolAddress((void**)&W2TH,   g_W2T_HI);
    cudaGetSymbolAddress((void**)&W2TL,   g_W2T_LO);

    cudaFuncSetAttribute(gemm_fused_kernel,
                         cudaFuncAttributeMaxDynamicSharedMemorySize, SMF_TOTAL);

    setup_kernel<<<cdiv(SETUP_TOTAL, 256), 256>>>(W1, W2, as1, ad1,
                                                  W1TH, W1TL, W2TH, W2TL,
                                                  P1S, P1D, POOL, CNT, DEG, LOOK);
    {
        int gx = cdiv(n, 8);
        if (gx < cdiv(e, 256)) gx = cdiv(e, 256);
        dim3 gs(gx, 4);
        stage1_kernel<<<gs, 256>>>(x1, x2, P1S, P1D, AS, AD, X16,
                                   ei1, ei2, DEG, EIDX, n, e);
    }
    {
        dim3 gs2(nb, 2);
        scan_lookback_kernel<<<gs2, 256>>>(DEG, ROWPTR, LOOK, n, nb);
    }
    {
        dim3 ge2(cdiv(e, 256), 2);
        fill_kernel<<<ge2, 256>>>(ei1, ei2, ROWPTR, EIDX, ECOL, e);
    }
    {
        dim3 ga(cdiv(n, 8), 2);
        agg_x_kernel<<<ga, 256>>>(ROWPTR, ECOL, AS, AD, X16, AGG, n);
    }
    {
        dim3 gg(cdiv(n, 128), 2);
        gemm_fused_kernel<<<gg, 256, SMF_TOTAL>>>(AGG, W1TH, W1TL, b1,
                                                  W2TH, W2TL, H2,
                                                  as2, ad2, AS, AD, n);
    }
    {
        dim3 ga(cdiv(n, 8), 2);
        agg2_pool_kernel<<<ga, 256>>>(ROWPTR, ECOL, AS, AD, H2, b2,
                                      bt1, bt2, POOL, CNT, n);
    }
    final_write_kernel<<<cdiv(2 * GNUM * 64, 256), 256>>>(POOL, CNT, (float*)d_out);
}

// round 14
// speedup vs baseline: 1.2812x; 1.0693x over previous
#include <cuda_runtime.h>
#include <cuda_bf16.h>
#include <cstdint>

// ---------------------------------------------------------------------------
// GATGraphSimilarity: Siamese 2-layer GAT (heads=4 then 1) + mean pool.
// Round 14: gemm_fused smem cut 157KB -> 91KB via B1/O overlay (B1 dead when
// O is written) and dropping the A double-buffer -> 2 blocks/SM (waves 5.3->2.6).
// agg_x consume loop unrolled x4.
// ---------------------------------------------------------------------------

#define NMAX 50000
#define EMAX 800000
#define GNUM 64
#define NEG_SLOPE 0.2f
#define SCAN_CHUNK 4096
#define SCAN_NB ((NMAX + SCAN_CHUNK - 1) / SCAN_CHUNK)

__device__ __nv_bfloat16 g_X16[2][(size_t)NMAX * 128];
__device__ __nv_bfloat16 g_AGG[2][(size_t)NMAX * 512];
__device__ __nv_bfloat16 g_H2 [2][(size_t)NMAX * 64];
__device__ float g_AS  [2][NMAX * 4];
__device__ float g_AD  [2][NMAX * 4];
__device__ int   g_DEG [2][NMAX];
__device__ int   g_ROWPTR[2][NMAX + 1];
__device__ int   g_ECOL[2][EMAX];
__device__ int   g_EIDX[2][EMAX];
__device__ unsigned long long g_LOOK[2][SCAN_NB];
__device__ float g_POOL[2 * GNUM * 64];
__device__ float g_CNT [2 * GNUM];
__device__ float g_P1S [128 * 4];
__device__ float g_P1D [128 * 4];
__device__ __nv_bfloat16 g_W1T_HI[256 * 128];
__device__ __nv_bfloat16 g_W1T_LO[256 * 128];
__device__ __nv_bfloat16 g_W2T_HI[64 * 256];
__device__ __nv_bfloat16 g_W2T_LO[64 * 256];

static inline int cdiv(int a, int b) { return (a + b - 1) / b; }

__device__ __forceinline__ float leaky(float v) {
    return v > 0.0f ? v : NEG_SLOPE * v;
}

__device__ __forceinline__ uint32_t bf2u(__nv_bfloat162 v) {
    return *reinterpret_cast<uint32_t*>(&v);
}

__device__ __forceinline__ void mma16816(float* d, const uint32_t* a, const uint32_t* b) {
    asm volatile(
        "mma.sync.aligned.m16n8k16.row.col.f32.bf16.bf16.f32 "
        "{%0,%1,%2,%3}, {%4,%5,%6,%7}, {%8,%9}, {%0,%1,%2,%3};"
        : "+f"(d[0]), "+f"(d[1]), "+f"(d[2]), "+f"(d[3])
        : "r"(a[0]), "r"(a[1]), "r"(a[2]), "r"(a[3]), "r"(b[0]), "r"(b[1]));
}

// ---------------------------------------------------------------------------
// Setup
// ---------------------------------------------------------------------------
#define SEG1 (256 * 128)
#define SEG2 (64 * 256)
#define SEG3 1024
#define SEG4 (2 * GNUM * 64 + 2 * GNUM)
#define SEG5 (2 * NMAX)
#define SEG6 (2 * SCAN_NB)
#define SETUP_TOTAL (SEG1 + SEG2 + SEG3 + SEG4 + SEG5 + SEG6)

__global__ void setup_kernel(const float* __restrict__ W1,
                             const float* __restrict__ W2,
                             const float* __restrict__ as1,
                             const float* __restrict__ ad1,
                             __nv_bfloat16* __restrict__ W1TH,
                             __nv_bfloat16* __restrict__ W1TL,
                             __nv_bfloat16* __restrict__ W2TH,
                             __nv_bfloat16* __restrict__ W2TL,
                             float* __restrict__ P1S,
                             float* __restrict__ P1D,
                             float* __restrict__ POOL,
                             float* __restrict__ CNT,
                             int* __restrict__ DEG,
                             unsigned long long* __restrict__ LOOK) {
    int i = blockIdx.x * blockDim.x + threadIdx.x;
    if (i < SEG1) {
        int n = i / 128, k = i % 128;
        float v = W1[(size_t)k * 256 + n];
        __nv_bfloat16 h = __float2bfloat16(v);
        W1TH[i] = h;
        W1TL[i] = __float2bfloat16(v - __bfloat162float(h));
        return;
    }
    i -= SEG1;
    if (i < SEG2) {
        int n = i / 256, k = i % 256;
        float v = W2[(size_t)k * 64 + n];
        __nv_bfloat16 h = __float2bfloat16(v);
        W2TH[i] = h;
        W2TL[i] = __float2bfloat16(v - __bfloat162float(h));
        return;
    }
    i -= SEG2;
    if (i < SEG3) {
        int is_dst = i >> 9;
        int o = i & 511;
        int k = o >> 2, h = o & 3;
        const float* a = is_dst ? ad1 : as1;
        float s = 0.0f;
        #pragma unroll 8
        for (int d = 0; d < 64; d++)
            s += W1[(size_t)k * 256 + h * 64 + d] * a[h * 64 + d];
        (is_dst ? P1D : P1S)[k * 4 + h] = s;
        return;
    }
    i -= SEG3;
    if (i < 2 * GNUM * 64) { POOL[i] = 0.0f; return; }
    i -= 2 * GNUM * 64;
    if (i < 2 * GNUM) { CNT[i] = 0.0f; return; }
    i -= 2 * GNUM;
    if (i < SEG5) { DEG[i] = 0; return; }
    i -= SEG5;
    if (i < SEG6) LOOK[i] = 0ULL;
}

// ---------------------------------------------------------------------------
// Stage1: alphas+X16 (parts 0,1); degree histogram + edge ranks (parts 2,3).
// ---------------------------------------------------------------------------
__global__ void stage1_kernel(const float* __restrict__ x0,
                              const float* __restrict__ x1,
                              const float* __restrict__ P1S,
                              const float* __restrict__ P1D,
                              float* __restrict__ AS,
                              float* __restrict__ AD,
                              __nv_bfloat16* __restrict__ X16,
                              const int* __restrict__ ei0,
                              const int* __restrict__ ei1,
                              int* __restrict__ deg,
                              int* __restrict__ eidx,
                              int n, int E) {
    const int part = blockIdx.y;
    if (part >= 2) {
        int g = part - 2;
        const int* ei = g ? ei1 : ei0;
        int i = blockIdx.x * blockDim.x + threadIdx.x;
        if (i < E) {
            int rank = atomicAdd(&deg[g * NMAX + ei[E + i]], 1);
            eidx[(size_t)g * EMAX + i] = rank;
        }
        return;
    }
    const int g = part;
    const float* x = g ? x1 : x0;
    const int warp = (blockIdx.x * blockDim.x + threadIdx.x) >> 5;
    const int lane = threadIdx.x & 31;
    if (warp >= n) return;
    float4 xv = *(const float4*)&x[(size_t)warp * 128 + lane * 4];
    {
        __nv_bfloat162 p0 = __floats2bfloat162_rn(xv.x, xv.y);
        __nv_bfloat162 p1 = __floats2bfloat162_rn(xv.z, xv.w);
        uint2 u = make_uint2(bf2u(p0), bf2u(p1));
        *(uint2*)&X16[(size_t)g * NMAX * 128 + (size_t)warp * 128 + lane * 4] = u;
    }
    float s[4] = {0.f, 0.f, 0.f, 0.f};
    float d[4] = {0.f, 0.f, 0.f, 0.f};
    const float* xp = (const float*)&xv;
    #pragma unroll
    for (int j = 0; j < 4; j++) {
        float xk = xp[j];
        float4 ps = *(const float4*)&P1S[(lane * 4 + j) * 4];
        float4 pd = *(const float4*)&P1D[(lane * 4 + j) * 4];
        s[0] += xk * ps.x; s[1] += xk * ps.y; s[2] += xk * ps.z; s[3] += xk * ps.w;
        d[0] += xk * pd.x; d[1] += xk * pd.y; d[2] += xk * pd.z; d[3] += xk * pd.w;
    }
    #pragma unroll
    for (int off = 16; off >= 1; off >>= 1) {
        #pragma unroll
        for (int h = 0; h < 4; h++) {
            s[h] += __shfl_xor_sync(0xffffffffu, s[h], off);
            d[h] += __shfl_xor_sync(0xffffffffu, d[h], off);
        }
    }
    if (lane == 0) {
        *(float4*)&AS[(size_t)g * NMAX * 4 + warp * 4] = make_float4(s[0], s[1], s[2], s[3]);
        *(float4*)&AD[(size_t)g * NMAX * 4 + warp * 4] = make_float4(d[0], d[1], d[2], d[3]);
    }
}

// ---------------------------------------------------------------------------
// Decoupled-lookback scan: deg -> rowptr (exclusive).
// ---------------------------------------------------------------------------
__global__ void scan_lookback_kernel(const int* __restrict__ deg,
                                     int* __restrict__ rowptr,
                                     unsigned long long* __restrict__ LOOK,
                                     int n, int nb) {
    __shared__ int thr[256];
    __shared__ int sh_P;
    const int g = blockIdx.y;
    const int b = blockIdx.x;
    const int t = threadIdx.x;
    const int base = b * SCAN_CHUNK + t * 16;
    const int* dg = deg + g * NMAX;
    int* rp = rowptr + g * (NMAX + 1);
    unsigned long long* look = LOOK + g * SCAN_NB;

    int s = 0;
    int dloc[16];
    #pragma unroll
    for (int q = 0; q < 16; q++) {
        int i = base + q;
        dloc[q] = (i < n) ? dg[i] : 0;
        s += dloc[q];
    }
    thr[t] = s;
    __syncthreads();
    #pragma unroll
    for (int off = 1; off < 256; off <<= 1) {
        int v = (t >= off) ? thr[t - off] : 0;
        __syncthreads();
        thr[t] += v;
        __syncthreads();
    }
    const int total = thr[255];

    if (t == 0) {
        int P = 0;
        if (b == 0) {
            atomicExch(&look[0], (2ULL << 32) | (unsigned int)total);
        } else {
            atomicExch(&look[b], (1ULL << 32) | (unsigned int)total);
            int i = b - 1;
            while (true) {
                unsigned long long w;
                do { w = atomicAdd(&look[i], 0ULL); } while ((w >> 32) == 0ULL);
                int v = (int)(w & 0xffffffffULL);
                P += v;
                if ((w >> 32) == 2ULL) break;
                i--;
            }
            atomicExch(&look[b], (2ULL << 32) | (unsigned int)(P + total));
        }
        sh_P = P;
    }
    __syncthreads();

    int offset = sh_P + ((t == 0) ? 0 : thr[t - 1]);
    #pragma unroll
    for (int q = 0; q < 16; q++) {
        int i = base + q;
        if (i < n) {
            rp[i] = offset;
            offset += dloc[q];
        }
    }
    if (b == nb - 1 && t == 255) rp[n] = offset;
}

// fill CSR: atomic-free scatter using precomputed ranks
__global__ void fill_kernel(const int* __restrict__ ei0, const int* __restrict__ ei1,
                            const int* __restrict__ rowptr,
                            const int* __restrict__ eidx,
                            int* __restrict__ ecol, int E) {
    int g = blockIdx.y;
    const int* ei = g ? ei1 : ei0;
    int i = blockIdx.x * blockDim.x + threadIdx.x;
    if (i >= E) return;
    int s = ei[i];
    int d = ei[E + i];
    int slot = rowptr[g * (NMAX + 1) + d] + eidx[(size_t)g * EMAX + i];
    ecol[(size_t)g * EMAX + slot] = s;
}

// ---------------------------------------------------------------------------
// conv1 aggregation: smem-staged lane-parallel edge weights, then gather+FMA.
// ---------------------------------------------------------------------------
__global__ void agg_x_kernel(const int* __restrict__ rowptr,
                             const int* __restrict__ ecol,
                             const float* __restrict__ AS,
                             const float* __restrict__ AD,
                             const __nv_bfloat16* __restrict__ X16,
                             __nv_bfloat16* __restrict__ AGG,
                             int n) {
    __shared__ int    sh_s[8][32];
    __shared__ float4 sh_u[8][32];

    const int g = blockIdx.y;
    const int* rp = rowptr + g * (NMAX + 1);
    const int* ec = ecol + (size_t)g * EMAX;
    const float* as = AS + (size_t)g * NMAX * 4;
    const __nv_bfloat16* X = X16 + (size_t)g * NMAX * 128;
    __nv_bfloat16* agg = AGG + (size_t)g * NMAX * 512;

    const int w = threadIdx.x >> 5;
    const int warp = (blockIdx.x * blockDim.x + threadIdx.x) >> 5;
    const int lane = threadIdx.x & 31;
    if (warp >= n) return;
    const int d = warp;
    const int beg = rp[d];
    const int end = rp[d + 1];

    float4 asv = *(const float4*)&as[d * 4];
    float4 adv = *(const float4*)&AD[(size_t)g * NMAX * 4 + d * 4];
    float den[4];
    den[0] = __expf(leaky(asv.x + adv.x));
    den[1] = __expf(leaky(asv.y + adv.y));
    den[2] = __expf(leaky(asv.z + adv.z));
    den[3] = __expf(leaky(asv.w + adv.w));

    uint2 ux = *(const uint2*)&X[(size_t)d * 128 + lane * 4];
    float2 xd01 = __bfloat1622float2(*(__nv_bfloat162*)&ux.x);
    float2 xd23 = __bfloat1622float2(*(__nv_bfloat162*)&ux.y);

    float acc[4][4];
    #pragma unroll
    for (int h = 0; h < 4; h++) {
        acc[h][0] = den[h] * xd01.x; acc[h][1] = den[h] * xd01.y;
        acc[h][2] = den[h] * xd23.x; acc[h][3] = den[h] * xd23.y;
    }

    for (int jb = beg; jb < end; jb += 32) {
        int m = end - jb;
        if (m > 32) m = 32;
        if (lane < m) {
            int s = ec[jb + lane];
            float4 a = *(const float4*)&as[s * 4];
            float4 u;
            u.x = __expf(leaky(a.x + adv.x));
            u.y = __expf(leaky(a.y + adv.y));
            u.z = __expf(leaky(a.z + adv.z));
            u.w = __expf(leaky(a.w + adv.w));
            sh_s[w][lane] = s;
            sh_u[w][lane] = u;
        }
        __syncwarp();
        #pragma unroll 4
        for (int k = 0; k < m; k++) {
            int ss = sh_s[w][k];
            float4 u = sh_u[w][k];
            den[0] += u.x; den[1] += u.y; den[2] += u.z; den[3] += u.w;
            uint2 q = *(const uint2*)&X[(size_t)ss * 128 + lane * 4];
            float2 f01 = __bfloat1622float2(*(__nv_bfloat162*)&q.x);
            float2 f23 = __bfloat1622float2(*(__nv_bfloat162*)&q.y);
            acc[0][0] += u.x * f01.x; acc[0][1] += u.x * f01.y;
            acc[0][2] += u.x * f23.x; acc[0][3] += u.x * f23.y;
            acc[1][0] += u.y * f01.x; acc[1][1] += u.y * f01.y;
            acc[1][2] += u.y * f23.x; acc[1][3] += u.y * f23.y;
            acc[2][0] += u.z * f01.x; acc[2][1] += u.z * f01.y;
            acc[2][2] += u.z * f23.x; acc[2][3] += u.z * f23.y;
            acc[3][0] += u.w * f01.x; acc[3][1] += u.w * f01.y;
            acc[3][2] += u.w * f23.x; acc[3][3] += u.w * f23.y;
        }
        __syncwarp();
    }

    #pragma unroll
    for (int h = 0; h < 4; h++) {
        float inv = 1.0f / (den[h] + 1e-16f);
        __nv_bfloat162 q0 = __floats2bfloat162_rn(acc[h][0] * inv, acc[h][1] * inv);
        __nv_bfloat162 q1 = __floats2bfloat162_rn(acc[h][2] * inv, acc[h][3] * inv);
        uint2 u = make_uint2(bf2u(q0), bf2u(q1));
        *(uint2*)&agg[(size_t)d * 512 + h * 128 + lane * 4] = u;
    }
}

// ---------------------------------------------------------------------------
// FUSED GEMM, 91KB smem (B1/O overlay, single A buffer) -> 2 blocks/SM.
// Per head: load A,B1,B2 -> gemm1 -> sync -> O overwrites B1 -> gemm2.
// ---------------------------------------------------------------------------
#define SMF_A     0                       // 128x68 words          34816
#define SMF_REG   34816                   // union region          36864
#define SMF_B1H   (SMF_REG)               //   64x68               17408
#define SMF_B1L   (SMF_REG + 17408)       //   64x68               17408
#define SMF_OH    (SMF_REG)               //   128x36              18432
#define SMF_OL    (SMF_REG + 18432)       //   128x36              18432
#define SMF_B2H   (SMF_REG + 36864)       //   64x36                9216
#define SMF_B2L   (SMF_B2H + 9216)        //                        9216
#define SMF_ALPHA (SMF_B2H + 18432)       //  256 floats            1024
#define SMF_TOTAL (SMF_ALPHA + 1024)      //                       91136

__global__ __launch_bounds__(256, 2)
void gemm_fused_kernel(const __nv_bfloat16* __restrict__ AGG,
                       const __nv_bfloat16* __restrict__ B1hi,
                       const __nv_bfloat16* __restrict__ B1lo,
                       const float* __restrict__ bias1,
                       const __nv_bfloat16* __restrict__ B2hi,
                       const __nv_bfloat16* __restrict__ B2lo,
                       __nv_bfloat16* __restrict__ H2,
                       const float* __restrict__ a_src,
                       const float* __restrict__ a_dst,
                       float* __restrict__ AS,
                       float* __restrict__ AD,
                       int M) {
    extern __shared__ char smem[];
    uint32_t* Asm = (uint32_t*)(smem + SMF_A);
    uint32_t* B1h = (uint32_t*)(smem + SMF_B1H);
    uint32_t* B1l = (uint32_t*)(smem + SMF_B1L);
    uint32_t* Oh  = (uint32_t*)(smem + SMF_OH);
    uint32_t* Ol  = (uint32_t*)(smem + SMF_OL);
    uint32_t* B2h = (uint32_t*)(smem + SMF_B2H);
    uint32_t* B2l = (uint32_t*)(smem + SMF_B2L);
    float* alpha_s = (float*)(smem + SMF_ALPHA);
    float* alpha_d = alpha_s + 128;

    const int g = blockIdx.y;
    const __nv_bfloat16* A = AGG + (size_t)g * NMAX * 512;
    __nv_bfloat16* C = H2 + (size_t)g * NMAX * 64;
    float* ASg = AS + (size_t)g * NMAX * 4;
    float* ADg = AD + (size_t)g * NMAX * 4;
    const int tid = threadIdx.x;
    const int lane = tid & 31;
    const int wid = tid >> 5;
    const int warp_m = wid & 3;
    const int warp_n = wid >> 2;
    const int m0 = blockIdx.x * 128;

    float acc2[2][4][4] = {};

    for (int h = 0; h < 4; h++) {
        if (h) __syncthreads();   // prev head's gemm2 reads of O/B2 done

        #pragma unroll
        for (int q = 0; q < 8; q++) {
            int idx = q * 256 + tid;
            int r = idx >> 4;
            int c8 = idx & 15;
            int gr = m0 + r;
            uint4 v = make_uint4(0u, 0u, 0u, 0u);
            if (gr < M) v = *(const uint4*)&A[(size_t)gr * 512 + h * 128 + c8 * 8];
            *(uint4*)&Asm[r * 68 + c8 * 4] = v;
        }
        #pragma unroll
        for (int q = 0; q < 4; q++) {
            int idx = q * 256 + tid;
            int r = idx >> 4;
            int c8 = idx & 15;
            uint4 vh = *(const uint4*)&B1hi[(size_t)(h * 64 + r) * 128 + c8 * 8];
            uint4 vl = *(const uint4*)&B1lo[(size_t)(h * 64 + r) * 128 + c8 * 8];
            *(uint4*)&B1h[r * 68 + c8 * 4] = vh;
            *(uint4*)&B1l[r * 68 + c8 * 4] = vl;
        }
        #pragma unroll
        for (int q = 0; q < 2; q++) {
            int idx = q * 256 + tid;
            int r = idx >> 3;
            int c8 = idx & 7;
            uint4 vh = *(const uint4*)&B2hi[(size_t)r * 256 + h * 64 + c8 * 8];
            uint4 vl = *(const uint4*)&B2lo[(size_t)r * 256 + h * 64 + c8 * 8];
            *(uint4*)&B2h[r * 36 + c8 * 4] = vh;
            *(uint4*)&B2l[r * 36 + c8 * 4] = vl;
        }
        __syncthreads();

        // gemm1: acc1 = A @ B1 (2-term)
        float acc1[2][4][4] = {};
        #pragma unroll
        for (int ks = 0; ks < 8; ks++) {
            const int kw = ks * 8 + (lane & 3);
            uint32_t ah[2][4], bh[4][2], bl[4][2];
            #pragma unroll
            for (int mt = 0; mt < 2; mt++) {
                int r0 = warp_m * 32 + mt * 16 + (lane >> 2);
                ah[mt][0] = Asm[r0 * 68 + kw];
                ah[mt][1] = Asm[(r0 + 8) * 68 + kw];
                ah[mt][2] = Asm[r0 * 68 + kw + 4];
                ah[mt][3] = Asm[(r0 + 8) * 68 + kw + 4];
            }
            #pragma unroll
            for (int nt = 0; nt < 4; nt++) {
                int n0 = warp_n * 32 + nt * 8 + (lane >> 2);
                bh[nt][0] = B1h[n0 * 68 + kw];
                bh[nt][1] = B1h[n0 * 68 + kw + 4];
                bl[nt][0] = B1l[n0 * 68 + kw];
                bl[nt][1] = B1l[n0 * 68 + kw + 4];
            }
            #pragma unroll
            for (int mt = 0; mt < 2; mt++)
                #pragma unroll
                for (int nt = 0; nt < 4; nt++) {
                    mma16816(acc1[mt][nt], ah[mt], bh[nt]);
                    mma16816(acc1[mt][nt], ah[mt], bl[nt]);
                }
        }
        __syncthreads();   // B1 reads complete before O overwrites the region

        // bias + ELU, split hi/lo into O (overlaying B1)
        #pragma unroll
        for (int mt = 0; mt < 2; mt++) {
            int r0 = warp_m * 32 + mt * 16 + (lane >> 2);
            #pragma unroll
            for (int nt = 0; nt < 4; nt++) {
                int c0 = warp_n * 32 + nt * 8 + (lane & 3) * 2;
                float b0 = __ldg(&bias1[h * 64 + c0]);
                float b1v = __ldg(&bias1[h * 64 + c0 + 1]);
                float* a4 = acc1[mt][nt];
                float v00 = a4[0] + b0, v01 = a4[1] + b1v;
                float v10 = a4[2] + b0, v11 = a4[3] + b1v;
                v00 = v00 > 0.f ? v00 : (__expf(v00) - 1.f);
                v01 = v01 > 0.f ? v01 : (__expf(v01) - 1.f);
                v10 = v10 > 0.f ? v10 : (__expf(v10) - 1.f);
                v11 = v11 > 0.f ? v11 : (__expf(v11) - 1.f);
                int w = warp_n * 16 + nt * 4 + (lane & 3);
                __nv_bfloat162 h0 = __floats2bfloat162_rn(v00, v01);
                __nv_bfloat162 h1 = __floats2bfloat162_rn(v10, v11);
                float2 f0 = __bfloat1622float2(h0);
                float2 f1 = __bfloat1622float2(h1);
                __nv_bfloat162 l0 = __floats2bfloat162_rn(v00 - f0.x, v01 - f0.y);
                __nv_bfloat162 l1 = __floats2bfloat162_rn(v10 - f1.x, v11 - f1.y);
                Oh[r0 * 36 + w] = bf2u(h0);
                Oh[(r0 + 8) * 36 + w] = bf2u(h1);
                Ol[r0 * 36 + w] = bf2u(l0);
                Ol[(r0 + 8) * 36 + w] = bf2u(l1);
            }
        }
        __syncthreads();

        // gemm2 accumulate: acc2 += O @ B2 (3-term)
        #pragma unroll
        for (int ks = 0; ks < 4; ks++) {
            const int kw = ks * 8 + (lane & 3);
            uint32_t aoh[2][4], aol[2][4], bh[4][2], bl[4][2];
            #pragma unroll
            for (int mt = 0; mt < 2; mt++) {
                int r0 = warp_m * 32 + mt * 16 + (lane >> 2);
                aoh[mt][0] = Oh[r0 * 36 + kw];
                aoh[mt][1] = Oh[(r0 + 8) * 36 + kw];
                aoh[mt][2] = Oh[r0 * 36 + kw + 4];
                aoh[mt][3] = Oh[(r0 + 8) * 36 + kw + 4];
                aol[mt][0] = Ol[r0 * 36 + kw];
                aol[mt][1] = Ol[(r0 + 8) * 36 + kw];
                aol[mt][2] = Ol[r0 * 36 + kw + 4];
                aol[mt][3] = Ol[(r0 + 8) * 36 + kw + 4];
            }
            #pragma unroll
            for (int nt = 0; nt < 4; nt++) {
                int n0 = warp_n * 32 + nt * 8 + (lane >> 2);
                bh[nt][0] = B2h[n0 * 36 + kw];
                bh[nt][1] = B2h[n0 * 36 + kw + 4];
                bl[nt][0] = B2l[n0 * 36 + kw];
                bl[nt][1] = B2l[n0 * 36 + kw + 4];
            }
            #pragma unroll
            for (int mt = 0; mt < 2; mt++)
                #pragma unroll
                for (int nt = 0; nt < 4; nt++) {
                    mma16816(acc2[mt][nt], aoh[mt], bh[nt]);
                    mma16816(acc2[mt][nt], aoh[mt], bl[nt]);
                    mma16816(acc2[mt][nt], aol[mt], bh[nt]);
                }
        }
    }

    __syncthreads();
    if (tid < 128) { alpha_s[tid] = 0.0f; alpha_d[tid] = 0.0f; }
    __syncthreads();

    float sp[4] = {0.f, 0.f, 0.f, 0.f};
    float dp[4] = {0.f, 0.f, 0.f, 0.f};
    #pragma unroll
    for (int mt = 0; mt < 2; mt++) {
        int r0 = warp_m * 32 + mt * 16 + (lane >> 2);
        #pragma unroll
        for (int nt = 0; nt < 4; nt++) {
            int c0 = warp_n * 32 + nt * 8 + (lane & 3) * 2;
            float* a4 = acc2[mt][nt];
            int gr0 = m0 + r0, gr1 = gr0 + 8;
            if (gr0 < M)
                *(__nv_bfloat162*)&C[(size_t)gr0 * 64 + c0] = __floats2bfloat162_rn(a4[0], a4[1]);
            if (gr1 < M)
                *(__nv_bfloat162*)&C[(size_t)gr1 * 64 + c0] = __floats2bfloat162_rn(a4[2], a4[3]);
            float s0 = __ldg(&a_src[c0]);
            float s1 = __ldg(&a_src[c0 + 1]);
            float d0 = __ldg(&a_dst[c0]);
            float d1 = __ldg(&a_dst[c0 + 1]);
            sp[mt * 2]     += a4[0] * s0 + a4[1] * s1;
            sp[mt * 2 + 1] += a4[2] * s0 + a4[3] * s1;
            dp[mt * 2]     += a4[0] * d0 + a4[1] * d1;
            dp[mt * 2 + 1] += a4[2] * d0 + a4[3] * d1;
        }
    }
    #pragma unroll
    for (int i = 0; i < 4; i++) {
        sp[i] += __shfl_xor_sync(0xffffffffu, sp[i], 1);
        sp[i] += __shfl_xor_sync(0xffffffffu, sp[i], 2);
        dp[i] += __shfl_xor_sync(0xffffffffu, dp[i], 1);
        dp[i] += __shfl_xor_sync(0xffffffffu, dp[i], 2);
    }
    if ((lane & 3) == 0) {
        int r0 = warp_m * 32 + (lane >> 2);
        atomicAdd(&alpha_s[r0],      sp[0]);
        atomicAdd(&alpha_s[r0 + 8],  sp[1]);
        atomicAdd(&alpha_s[r0 + 16], sp[2]);
        atomicAdd(&alpha_s[r0 + 24], sp[3]);
        atomicAdd(&alpha_d[r0],      dp[0]);
        atomicAdd(&alpha_d[r0 + 8],  dp[1]);
        atomicAdd(&alpha_d[r0 + 16], dp[2]);
        atomicAdd(&alpha_d[r0 + 24], dp[3]);
    }
    __syncthreads();
    if (tid < 128) {
        int gr = m0 + tid;
        if (gr < M) {
            ASg[gr * 4] = alpha_s[tid];
            ADg[gr * 4] = alpha_d[tid];
        }
    }
}

// ---------------------------------------------------------------------------
// conv2 aggregation with in-warp lane-parallel edge weights + mean pool.
// ---------------------------------------------------------------------------
__global__ void agg2_pool_kernel(const int* __restrict__ rowptr,
                                 const int* __restrict__ ecol,
                                 const float* __restrict__ AS,
                                 const float* __restrict__ AD,
                                 const __nv_bfloat16* __restrict__ H2,
                                 const float* __restrict__ bias,
                                 const int* __restrict__ bt0,
                                 const int* __restrict__ bt1,
                                 float* __restrict__ POOL,
                                 float* __restrict__ CNT,
                                 int n) {
    const int g = blockIdx.y;
    const int* rp = rowptr + g * (NMAX + 1);
    const int* ec = ecol + (size_t)g * EMAX;
    const float* as = AS + (size_t)g * NMAX * 4;
    const __nv_bfloat16* H = H2 + (size_t)g * NMAX * 64;
    const int* batch = g ? bt1 : bt0;
    float* pool = POOL + g * GNUM * 64;
    float* cnt = CNT + g * GNUM;

    const int warp = (blockIdx.x * blockDim.x + threadIdx.x) >> 5;
    const int lane = threadIdx.x & 31;
    if (warp >= n) return;
    const int d = warp;
    const int beg = rp[d];
    const int end = rp[d + 1];

    float ad_d = AD[(size_t)g * NMAX * 4 + d * 4];
    float den = __expf(leaky(as[d * 4] + ad_d));
    float2 hv = __bfloat1622float2(*(const __nv_bfloat162*)&H[(size_t)d * 64 + lane * 2]);
    float a0 = den * hv.x, a1 = den * hv.y;

    for (int jb = beg; jb < end; jb += 32) {
        int m = end - jb;
        if (m > 32) m = 32;
        int s = 0;
        float u = 0.0f;
        if (lane < m) {
            s = ec[jb + lane];
            u = __expf(leaky(as[s * 4] + ad_d));
        }
        for (int k = 0; k < m; k++) {
            int ss = __shfl_sync(0xffffffffu, s, k);
            float uk = __shfl_sync(0xffffffffu, u, k);
            den += uk;
            float2 hs = __bfloat1622float2(*(const __nv_bfloat162*)&H[(size_t)ss * 64 + lane * 2]);
            a0 += uk * hs.x;
            a1 += uk * hs.y;
        }
    }
    float inv = 1.0f / (den + 1e-16f);
    float v0 = a0 * inv + bias[lane * 2];
    float v1 = a1 * inv + bias[lane * 2 + 1];
    v0 = v0 > 0.0f ? v0 : (__expf(v0) - 1.0f);
    v1 = v1 > 0.0f ? v1 : (__expf(v1) - 1.0f);
    int grp = batch[d];
    atomicAdd(&pool[grp * 64 + lane * 2], v0);
    atomicAdd(&pool[grp * 64 + lane * 2 + 1], v1);
    if (lane == 0) atomicAdd(&cnt[grp], 1.0f);
}

__global__ void final_write_kernel(const float* __restrict__ POOL,
                                   const float* __restrict__ CNT,
                                   float* __restrict__ out) {
    int i = blockIdx.x * blockDim.x + threadIdx.x;
    if (i >= 2 * GNUM * 64) return;
    float c = CNT[i >> 6];
    out[i] = POOL[i] / fmaxf(c, 1.0f);
}

// ---------------------------------------------------------------------------
// Launch
// ---------------------------------------------------------------------------
extern "C" void kernel_launch(void* const* d_in, const int* in_sizes, int n_in,
                              void* d_out, int out_size) {
    const float* x1  = (const float*)d_in[0];
    const int*   ei1 = (const int*)d_in[1];
    const int*   bt1 = (const int*)d_in[2];
    const float* x2  = (const float*)d_in[3];
    const int*   ei2 = (const int*)d_in[4];
    const int*   bt2 = (const int*)d_in[5];
    const float* W1  = (const float*)d_in[6];
    const float* as1 = (const float*)d_in[7];
    const float* ad1 = (const float*)d_in[8];
    const float* b1  = (const float*)d_in[9];
    const float* W2  = (const float*)d_in[10];
    const float* as2 = (const float*)d_in[11];
    const float* ad2 = (const float*)d_in[12];
    const float* b2  = (const float*)d_in[13];

    const int n = in_sizes[0] / 128;
    const int e = in_sizes[1] / 2;
    const int nb = cdiv(n, SCAN_CHUNK);

    float *AS, *AD, *POOL, *CNT, *P1S, *P1D;
    int *DEG, *ROWPTR, *ECOL, *EIDX;
    unsigned long long* LOOK;
    __nv_bfloat16 *X16, *AGG, *H2, *W1TH, *W1TL, *W2TH, *W2TL;
    cudaGetSymbolAddress((void**)&X16,    g_X16);
    cudaGetSymbolAddress((void**)&AGG,    g_AGG);
    cudaGetSymbolAddress((void**)&H2,     g_H2);
    cudaGetSymbolAddress((void**)&AS,     g_AS);
    cudaGetSymbolAddress((void**)&AD,     g_AD);
    cudaGetSymbolAddress((void**)&DEG,    g_DEG);
    cudaGetSymbolAddress((void**)&ROWPTR, g_ROWPTR);
    cudaGetSymbolAddress((void**)&ECOL,   g_ECOL);
    cudaGetSymbolAddress((void**)&EIDX,   g_EIDX);
    cudaGetSymbolAddress((void**)&LOOK,   g_LOOK);
    cudaGetSymbolAddress((void**)&POOL,   g_POOL);
    cudaGetSymbolAddress((void**)&CNT,    g_CNT);
    cudaGetSymbolAddress((void**)&P1S,    g_P1S);
    cudaGetSymbolAddress((void**)&P1D,    g_P1D);
    cudaGetSymbolAddress((void**)&W1TH,   g_W1T_HI);
    cudaGetSymbolAddress((void**)&W1TL,   g_W1T_LO);
    cudaGetSymbolAddress((void**)&W2TH,   g_W2T_HI);
    cudaGetSymbolAddress((void**)&W2TL,   g_W2T_LO);

    cudaFuncSetAttribute(gemm_fused_kernel,
                         cudaFuncAttributeMaxDynamicSharedMemorySize, SMF_TOTAL);

    setup_kernel<<<cdiv(SETUP_TOTAL, 256), 256>>>(W1, W2, as1, ad1,
                                                  W1TH, W1TL, W2TH, W2TL,
                                                  P1S, P1D, POOL, CNT, DEG, LOOK);
    {
        int gx = cdiv(n, 8);
        if (gx < cdiv(e, 256)) gx = cdiv(e, 256);
        dim3 gs(gx, 4);
        stage1_kernel<<<gs, 256>>>(x1, x2, P1S, P1D, AS, AD, X16,
                                   ei1, ei2, DEG, EIDX, n, e);
    }
    {
        dim3 gs2(nb, 2);
        scan_lookback_kernel<<<gs2, 256>>>(DEG, ROWPTR, LOOK, n, nb);
    }
    {
        dim3 ge2(cdiv(e, 256), 2);
        fill_kernel<<<ge2, 256>>>(ei1, ei2, ROWPTR, EIDX, ECOL, e);
    }
    {
        dim3 ga(cdiv(n, 8), 2);
        agg_x_kernel<<<ga, 256>>>(ROWPTR, ECOL, AS, AD, X16, AGG, n);
    }
    {
        dim3 gg(cdiv(n, 128), 2);
        gemm_fused_kernel<<<gg, 256, SMF_TOTAL>>>(AGG, W1TH, W1TL, b1,
                                                  W2TH, W2TL, H2,
                                                  as2, ad2, AS, AD, n);
    }
    {
        dim3 ga(cdiv(n, 8), 2);
        agg2_pool_kernel<<<ga, 256>>>(ROWPTR, ECOL, AS, AD, H2, b2,
                                      bt1, bt2, POOL, CNT, n);
    }
    final_write_kernel<<<cdiv(2 * GNUM * 64, 256), 256>>>(POOL, CNT, (float*)d_out);
}